// round 1
// baseline (speedup 1.0000x reference)
#include <cuda_runtime.h>
#include <math.h>

// ---------------------------------------------------------------------------
// Problem dims (compile-time)
// ---------------------------------------------------------------------------
#define BB 16
#define MM 512
#define NNd 512
#define RR 8
#define DD 256
#define HH 4
#define DHH 64
#define NN1 1024          // M + N
#define TM  (BB*MM*RR)    // 65536 track-feature rows
#define TT  (BB*MM)       // 8192 tokens
#define ND  (BB*NNd)      // 8192 detection rows
#define ROWS1 (BB*NN1)    // 16384 graph rows

// ---------------------------------------------------------------------------
// Scratch (device globals — no allocation allowed)
// ---------------------------------------------------------------------------
__device__ float g_tr_h1[TM*DD];
__device__ float g_tr_emb[TM*DD];
__device__ float g_ln[TM*DD];
__device__ float g_kv[TM*512];
__device__ float g_det_h1[ND*DD];
__device__ float g_det_emb[ND*DD];
__device__ float g_q0[TT*DD];
__device__ float g_o0[TT*DD];
__device__ float g_wo[TT*DD];
__device__ float g_x1[TT*DD];
__device__ float g_ln2[TT*DD];
__device__ float g_ffh[TT*1024];
__device__ float g_ffout[TT*DD];
__device__ float g_feat0[ROWS1*DD];
__device__ float g_x[ROWS1*DD];
__device__ float g_h[ROWS1*DD];
__device__ float g_gout[ROWS1*DD];
__device__ float g_src[ROWS1*HH];
__device__ float g_dst[ROWS1*HH];
__device__ float g_alpha[(size_t)BB*HH*NN1*NN1];   // 268MB, reused as raw scores
__device__ unsigned char g_adj[(size_t)BB*NN1*NN1];
__device__ unsigned char g_adjd[(size_t)BB*NNd*NNd];
__device__ float g_pos[BB*NN1*2];
__device__ unsigned char g_vm[BB*NN1];
__device__ float g_xq[ROWS1*DD];
__device__ float g_xk[ROWS1*DD];

// ---------------------------------------------------------------------------
// Generic tiled SGEMM: C = A @ B (+bias) (+relu), optional B^T, 2-level batch
// Tile 64x64, K-step 16, 256 threads, 4x4 per thread. Dims must be %64 (M,N)
// and %16 (K) — all call sites satisfy this.
// ---------------------------------------------------------------------------
template<bool TRANSB, bool RELU>
__global__ __launch_bounds__(256)
void sgemm_k(const float* __restrict__ A, int lda, long long sA1, long long sA2,
             const float* __restrict__ B, int ldb, long long sB1, long long sB2,
             float* __restrict__ C, int ldc, long long sC1, long long sC2,
             int K, int bdiv, const float* __restrict__ bias)
{
    int bz = blockIdx.z;
    int b1 = bz / bdiv;
    int b2 = bz - b1 * bdiv;
    A += (long long)b1 * sA1 + (long long)b2 * sA2;
    B += (long long)b1 * sB1 + (long long)b2 * sB2;
    C += (long long)b1 * sC1 + (long long)b2 * sC2;

    int m0 = blockIdx.y * 64, n0 = blockIdx.x * 64;
    __shared__ float As[16][65];
    __shared__ float Bs[16][65];
    int tid = threadIdx.x;
    int tx = tid & 15, ty = tid >> 4;
    float acc[4][4] = {};

    for (int k0 = 0; k0 < K; k0 += 16) {
        #pragma unroll
        for (int r = 0; r < 4; r++) {
            int m = (tid >> 4) + r * 16;
            int k = tid & 15;
            As[k][m] = A[(size_t)(m0 + m) * lda + k0 + k];
        }
        if (!TRANSB) {
            #pragma unroll
            for (int r = 0; r < 4; r++) {
                int k = (tid >> 6) + r * 4;
                int n = tid & 63;
                Bs[k][n] = B[(size_t)(k0 + k) * ldb + n0 + n];
            }
        } else {
            #pragma unroll
            for (int r = 0; r < 4; r++) {
                int n = (tid >> 4) + r * 16;
                int k = tid & 15;
                Bs[k][n] = B[(size_t)(n0 + n) * ldb + k0 + k];
            }
        }
        __syncthreads();
        #pragma unroll
        for (int k = 0; k < 16; k++) {
            float a[4], b[4];
            #pragma unroll
            for (int i = 0; i < 4; i++) a[i] = As[k][ty + i * 16];
            #pragma unroll
            for (int j = 0; j < 4; j++) b[j] = Bs[k][tx + j * 16];
            #pragma unroll
            for (int i = 0; i < 4; i++)
                #pragma unroll
                for (int j = 0; j < 4; j++)
                    acc[i][j] += a[i] * b[j];
        }
        __syncthreads();
    }
    #pragma unroll
    for (int i = 0; i < 4; i++) {
        int m = m0 + ty + i * 16;
        #pragma unroll
        for (int j = 0; j < 4; j++) {
            int n = n0 + tx + j * 16;
            float v = acc[i][j];
            if (bias) v += bias[n];
            if (RELU) v = fmaxf(v, 0.f);
            C[(size_t)m * ldc + n] = v;
        }
    }
}

// ---------------------------------------------------------------------------
// Small kernels
// ---------------------------------------------------------------------------
// out[row,d] = elu(x[row,:4] @ W1[:,d] + b1[d]); grid = rows, block = 256
__global__ void k_feat1(const float* __restrict__ x, const float* __restrict__ W1,
                        const float* __restrict__ b1, float* __restrict__ out)
{
    size_t idx = (size_t)blockIdx.x * 256 + threadIdx.x;
    size_t row = idx >> 8;
    int d = idx & 255;
    const float* xr = x + row * 4;
    float v = b1[d] + xr[0]*W1[d] + xr[1]*W1[256+d] + xr[2]*W1[512+d] + xr[3]*W1[768+d];
    out[idx] = (v > 0.f) ? v : expm1f(v);
}

// LayerNorm over 256 cols; grid = rows
__global__ void k_ln(const float* __restrict__ in, float* __restrict__ out)
{
    size_t row = blockIdx.x;
    int t = threadIdx.x;
    float v = in[row * 256 + t];
    float a = v, b = v * v;
    #pragma unroll
    for (int o = 16; o; o >>= 1) {
        a += __shfl_xor_sync(0xffffffff, a, o);
        b += __shfl_xor_sync(0xffffffff, b, o);
    }
    __shared__ float sa[8], sb[8];
    if ((t & 31) == 0) { sa[t >> 5] = a; sb[t >> 5] = b; }
    __syncthreads();
    if (t < 32) {
        a = (t < 8) ? sa[t] : 0.f;
        b = (t < 8) ? sb[t] : 0.f;
        #pragma unroll
        for (int o = 4; o; o >>= 1) {
            a += __shfl_xor_sync(0xffffffff, a, o);
            b += __shfl_xor_sync(0xffffffff, b, o);
        }
        if (t == 0) { sa[0] = a; sb[0] = b; }
    }
    __syncthreads();
    float mean = sa[0] * (1.f / 256.f);
    float var = sb[0] * (1.f / 256.f) - mean * mean;
    out[row * 256 + t] = (v - mean) * rsqrtf(var + 1e-5f);
}

// Tiny attention (R=8) for r=0 query only; grid = TT tokens, block = 256
__global__ void k_attn(const float* __restrict__ q0, const float* __restrict__ kv,
                       float* __restrict__ o0)
{
    size_t t = blockIdx.x;
    int d = threadIdx.x;
    int h = d >> 6;
    __shared__ float logits[4][8];
    __shared__ float red[8];
    float qd = q0[t * 256 + d];
    for (int s = 0; s < 8; s++) {
        float p = qd * kv[(t * 8 + s) * 512 + d];
        #pragma unroll
        for (int o = 16; o; o >>= 1) p += __shfl_xor_sync(0xffffffff, p, o);
        if ((d & 31) == 0) red[d >> 5] = p;
        __syncthreads();
        if (d < 4) logits[d][s] = (red[2 * d] + red[2 * d + 1]) * 0.125f;
        __syncthreads();
    }
    float m = -1e30f;
    #pragma unroll
    for (int s = 0; s < 8; s++) m = fmaxf(m, logits[h][s]);
    float w[8], sum = 0.f;
    #pragma unroll
    for (int s = 0; s < 8; s++) { w[s] = expf(logits[h][s] - m); sum += w[s]; }
    float inv = 1.f / sum;
    float o = 0.f;
    #pragma unroll
    for (int s = 0; s < 8; s++) o += w[s] * inv * kv[(t * 8 + s) * 512 + 256 + d];
    o0[t * 256 + d] = o;
}

// X1 = tr_emb[token r=0 rows] + wo; grid = TT
__global__ void k_x1(const float* __restrict__ tr_emb, const float* __restrict__ wo,
                     float* __restrict__ x1)
{
    size_t idx = (size_t)blockIdx.x * 256 + threadIdx.x;
    size_t t = idx >> 8;
    int d = idx & 255;
    x1[idx] = tr_emb[t * 2048 + d] + wo[idx];
}

// feat0 = concat(predicted, det_emb); also x = feat0. grid = ROWS1
__global__ void k_feat0(const float* __restrict__ tr_emb, const float* __restrict__ x1,
                        const float* __restrict__ ffout, const float* __restrict__ det_emb,
                        float* __restrict__ feat0, float* __restrict__ x)
{
    size_t idx = (size_t)blockIdx.x * 256 + threadIdx.x;
    int d = idx & 255;
    size_t row = idx >> 8;
    int i = row & 1023;
    int b = row >> 10;
    float v;
    if (i < 512) {
        size_t t = (size_t)b * 512 + i;
        v = tr_emb[t * 2048 + d] + 0.9f * (x1[t * 256 + d] + ffout[t * 256 + d]);
    } else {
        size_t t = (size_t)b * 512 + (i - 512);
        v = det_emb[t * 256 + d];
    }
    feat0[idx] = v;
    x[idx] = v;
}

// positions + validity masks; 16384 entries
__global__ void k_posvm(const float* __restrict__ tracks, const float* __restrict__ dets,
                        const int* __restrict__ tmarks, const int* __restrict__ dmarks,
                        float* __restrict__ pos, unsigned char* __restrict__ vm)
{
    int idx = blockIdx.x * 256 + threadIdx.x;
    if (idx >= BB * NN1) return;
    int b = idx >> 10, i = idx & 1023;
    float x, y; unsigned char v;
    if (i < 512) {
        const float* p = tracks + ((size_t)(b * 512 + i)) * 8 * 4;
        x = p[0]; y = p[1];
        v = (i < tmarks[b]);
    } else {
        int n = i - 512;
        const float* p = dets + ((size_t)(b * 512 + n)) * 4;
        x = p[0]; y = p[1];
        v = (n < dmarks[b]);
    }
    pos[idx * 2] = x; pos[idx * 2 + 1] = y; vm[idx] = v;
}

__global__ void k_adj(const float* __restrict__ pos, const unsigned char* __restrict__ vm,
                      unsigned char* __restrict__ adj)
{
    int i = blockIdx.x, b = blockIdx.y;
    size_t base = (size_t)b * NN1;
    float px = pos[(base + i) * 2], py = pos[(base + i) * 2 + 1];
    unsigned char vi = vm[base + i];
    for (int j = threadIdx.x; j < NN1; j += 256) {
        float dx = px - pos[(base + j) * 2];
        float dy = py - pos[(base + j) * 2 + 1];
        adj[((size_t)b * NN1 + i) * NN1 + j] =
            (unsigned char)((dx * dx + dy * dy < 4.0f) && vi && vm[base + j]);
    }
}

__global__ void k_adjd(const float* __restrict__ pos, const unsigned char* __restrict__ vm,
                       unsigned char* __restrict__ adjd)
{
    int i = blockIdx.x, b = blockIdx.y;
    size_t base = (size_t)b * NN1 + 512;
    float px = pos[(base + i) * 2], py = pos[(base + i) * 2 + 1];
    unsigned char vi = vm[base + i];
    for (int j = threadIdx.x; j < NNd; j += 256) {
        float dx = px - pos[(base + j) * 2];
        float dy = py - pos[(base + j) * 2 + 1];
        adjd[((size_t)b * NNd + i) * NNd + j] =
            (unsigned char)((dx * dx + dy * dy < 4.0f) && vi && vm[base + j]);
    }
}

// per-row src/dst head projections; grid = rows, block = 256
__global__ void k_srcdst(const float* __restrict__ Hm, const float* __restrict__ a0,
                         float* __restrict__ src, float* __restrict__ dst)
{
    size_t row = blockIdx.x;
    int d = threadIdx.x;
    float hv = Hm[row * 256 + d];
    float s = hv * a0[d];
    float t2 = hv * a0[256 + d];
    #pragma unroll
    for (int o = 16; o; o >>= 1) {
        s  += __shfl_xor_sync(0xffffffff, s, o);
        t2 += __shfl_xor_sync(0xffffffff, t2, o);
    }
    __shared__ float ps[8], pt[8];
    if ((d & 31) == 0) { ps[d >> 5] = s; pt[d >> 5] = t2; }
    __syncthreads();
    if (d < 4) {
        src[row * 4 + d] = ps[2 * d] + ps[2 * d + 1];
        dst[row * 4 + d] = pt[2 * d] + pt[2 * d + 1];
    }
}

// GAT edge softmax: alpha[b,h,i,:] ; grid = (NN, B), block = 128
__global__ void k_alpha(const float* __restrict__ src, const float* __restrict__ dst,
                        const unsigned char* __restrict__ adj, float* __restrict__ alpha,
                        int NN)
{
    int i = blockIdx.x, b = blockIdx.y;
    __shared__ float e[4096];
    const float* srci = src + ((size_t)b * NN + i) * 4;
    float s0 = srci[0], s1 = srci[1], s2 = srci[2], s3 = srci[3];
    const unsigned char* adjrow = adj + ((size_t)b * NN + i) * NN;
    const float* dstb = dst + (size_t)b * NN * 4;
    for (int j = threadIdx.x; j < NN; j += 128) {
        unsigned char msk = adjrow[j];
        float d0 = dstb[j * 4 + 0], d1 = dstb[j * 4 + 1];
        float d2 = dstb[j * 4 + 2], d3 = dstb[j * 4 + 3];
        float v0 = s0 + d0; v0 = v0 > 0.f ? v0 : 0.2f * v0;
        float v1 = s1 + d1; v1 = v1 > 0.f ? v1 : 0.2f * v1;
        float v2 = s2 + d2; v2 = v2 > 0.f ? v2 : 0.2f * v2;
        float v3 = s3 + d3; v3 = v3 > 0.f ? v3 : 0.2f * v3;
        e[j * 4 + 0] = msk ? v0 : -1e9f;
        e[j * 4 + 1] = msk ? v1 : -1e9f;
        e[j * 4 + 2] = msk ? v2 : -1e9f;
        e[j * 4 + 3] = msk ? v3 : -1e9f;
    }
    __syncthreads();
    int w = threadIdx.x >> 5, lane = threadIdx.x & 31;
    float mx = -1e30f;
    for (int j = lane; j < NN; j += 32) mx = fmaxf(mx, e[j * 4 + w]);
    #pragma unroll
    for (int o = 16; o; o >>= 1) mx = fmaxf(mx, __shfl_xor_sync(0xffffffff, mx, o));
    float sum = 0.f;
    for (int j = lane; j < NN; j += 32) {
        float ex = expf(e[j * 4 + w] - mx);
        e[j * 4 + w] = ex;
        sum += ex;
    }
    #pragma unroll
    for (int o = 16; o; o >>= 1) sum += __shfl_xor_sync(0xffffffff, sum, o);
    float inv = 1.f / sum;
    float* arow = alpha + (((size_t)b * 4 + w) * NN + i) * (size_t)NN;
    for (int j = lane; j < NN; j += 32) arow[j] = e[j * 4 + w] * inv;
}

// x = gw*elu(out) + ow*feat0
__global__ void k_gatmix(const float* __restrict__ out, const float* __restrict__ feat0,
                         float* __restrict__ x, size_t total)
{
    size_t idx = (size_t)blockIdx.x * 256 + threadIdx.x;
    if (idx >= total) return;
    float v = out[idx];
    v = (v > 0.f) ? v : expm1f(v);
    x[idx] = 0.5f * v + 0.5f * feat0[idx];
}

// sigmoid(raw/16)*adj (optional diag zero)
__global__ void k_scores(const float* __restrict__ raw, const unsigned char* __restrict__ adj,
                         float* __restrict__ out, int nnShift, int zerodiag)
{
    size_t idx = (size_t)blockIdx.x * 256 + threadIdx.x;
    int mask = (1 << nnShift) - 1;
    int j = (int)(idx & mask);
    int i = (int)((idx >> nnShift) & mask);
    float v = 0.f;
    if (adj[idx]) v = 1.f / (1.f + expf(-raw[idx] * 0.0625f));
    if (zerodiag && i == j) v = 0.f;
    out[idx] = v;
}

__global__ void k_asso(const float* __restrict__ scores, float* __restrict__ out)
{
    size_t idx = (size_t)blockIdx.x * 256 + threadIdx.x;
    int j = idx & 511;
    size_t r = idx >> 9;
    int m = r & 511;
    int b = (int)(r >> 9);
    out[idx] = scores[(((size_t)b * 1024 + m) * 1024) + 512 + j];
}

// ---------------------------------------------------------------------------
// Host side
// ---------------------------------------------------------------------------
static void run_gemm(const float* A, int lda, long long sA1, long long sA2,
                     const float* B, int ldb, long long sB1, long long sB2,
                     float* C, int ldc, long long sC1, long long sC2,
                     int M, int N, int K, int batch, int bdiv,
                     const float* bias, bool relu, bool transb)
{
    dim3 grid(N / 64, M / 64, batch);
    if (transb)
        sgemm_k<true, false><<<grid, 256>>>(A, lda, sA1, sA2, B, ldb, sB1, sB2,
                                            C, ldc, sC1, sC2, K, bdiv, bias);
    else if (relu)
        sgemm_k<false, true><<<grid, 256>>>(A, lda, sA1, sA2, B, ldb, sB1, sB2,
                                            C, ldc, sC1, sC2, K, bdiv, bias);
    else
        sgemm_k<false, false><<<grid, 256>>>(A, lda, sA1, sA2, B, ldb, sB1, sB2,
                                             C, ldc, sC1, sC2, K, bdiv, bias);
}

#define SYM(p, s) cudaGetSymbolAddress((void**)&p, s)

extern "C" void kernel_launch(void* const* d_in, const int* in_sizes, int n_in,
                              void* d_out, int out_size)
{
    (void)in_sizes; (void)n_in; (void)out_size;
    const float* tracks = (const float*)d_in[0];
    const float* dets   = (const float*)d_in[1];
    const int* tmarks   = (const int*)d_in[2];
    const int* dmarks   = (const int*)d_in[3];
    const float* W1     = (const float*)d_in[4];
    const float* b1     = (const float*)d_in[5];
    const float* W2     = (const float*)d_in[6];
    const float* b2     = (const float*)d_in[7];
    const float* Wqkv   = (const float*)d_in[8];
    const float* Wo     = (const float*)d_in[9];
    const float* ff1    = (const float*)d_in[10];
    const float* ff2    = (const float*)d_in[11];
    const float* gatW   = (const float*)d_in[12];
    const float* gata   = (const float*)d_in[13];
    const float* dgatW  = (const float*)d_in[14];
    const float* dgata  = (const float*)d_in[15];
    const float* clsWq  = (const float*)d_in[16];
    const float* clsWk  = (const float*)d_in[17];

    float* out = (float*)d_out;
    float* out_scores = out;
    float* out_det    = out + (size_t)BB * NN1 * NN1;
    float* out_asso   = out_det + (size_t)BB * NNd * NNd;

    float *tr_h1, *tr_emb, *ln, *kv, *det_h1, *det_emb, *q0, *o0, *wo, *x1,
          *ln2, *ffh, *ffout, *feat0, *x, *h, *gout, *src, *dst, *alpha,
          *pos, *xq, *xk;
    unsigned char *adj, *adjd, *vm;
    SYM(tr_h1, g_tr_h1);   SYM(tr_emb, g_tr_emb); SYM(ln, g_ln);
    SYM(kv, g_kv);         SYM(det_h1, g_det_h1); SYM(det_emb, g_det_emb);
    SYM(q0, g_q0);         SYM(o0, g_o0);         SYM(wo, g_wo);
    SYM(x1, g_x1);         SYM(ln2, g_ln2);       SYM(ffh, g_ffh);
    SYM(ffout, g_ffout);   SYM(feat0, g_feat0);   SYM(x, g_x);
    SYM(h, g_h);           SYM(gout, g_gout);     SYM(src, g_src);
    SYM(dst, g_dst);       SYM(alpha, g_alpha);   SYM(adj, g_adj);
    SYM(adjd, g_adjd);     SYM(pos, g_pos);       SYM(vm, g_vm);
    SYM(xq, g_xq);         SYM(xk, g_xk);

    // ---- feature MLP ----
    k_feat1<<<TM, 256>>>(tracks, W1, b1, tr_h1);
    run_gemm(tr_h1, 256, 0, 0, W2, 256, 0, 0, tr_emb, 256, 0, 0,
             TM, 256, 256, 1, 1, b2, false, false);
    k_feat1<<<ND, 256>>>(dets, W1, b1, det_h1);
    run_gemm(det_h1, 256, 0, 0, W2, 256, 0, 0, det_emb, 256, 0, 0,
             ND, 256, 256, 1, 1, b2, false, false);

    // ---- encoder (only r=0 outputs needed downstream) ----
    k_ln<<<TM, 256>>>(tr_emb, ln);
    run_gemm(ln, 256, 0, 0, Wqkv + 256, 768, 0, 0, kv, 512, 0, 0,
             TM, 512, 256, 1, 1, nullptr, false, false);           // K,V all rows
    run_gemm(ln, 2048, 0, 0, Wqkv, 768, 0, 0, q0, 256, 0, 0,
             TT, 256, 256, 1, 1, nullptr, false, false);           // Q only r=0
    k_attn<<<TT, 256>>>(q0, kv, o0);
    run_gemm(o0, 256, 0, 0, Wo, 256, 0, 0, wo, 256, 0, 0,
             TT, 256, 256, 1, 1, nullptr, false, false);
    k_x1<<<TT, 256>>>(tr_emb, wo, x1);
    k_ln<<<TT, 256>>>(x1, ln2);
    run_gemm(ln2, 256, 0, 0, ff1, 1024, 0, 0, ffh, 1024, 0, 0,
             TT, 1024, 256, 1, 1, nullptr, true, false);
    run_gemm(ffh, 1024, 0, 0, ff2, 256, 0, 0, ffout, 256, 0, 0,
             TT, 256, 1024, 1, 1, nullptr, false, false);
    k_feat0<<<ROWS1, 256>>>(tr_emb, x1, ffout, det_emb, feat0, x);

    // ---- adjacency ----
    k_posvm<<<64, 256>>>(tracks, dets, tmarks, dmarks, pos, vm);
    k_adj<<<dim3(NN1, BB), 256>>>(pos, vm, adj);
    k_adjd<<<dim3(NNd, BB), 256>>>(pos, vm, adjd);

    // ---- main GAT x2 ----
    for (int l = 0; l < 2; l++) {
        run_gemm(x, 256, 0, 0, gatW + (size_t)l * 256 * 256, 256, 0, 0,
                 h, 256, 0, 0, ROWS1, 256, 256, 1, 1, nullptr, false, false);
        k_srcdst<<<ROWS1, 256>>>(h, gata + (size_t)l * 512, src, dst);
        k_alpha<<<dim3(NN1, BB), 128>>>(src, dst, adj, alpha, NN1);
        run_gemm(alpha, NN1, 4LL * NN1 * NN1, (long long)NN1 * NN1,
                 h, 256, (long long)NN1 * 256, 64,
                 gout, 256, (long long)NN1 * 256, 64,
                 NN1, 64, NN1, BB * HH, HH, nullptr, false, false);
        k_gatmix<<<ROWS1, 256>>>(gout, feat0, x, (size_t)ROWS1 * 256);
    }

    // ---- main scores ----
    run_gemm(x, 256, 0, 0, clsWq, 256, 0, 0, xq, 256, 0, 0,
             ROWS1, 256, 256, 1, 1, nullptr, false, false);
    run_gemm(x, 256, 0, 0, clsWk, 256, 0, 0, xk, 256, 0, 0,
             ROWS1, 256, 256, 1, 1, nullptr, false, false);
    run_gemm(xq, 256, (long long)NN1 * 256, 0,
             xk, 256, (long long)NN1 * 256, 0,
             alpha, NN1, (long long)NN1 * NN1, 0,
             NN1, NN1, 256, BB, 1, nullptr, false, true);          // raw = XQ @ XK^T
    k_scores<<<(int)(((size_t)BB * NN1 * NN1) / 256), 256>>>(alpha, adj, out_scores, 10, 0);
    k_asso<<<(int)(((size_t)BB * 512 * 512) / 256), 256>>>(out_scores, out_asso);

    // ---- detection GAT x2 ----
    for (int l = 0; l < 2; l++) {
        const float* xin = (l == 0) ? det_emb : x;
        run_gemm(xin, 256, 0, 0, dgatW + (size_t)l * 256 * 256, 256, 0, 0,
                 h, 256, 0, 0, ND, 256, 256, 1, 1, nullptr, false, false);
        k_srcdst<<<ND, 256>>>(h, dgata + (size_t)l * 512, src, dst);
        k_alpha<<<dim3(NNd, BB), 128>>>(src, dst, adjd, alpha, NNd);
        run_gemm(alpha, NNd, 4LL * NNd * NNd, (long long)NNd * NNd,
                 h, 256, (long long)NNd * 256, 64,
                 gout, 256, (long long)NNd * 256, 64,
                 NNd, 64, NNd, BB * HH, HH, nullptr, false, false);
        k_gatmix<<<ND, 256>>>(gout, det_emb, x, (size_t)ND * 256);
    }

    // ---- detection scores ----
    run_gemm(x, 256, 0, 0, clsWq + 256 * 256, 256, 0, 0, xq, 256, 0, 0,
             ND, 256, 256, 1, 1, nullptr, false, false);
    run_gemm(x, 256, 0, 0, clsWk + 256 * 256, 256, 0, 0, xk, 256, 0, 0,
             ND, 256, 256, 1, 1, nullptr, false, false);
    run_gemm(xq, 256, (long long)NNd * 256, 0,
             xk, 256, (long long)NNd * 256, 0,
             alpha, NNd, (long long)NNd * NNd, 0,
             NNd, NNd, 256, BB, 1, nullptr, false, true);
    k_scores<<<(int)(((size_t)BB * NNd * NNd) / 256), 256>>>(alpha, adjd, out_det, 9, 1);
}

// round 2
// speedup vs baseline: 1.5308x; 1.5308x over previous
#include <cuda_runtime.h>
#include <math.h>
#include <stdint.h>

// ---------------------------------------------------------------------------
// Problem dims (compile-time)
// ---------------------------------------------------------------------------
#define BB 16
#define MM 512
#define NNd 512
#define RR 8
#define DD 256
#define HH 4
#define DHH 64
#define NN1 1024          // M + N
#define TM  (BB*MM*RR)    // 65536 track-feature rows
#define TT  (BB*MM)       // 8192 tokens
#define ND  (BB*NNd)      // 8192 detection rows
#define ROWS1 (BB*NN1)    // 16384 graph rows

// ---------------------------------------------------------------------------
// Scratch (device globals — no allocation allowed)
// ---------------------------------------------------------------------------
__device__ float g_tr_h1[TM*DD];
__device__ float g_tr_emb[TM*DD];
__device__ float g_ln[TM*DD];
__device__ float g_kv[TM*512];
__device__ float g_det_h1[ND*DD];
__device__ float g_det_emb[ND*DD];
__device__ float g_q0[TT*DD];
__device__ float g_o0[TT*DD];
__device__ float g_wo[TT*DD];
__device__ float g_x1[TT*DD];
__device__ float g_ln2[TT*DD];
__device__ float g_ffh[TT*1024];
__device__ float g_ffout[TT*DD];
__device__ float g_feat0[ROWS1*DD];
__device__ float g_x[ROWS1*DD];
__device__ float g_h[ROWS1*DD];
__device__ float g_gout[ROWS1*DD];
__device__ float g_src[ROWS1*HH];
__device__ float g_dst[ROWS1*HH];
__device__ float g_alpha[(size_t)BB*HH*NN1*NN1];   // 268MB, reused as raw scores
__device__ unsigned char g_adj[(size_t)BB*NN1*NN1];
__device__ unsigned char g_adjd[(size_t)BB*NNd*NNd];
__device__ float g_pos[BB*NN1*2];
__device__ unsigned char g_vm[BB*NN1];
__device__ float g_xq[ROWS1*DD];
__device__ float g_xk[ROWS1*DD];

// ---------------------------------------------------------------------------
// tf32 tensor-core GEMM: C = A @ B (+bias)(+relu), optional B^T, 2-level batch
// CTA tile 128x64, BK=16, 256 threads = 8 warps in 4x2 grid, warp tile 32x32.
// mma.sync.m16n8k8 tf32. Requires M%128==0, N%64==0, K%16==0 (all call sites).
// ---------------------------------------------------------------------------
__device__ __forceinline__ float to_tf32(float x) {
    float r;
    asm("cvt.rna.tf32.f32 %0, %1;" : "=f"(r) : "f"(x));
    return r;
}

__device__ __forceinline__ void mma_tf32(float* c, const uint32_t* a, const uint32_t* b) {
    asm volatile(
        "mma.sync.aligned.m16n8k8.row.col.f32.tf32.tf32.f32 "
        "{%0,%1,%2,%3}, {%4,%5,%6,%7}, {%8,%9}, {%0,%1,%2,%3};\n"
        : "+f"(c[0]), "+f"(c[1]), "+f"(c[2]), "+f"(c[3])
        : "r"(a[0]), "r"(a[1]), "r"(a[2]), "r"(a[3]), "r"(b[0]), "r"(b[1]));
}

template<bool TRANSB, bool RELU>
__global__ __launch_bounds__(256)
void tgemm_k(const float* __restrict__ A, int lda, long long sA1, long long sA2,
             const float* __restrict__ B, int ldb, long long sB1, long long sB2,
             float* __restrict__ C, int ldc, long long sC1, long long sC2,
             int K, int bdiv, const float* __restrict__ bias)
{
    int bz = blockIdx.z;
    int b1 = bz / bdiv, b2 = bz - b1 * bdiv;
    A += (long long)b1 * sA1 + (long long)b2 * sA2;
    B += (long long)b1 * sB1 + (long long)b2 * sB2;
    C += (long long)b1 * sC1 + (long long)b2 * sC2;

    int m0 = blockIdx.y * 128, n0 = blockIdx.x * 64;

    __shared__ float As[128 * 20];          // [m][k], stride 20 (conflict-free frags)
    __shared__ float Bs[1280];              // !TRANSB: [k][n] stride 72; TRANSB: [n][k] stride 20

    int tid = threadIdx.x;

    // global load pointers
    const float* aptr0 = A + (size_t)(m0 + (tid >> 2)) * lda + (tid & 3) * 4;
    const float* aptr1 = aptr0 + (size_t)64 * lda;
    const float* bptr;
    if (!TRANSB) bptr = B + (size_t)(tid >> 4) * ldb + n0 + (tid & 15) * 4;
    else         bptr = B + (size_t)(n0 + (tid >> 2)) * ldb + (tid & 3) * 4;

    // smem store pointers
    float* as0 = &As[(tid >> 2) * 20 + (tid & 3) * 4];
    float* as1 = &As[((tid >> 2) + 64) * 20 + (tid & 3) * 4];
    float* bs;
    if (!TRANSB) bs = &Bs[(tid >> 4) * 72 + (tid & 15) * 4];
    else         bs = &Bs[(tid >> 2) * 20 + (tid & 3) * 4];

    int w = tid >> 5, l = tid & 31;
    int wm = w >> 1, wn = w & 1;
    int mrow = wm * 32, ncol = wn * 32;
    int grp = l >> 2, tig = l & 3;

    float acc[2][4][4];
    #pragma unroll
    for (int i = 0; i < 2; i++)
        #pragma unroll
        for (int j = 0; j < 4; j++)
            #pragma unroll
            for (int q = 0; q < 4; q++) acc[i][j][q] = 0.f;

    float4 ra0, ra1, rb;
    // prologue load
    ra0 = *(const float4*)(aptr0);
    ra1 = *(const float4*)(aptr1);
    if (!TRANSB) rb = *(const float4*)(bptr);
    else         rb = *(const float4*)(bptr);

    for (int k0 = 0; k0 < K; k0 += 16) {
        // store current tile to smem (with tf32 rounding)
        as0[0] = to_tf32(ra0.x); as0[1] = to_tf32(ra0.y); as0[2] = to_tf32(ra0.z); as0[3] = to_tf32(ra0.w);
        as1[0] = to_tf32(ra1.x); as1[1] = to_tf32(ra1.y); as1[2] = to_tf32(ra1.z); as1[3] = to_tf32(ra1.w);
        bs[0] = to_tf32(rb.x); bs[1] = to_tf32(rb.y); bs[2] = to_tf32(rb.z); bs[3] = to_tf32(rb.w);
        __syncthreads();

        // prefetch next tile
        if (k0 + 16 < K) {
            ra0 = *(const float4*)(aptr0 + k0 + 16);
            ra1 = *(const float4*)(aptr1 + k0 + 16);
            if (!TRANSB) rb = *(const float4*)(bptr + (size_t)(k0 + 16) * ldb);
            else         rb = *(const float4*)(bptr + k0 + 16);
        }

        #pragma unroll
        for (int kk = 0; kk < 16; kk += 8) {
            uint32_t af[2][4];
            #pragma unroll
            for (int fm = 0; fm < 2; fm++) {
                int r = (mrow + fm * 16 + grp) * 20;
                af[fm][0] = __float_as_uint(As[r + kk + tig]);
                af[fm][1] = __float_as_uint(As[r + 160 + kk + tig]);        // +8 rows
                af[fm][2] = __float_as_uint(As[r + kk + tig + 4]);
                af[fm][3] = __float_as_uint(As[r + 160 + kk + tig + 4]);
            }
            uint32_t bf[4][2];
            #pragma unroll
            for (int fn = 0; fn < 4; fn++) {
                int c = ncol + fn * 8 + grp;
                if (!TRANSB) {
                    bf[fn][0] = __float_as_uint(Bs[(kk + tig) * 72 + c]);
                    bf[fn][1] = __float_as_uint(Bs[(kk + tig + 4) * 72 + c]);
                } else {
                    bf[fn][0] = __float_as_uint(Bs[c * 20 + kk + tig]);
                    bf[fn][1] = __float_as_uint(Bs[c * 20 + kk + tig + 4]);
                }
            }
            #pragma unroll
            for (int fm = 0; fm < 2; fm++)
                #pragma unroll
                for (int fn = 0; fn < 4; fn++)
                    mma_tf32(acc[fm][fn], af[fm], bf[fn]);
        }
        __syncthreads();
    }

    // epilogue
    #pragma unroll
    for (int fm = 0; fm < 2; fm++) {
        int row = m0 + mrow + fm * 16 + grp;
        #pragma unroll
        for (int fn = 0; fn < 4; fn++) {
            int col = n0 + ncol + fn * 8 + 2 * tig;
            float v0 = acc[fm][fn][0], v1 = acc[fm][fn][1];
            float v2 = acc[fm][fn][2], v3 = acc[fm][fn][3];
            if (bias) {
                float bb0 = bias[col], bb1 = bias[col + 1];
                v0 += bb0; v1 += bb1; v2 += bb0; v3 += bb1;
            }
            if (RELU) {
                v0 = fmaxf(v0, 0.f); v1 = fmaxf(v1, 0.f);
                v2 = fmaxf(v2, 0.f); v3 = fmaxf(v3, 0.f);
            }
            float2 p0 = make_float2(v0, v1);
            float2 p1 = make_float2(v2, v3);
            *(float2*)&C[(size_t)row * ldc + col] = p0;
            *(float2*)&C[(size_t)(row + 8) * ldc + col] = p1;
        }
    }
}

// ---------------------------------------------------------------------------
// Small kernels
// ---------------------------------------------------------------------------
__global__ void k_feat1(const float* __restrict__ x, const float* __restrict__ W1,
                        const float* __restrict__ b1, float* __restrict__ out)
{
    size_t idx = (size_t)blockIdx.x * 256 + threadIdx.x;
    size_t row = idx >> 8;
    int d = idx & 255;
    const float* xr = x + row * 4;
    float v = b1[d] + xr[0]*W1[d] + xr[1]*W1[256+d] + xr[2]*W1[512+d] + xr[3]*W1[768+d];
    out[idx] = (v > 0.f) ? v : expm1f(v);
}

__global__ void k_ln(const float* __restrict__ in, float* __restrict__ out)
{
    size_t row = blockIdx.x;
    int t = threadIdx.x;
    float v = in[row * 256 + t];
    float a = v, b = v * v;
    #pragma unroll
    for (int o = 16; o; o >>= 1) {
        a += __shfl_xor_sync(0xffffffff, a, o);
        b += __shfl_xor_sync(0xffffffff, b, o);
    }
    __shared__ float sa[8], sb[8];
    if ((t & 31) == 0) { sa[t >> 5] = a; sb[t >> 5] = b; }
    __syncthreads();
    if (t < 32) {
        a = (t < 8) ? sa[t] : 0.f;
        b = (t < 8) ? sb[t] : 0.f;
        #pragma unroll
        for (int o = 4; o; o >>= 1) {
            a += __shfl_xor_sync(0xffffffff, a, o);
            b += __shfl_xor_sync(0xffffffff, b, o);
        }
        if (t == 0) { sa[0] = a; sb[0] = b; }
    }
    __syncthreads();
    float mean = sa[0] * (1.f / 256.f);
    float var = sb[0] * (1.f / 256.f) - mean * mean;
    out[row * 256 + t] = (v - mean) * rsqrtf(var + 1e-5f);
}

__global__ void k_attn(const float* __restrict__ q0, const float* __restrict__ kv,
                       float* __restrict__ o0)
{
    size_t t = blockIdx.x;
    int d = threadIdx.x;
    int h = d >> 6;
    __shared__ float logits[4][8];
    __shared__ float red[8];
    float qd = q0[t * 256 + d];
    for (int s = 0; s < 8; s++) {
        float p = qd * kv[(t * 8 + s) * 512 + d];
        #pragma unroll
        for (int o = 16; o; o >>= 1) p += __shfl_xor_sync(0xffffffff, p, o);
        if ((d & 31) == 0) red[d >> 5] = p;
        __syncthreads();
        if (d < 4) logits[d][s] = (red[2 * d] + red[2 * d + 1]) * 0.125f;
        __syncthreads();
    }
    float m = -1e30f;
    #pragma unroll
    for (int s = 0; s < 8; s++) m = fmaxf(m, logits[h][s]);
    float w[8], sum = 0.f;
    #pragma unroll
    for (int s = 0; s < 8; s++) { w[s] = expf(logits[h][s] - m); sum += w[s]; }
    float inv = 1.f / sum;
    float o = 0.f;
    #pragma unroll
    for (int s = 0; s < 8; s++) o += w[s] * inv * kv[(t * 8 + s) * 512 + 256 + d];
    o0[t * 256 + d] = o;
}

__global__ void k_x1(const float* __restrict__ tr_emb, const float* __restrict__ wo,
                     float* __restrict__ x1)
{
    size_t idx = (size_t)blockIdx.x * 256 + threadIdx.x;
    size_t t = idx >> 8;
    int d = idx & 255;
    x1[idx] = tr_emb[t * 2048 + d] + wo[idx];
}

__global__ void k_feat0(const float* __restrict__ tr_emb, const float* __restrict__ x1,
                        const float* __restrict__ ffout, const float* __restrict__ det_emb,
                        float* __restrict__ feat0, float* __restrict__ x)
{
    size_t idx = (size_t)blockIdx.x * 256 + threadIdx.x;
    int d = idx & 255;
    size_t row = idx >> 8;
    int i = row & 1023;
    int b = row >> 10;
    float v;
    if (i < 512) {
        size_t t = (size_t)b * 512 + i;
        v = tr_emb[t * 2048 + d] + 0.9f * (x1[t * 256 + d] + ffout[t * 256 + d]);
    } else {
        size_t t = (size_t)b * 512 + (i - 512);
        v = det_emb[t * 256 + d];
    }
    feat0[idx] = v;
    x[idx] = v;
}

__global__ void k_posvm(const float* __restrict__ tracks, const float* __restrict__ dets,
                        const int* __restrict__ tmarks, const int* __restrict__ dmarks,
                        float* __restrict__ pos, unsigned char* __restrict__ vm)
{
    int idx = blockIdx.x * 256 + threadIdx.x;
    if (idx >= BB * NN1) return;
    int b = idx >> 10, i = idx & 1023;
    float x, y; unsigned char v;
    if (i < 512) {
        const float* p = tracks + ((size_t)(b * 512 + i)) * 8 * 4;
        x = p[0]; y = p[1];
        v = (i < tmarks[b]);
    } else {
        int n = i - 512;
        const float* p = dets + ((size_t)(b * 512 + n)) * 4;
        x = p[0]; y = p[1];
        v = (n < dmarks[b]);
    }
    pos[idx * 2] = x; pos[idx * 2 + 1] = y; vm[idx] = v;
}

__global__ void k_adj(const float* __restrict__ pos, const unsigned char* __restrict__ vm,
                      unsigned char* __restrict__ adj)
{
    int i = blockIdx.x, b = blockIdx.y;
    size_t base = (size_t)b * NN1;
    float px = pos[(base + i) * 2], py = pos[(base + i) * 2 + 1];
    unsigned char vi = vm[base + i];
    for (int j = threadIdx.x; j < NN1; j += 256) {
        float dx = px - pos[(base + j) * 2];
        float dy = py - pos[(base + j) * 2 + 1];
        adj[((size_t)b * NN1 + i) * NN1 + j] =
            (unsigned char)((dx * dx + dy * dy < 4.0f) && vi && vm[base + j]);
    }
}

__global__ void k_adjd(const float* __restrict__ pos, const unsigned char* __restrict__ vm,
                       unsigned char* __restrict__ adjd)
{
    int i = blockIdx.x, b = blockIdx.y;
    size_t base = (size_t)b * NN1 + 512;
    float px = pos[(base + i) * 2], py = pos[(base + i) * 2 + 1];
    unsigned char vi = vm[base + i];
    for (int j = threadIdx.x; j < NNd; j += 256) {
        float dx = px - pos[(base + j) * 2];
        float dy = py - pos[(base + j) * 2 + 1];
        adjd[((size_t)b * NNd + i) * NNd + j] =
            (unsigned char)((dx * dx + dy * dy < 4.0f) && vi && vm[base + j]);
    }
}

__global__ void k_srcdst(const float* __restrict__ Hm, const float* __restrict__ a0,
                         float* __restrict__ src, float* __restrict__ dst)
{
    size_t row = blockIdx.x;
    int d = threadIdx.x;
    float hv = Hm[row * 256 + d];
    float s = hv * a0[d];
    float t2 = hv * a0[256 + d];
    #pragma unroll
    for (int o = 16; o; o >>= 1) {
        s  += __shfl_xor_sync(0xffffffff, s, o);
        t2 += __shfl_xor_sync(0xffffffff, t2, o);
    }
    __shared__ float ps[8], pt[8];
    if ((d & 31) == 0) { ps[d >> 5] = s; pt[d >> 5] = t2; }
    __syncthreads();
    if (d < 4) {
        src[row * 4 + d] = ps[2 * d] + ps[2 * d + 1];
        dst[row * 4 + d] = pt[2 * d] + pt[2 * d + 1];
    }
}

__global__ void k_alpha(const float* __restrict__ src, const float* __restrict__ dst,
                        const unsigned char* __restrict__ adj, float* __restrict__ alpha,
                        int NN)
{
    int i = blockIdx.x, b = blockIdx.y;
    __shared__ float e[4096];
    const float* srci = src + ((size_t)b * NN + i) * 4;
    float s0 = srci[0], s1 = srci[1], s2 = srci[2], s3 = srci[3];
    const unsigned char* adjrow = adj + ((size_t)b * NN + i) * NN;
    const float* dstb = dst + (size_t)b * NN * 4;
    for (int j = threadIdx.x; j < NN; j += 128) {
        unsigned char msk = adjrow[j];
        float d0 = dstb[j * 4 + 0], d1 = dstb[j * 4 + 1];
        float d2 = dstb[j * 4 + 2], d3 = dstb[j * 4 + 3];
        float v0 = s0 + d0; v0 = v0 > 0.f ? v0 : 0.2f * v0;
        float v1 = s1 + d1; v1 = v1 > 0.f ? v1 : 0.2f * v1;
        float v2 = s2 + d2; v2 = v2 > 0.f ? v2 : 0.2f * v2;
        float v3 = s3 + d3; v3 = v3 > 0.f ? v3 : 0.2f * v3;
        e[j * 4 + 0] = msk ? v0 : -1e9f;
        e[j * 4 + 1] = msk ? v1 : -1e9f;
        e[j * 4 + 2] = msk ? v2 : -1e9f;
        e[j * 4 + 3] = msk ? v3 : -1e9f;
    }
    __syncthreads();
    int w = threadIdx.x >> 5, lane = threadIdx.x & 31;
    float mx = -1e30f;
    for (int j = lane; j < NN; j += 32) mx = fmaxf(mx, e[j * 4 + w]);
    #pragma unroll
    for (int o = 16; o; o >>= 1) mx = fmaxf(mx, __shfl_xor_sync(0xffffffff, mx, o));
    float sum = 0.f;
    for (int j = lane; j < NN; j += 32) {
        float ex = expf(e[j * 4 + w] - mx);
        e[j * 4 + w] = ex;
        sum += ex;
    }
    #pragma unroll
    for (int o = 16; o; o >>= 1) sum += __shfl_xor_sync(0xffffffff, sum, o);
    float inv = 1.f / sum;
    float* arow = alpha + (((size_t)b * 4 + w) * NN + i) * (size_t)NN;
    for (int j = lane; j < NN; j += 32) arow[j] = e[j * 4 + w] * inv;
}

__global__ void k_gatmix(const float* __restrict__ out, const float* __restrict__ feat0,
                         float* __restrict__ x, size_t total)
{
    size_t idx = (size_t)blockIdx.x * 256 + threadIdx.x;
    if (idx >= total) return;
    float v = out[idx];
    v = (v > 0.f) ? v : expm1f(v);
    x[idx] = 0.5f * v + 0.5f * feat0[idx];
}

__global__ void k_scores(const float* __restrict__ raw, const unsigned char* __restrict__ adj,
                         float* __restrict__ out, int nnShift, int zerodiag)
{
    size_t idx = (size_t)blockIdx.x * 256 + threadIdx.x;
    int mask = (1 << nnShift) - 1;
    int j = (int)(idx & mask);
    int i = (int)((idx >> nnShift) & mask);
    float v = 0.f;
    if (adj[idx]) v = 1.f / (1.f + expf(-raw[idx] * 0.0625f));
    if (zerodiag && i == j) v = 0.f;
    out[idx] = v;
}

__global__ void k_asso(const float* __restrict__ scores, float* __restrict__ out)
{
    size_t idx = (size_t)blockIdx.x * 256 + threadIdx.x;
    int j = idx & 511;
    size_t r = idx >> 9;
    int m = r & 511;
    int b = (int)(r >> 9);
    out[idx] = scores[(((size_t)b * 1024 + m) * 1024) + 512 + j];
}

// ---------------------------------------------------------------------------
// Host side
// ---------------------------------------------------------------------------
static void run_gemm(const float* A, int lda, long long sA1, long long sA2,
                     const float* B, int ldb, long long sB1, long long sB2,
                     float* C, int ldc, long long sC1, long long sC2,
                     int M, int N, int K, int batch, int bdiv,
                     const float* bias, bool relu, bool transb)
{
    dim3 grid(N / 64, M / 128, batch);
    if (transb)
        tgemm_k<true, false><<<grid, 256>>>(A, lda, sA1, sA2, B, ldb, sB1, sB2,
                                            C, ldc, sC1, sC2, K, bdiv, bias);
    else if (relu)
        tgemm_k<false, true><<<grid, 256>>>(A, lda, sA1, sA2, B, ldb, sB1, sB2,
                                            C, ldc, sC1, sC2, K, bdiv, bias);
    else
        tgemm_k<false, false><<<grid, 256>>>(A, lda, sA1, sA2, B, ldb, sB1, sB2,
                                             C, ldc, sC1, sC2, K, bdiv, bias);
}

#define SYM(p, s) cudaGetSymbolAddress((void**)&p, s)

extern "C" void kernel_launch(void* const* d_in, const int* in_sizes, int n_in,
                              void* d_out, int out_size)
{
    (void)in_sizes; (void)n_in; (void)out_size;
    const float* tracks = (const float*)d_in[0];
    const float* dets   = (const float*)d_in[1];
    const int* tmarks   = (const int*)d_in[2];
    const int* dmarks   = (const int*)d_in[3];
    const float* W1     = (const float*)d_in[4];
    const float* b1     = (const float*)d_in[5];
    const float* W2     = (const float*)d_in[6];
    const float* b2     = (const float*)d_in[7];
    const float* Wqkv   = (const float*)d_in[8];
    const float* Wo     = (const float*)d_in[9];
    const float* ff1    = (const float*)d_in[10];
    const float* ff2    = (const float*)d_in[11];
    const float* gatW   = (const float*)d_in[12];
    const float* gata   = (const float*)d_in[13];
    const float* dgatW  = (const float*)d_in[14];
    const float* dgata  = (const float*)d_in[15];
    const float* clsWq  = (const float*)d_in[16];
    const float* clsWk  = (const float*)d_in[17];

    float* out = (float*)d_out;
    float* out_scores = out;
    float* out_det    = out + (size_t)BB * NN1 * NN1;
    float* out_asso   = out_det + (size_t)BB * NNd * NNd;

    float *tr_h1, *tr_emb, *ln, *kv, *det_h1, *det_emb, *q0, *o0, *wo, *x1,
          *ln2, *ffh, *ffout, *feat0, *x, *h, *gout, *src, *dst, *alpha,
          *pos, *xq, *xk;
    unsigned char *adj, *adjd, *vm;
    SYM(tr_h1, g_tr_h1);   SYM(tr_emb, g_tr_emb); SYM(ln, g_ln);
    SYM(kv, g_kv);         SYM(det_h1, g_det_h1); SYM(det_emb, g_det_emb);
    SYM(q0, g_q0);         SYM(o0, g_o0);         SYM(wo, g_wo);
    SYM(x1, g_x1);         SYM(ln2, g_ln2);       SYM(ffh, g_ffh);
    SYM(ffout, g_ffout);   SYM(feat0, g_feat0);   SYM(x, g_x);
    SYM(h, g_h);           SYM(gout, g_gout);     SYM(src, g_src);
    SYM(dst, g_dst);       SYM(alpha, g_alpha);   SYM(adj, g_adj);
    SYM(adjd, g_adjd);     SYM(pos, g_pos);       SYM(vm, g_vm);
    SYM(xq, g_xq);         SYM(xk, g_xk);

    // ---- feature MLP ----
    k_feat1<<<TM, 256>>>(tracks, W1, b1, tr_h1);
    run_gemm(tr_h1, 256, 0, 0, W2, 256, 0, 0, tr_emb, 256, 0, 0,
             TM, 256, 256, 1, 1, b2, false, false);
    k_feat1<<<ND, 256>>>(dets, W1, b1, det_h1);
    run_gemm(det_h1, 256, 0, 0, W2, 256, 0, 0, det_emb, 256, 0, 0,
             ND, 256, 256, 1, 1, b2, false, false);

    // ---- encoder (only r=0 outputs needed downstream) ----
    k_ln<<<TM, 256>>>(tr_emb, ln);
    run_gemm(ln, 256, 0, 0, Wqkv + 256, 768, 0, 0, kv, 512, 0, 0,
             TM, 512, 256, 1, 1, nullptr, false, false);           // K,V all rows
    run_gemm(ln, 2048, 0, 0, Wqkv, 768, 0, 0, q0, 256, 0, 0,
             TT, 256, 256, 1, 1, nullptr, false, false);           // Q only r=0
    k_attn<<<TT, 256>>>(q0, kv, o0);
    run_gemm(o0, 256, 0, 0, Wo, 256, 0, 0, wo, 256, 0, 0,
             TT, 256, 256, 1, 1, nullptr, false, false);
    k_x1<<<TT, 256>>>(tr_emb, wo, x1);
    k_ln<<<TT, 256>>>(x1, ln2);
    run_gemm(ln2, 256, 0, 0, ff1, 1024, 0, 0, ffh, 1024, 0, 0,
             TT, 1024, 256, 1, 1, nullptr, true, false);
    run_gemm(ffh, 1024, 0, 0, ff2, 256, 0, 0, ffout, 256, 0, 0,
             TT, 256, 1024, 1, 1, nullptr, false, false);
    k_feat0<<<ROWS1, 256>>>(tr_emb, x1, ffout, det_emb, feat0, x);

    // ---- adjacency ----
    k_posvm<<<64, 256>>>(tracks, dets, tmarks, dmarks, pos, vm);
    k_adj<<<dim3(NN1, BB), 256>>>(pos, vm, adj);
    k_adjd<<<dim3(NNd, BB), 256>>>(pos, vm, adjd);

    // ---- main GAT x2 ----
    for (int l = 0; l < 2; l++) {
        run_gemm(x, 256, 0, 0, gatW + (size_t)l * 256 * 256, 256, 0, 0,
                 h, 256, 0, 0, ROWS1, 256, 256, 1, 1, nullptr, false, false);
        k_srcdst<<<ROWS1, 256>>>(h, gata + (size_t)l * 512, src, dst);
        k_alpha<<<dim3(NN1, BB), 128>>>(src, dst, adj, alpha, NN1);
        run_gemm(alpha, NN1, 4LL * NN1 * NN1, (long long)NN1 * NN1,
                 h, 256, (long long)NN1 * 256, 64,
                 gout, 256, (long long)NN1 * 256, 64,
                 NN1, 64, NN1, BB * HH, HH, nullptr, false, false);
        k_gatmix<<<ROWS1, 256>>>(gout, feat0, x, (size_t)ROWS1 * 256);
    }

    // ---- main scores ----
    run_gemm(x, 256, 0, 0, clsWq, 256, 0, 0, xq, 256, 0, 0,
             ROWS1, 256, 256, 1, 1, nullptr, false, false);
    run_gemm(x, 256, 0, 0, clsWk, 256, 0, 0, xk, 256, 0, 0,
             ROWS1, 256, 256, 1, 1, nullptr, false, false);
    run_gemm(xq, 256, (long long)NN1 * 256, 0,
             xk, 256, (long long)NN1 * 256, 0,
             alpha, NN1, (long long)NN1 * NN1, 0,
             NN1, NN1, 256, BB, 1, nullptr, false, true);          // raw = XQ @ XK^T
    k_scores<<<(int)(((size_t)BB * NN1 * NN1) / 256), 256>>>(alpha, adj, out_scores, 10, 0);
    k_asso<<<(int)(((size_t)BB * 512 * 512) / 256), 256>>>(out_scores, out_asso);

    // ---- detection GAT x2 ----
    for (int l = 0; l < 2; l++) {
        const float* xin = (l == 0) ? det_emb : x;
        run_gemm(xin, 256, 0, 0, dgatW + (size_t)l * 256 * 256, 256, 0, 0,
                 h, 256, 0, 0, ND, 256, 256, 1, 1, nullptr, false, false);
        k_srcdst<<<ND, 256>>>(h, dgata + (size_t)l * 512, src, dst);
        k_alpha<<<dim3(NNd, BB), 128>>>(src, dst, adjd, alpha, NNd);
        run_gemm(alpha, NNd, 4LL * NNd * NNd, (long long)NNd * NNd,
                 h, 256, (long long)NNd * 256, 64,
                 gout, 256, (long long)NNd * 256, 64,
                 NNd, 64, NNd, BB * HH, HH, nullptr, false, false);
        k_gatmix<<<ND, 256>>>(gout, det_emb, x, (size_t)ND * 256);
    }

    // ---- detection scores ----
    run_gemm(x, 256, 0, 0, clsWq + 256 * 256, 256, 0, 0, xq, 256, 0, 0,
             ND, 256, 256, 1, 1, nullptr, false, false);
    run_gemm(x, 256, 0, 0, clsWk + 256 * 256, 256, 0, 0, xk, 256, 0, 0,
             ND, 256, 256, 1, 1, nullptr, false, false);
    run_gemm(xq, 256, (long long)NNd * 256, 0,
             xk, 256, (long long)NNd * 256, 0,
             alpha, NNd, (long long)NNd * NNd, 0,
             NNd, NNd, 256, BB, 1, nullptr, false, true);
    k_scores<<<(int)(((size_t)BB * NNd * NNd) / 256), 256>>>(alpha, adjd, out_det, 9, 1);
}

// round 4
// speedup vs baseline: 2.7401x; 1.7900x over previous
#include <cuda_runtime.h>
#include <math.h>
#include <stdint.h>

// ---------------------------------------------------------------------------
// Problem dims (compile-time)
// ---------------------------------------------------------------------------
#define BB 16
#define MM 512
#define NNd 512
#define RR 8
#define DD 256
#define HH 4
#define NN1 1024          // M + N
#define TM  (BB*MM*RR)    // 65536 track-feature rows
#define TT  (BB*MM)       // 8192 tokens
#define ND  (BB*NNd)      // 8192 detection rows
#define ROWS1 (BB*NN1)    // 16384 graph rows

// epilogue flags
#define F_BIAS 1
#define F_RELU 2
#define F_AUX  4
#define F_SIG  8
#define F_DIAG 16

// ---------------------------------------------------------------------------
// Scratch (device globals — no allocation allowed)
// ---------------------------------------------------------------------------
__device__ float g_tr_h1[TM*DD];
__device__ float g_tr_emb[TM*DD];
__device__ float g_ln[TM*DD];
__device__ float g_kv[TM*512];
__device__ float g_det_h1[ND*DD];
__device__ float g_det_emb[ND*DD];
__device__ float g_q0[TT*DD];
__device__ float g_o0[TT*DD];
__device__ float g_x1[TT*DD];
__device__ float g_ln2[TT*DD];
__device__ float g_ffh[TT*1024];
__device__ float g_ffout[TT*DD];
__device__ float g_feat0[ROWS1*DD];
__device__ float g_x[ROWS1*DD];
__device__ float g_h[ROWS1*DD];
__device__ float g_src[ROWS1*HH];
__device__ float g_dst[ROWS1*HH];
__device__ float g_alpha[(size_t)BB*HH*NN1*NN1];   // 268MB
__device__ unsigned char g_adj[(size_t)BB*NN1*NN1];
__device__ unsigned char g_adjd[(size_t)BB*NNd*NNd];
__device__ float g_pos[BB*NN1*2];
__device__ unsigned char g_vm[BB*NN1];
__device__ float g_xq[ROWS1*DD];
__device__ float g_xk[ROWS1*DD];

// ---------------------------------------------------------------------------
// MMA helpers
// ---------------------------------------------------------------------------
__device__ __forceinline__ float to_tf32(float x) {
    float r;
    asm("cvt.rna.tf32.f32 %0, %1;" : "=f"(r) : "f"(x));
    return r;
}

__device__ __forceinline__ void mma_tf32(float* c, const uint32_t* a, const uint32_t* b) {
    asm volatile(
        "mma.sync.aligned.m16n8k8.row.col.f32.tf32.tf32.f32 "
        "{%0,%1,%2,%3}, {%4,%5,%6,%7}, {%8,%9}, {%0,%1,%2,%3};\n"
        : "+f"(c[0]), "+f"(c[1]), "+f"(c[2]), "+f"(c[3])
        : "r"(a[0]), "r"(a[1]), "r"(a[2]), "r"(a[3]), "r"(b[0]), "r"(b[1]));
}

// ---------------------------------------------------------------------------
// BIG GEMM: CTA 128x128, BK=16, 256 thr, warp grid 2x4, warp tile 64x32,
// 2-stage double buffer, XOR-swizzled A (and B if TRANSB) smem.
// Requires M%128==0, N%128==0, K%16==0.
// ---------------------------------------------------------------------------
template<bool TRANSB, int FLAGS>
__global__ __launch_bounds__(256, 2)
void tgemm_big(const float* __restrict__ A, int lda, long long sA1, long long sA2,
               const float* __restrict__ B, int ldb, long long sB1, long long sB2,
               float* __restrict__ C, int ldc, long long sC1, long long sC2,
               int K, int bdiv,
               const float* __restrict__ bias,
               const float* __restrict__ aux, int auxld,
               const unsigned char* __restrict__ adjp, long long sAdj)
{
    int bz = blockIdx.z;
    int bat1 = bz / bdiv, bat2 = bz - bat1 * bdiv;
    A += (long long)bat1 * sA1 + (long long)bat2 * sA2;
    B += (long long)bat1 * sB1 + (long long)bat2 * sB2;
    C += (long long)bat1 * sC1 + (long long)bat2 * sC2;
    if (FLAGS & F_SIG) adjp += (long long)bat1 * sAdj;

    int m0 = blockIdx.y * 128, n0 = blockIdx.x * 128;

    __shared__ float As[2][2048];   // [row][chunk swizzled], stride 16
    __shared__ float Bs[2][2176];   // !TRANSB: [k][n] stride 136; TRANSB: like A

    int tid = threadIdx.x;
    // A staging: rows ra, ra+64; chunk ca
    int ra = tid >> 2, ca = tid & 3;
    int swa = (ra >> 1) & 3;                 // same for ra+64
    const float* gA0 = A + (size_t)(m0 + ra) * lda + ca * 4;
    const float* gA1 = gA0 + (size_t)64 * lda;
    int offA0 = ra * 16 + ((ca ^ swa) << 2);
    int offA1 = (ra + 64) * 16 + ((ca ^ swa) << 2);

    // B staging
    const float* gB0;
    const float* gB1;
    int offB0, offB1;
    if (!TRANSB) {
        int kb = tid >> 4, nb = (tid & 15) * 4;
        gB0 = B + (size_t)kb * ldb + n0 + nb;
        gB1 = gB0 + 64;
        offB0 = kb * 136 + nb;
        offB1 = offB0 + 64;
    } else {
        gB0 = B + (size_t)(n0 + ra) * ldb + ca * 4;
        gB1 = gB0 + (size_t)64 * ldb;
        offB0 = offA0;
        offB1 = offA1;
    }

    int w = tid >> 5, l = tid & 31;
    int mbase = (w >> 2) * 64, nbase = (w & 3) * 32;
    int grp = l >> 2, tig = l & 3;

    float acc[4][4][4];
    #pragma unroll
    for (int i = 0; i < 4; i++)
        #pragma unroll
        for (int j = 0; j < 4; j++)
            #pragma unroll
            for (int q = 0; q < 4; q++) acc[i][j][q] = 0.f;

    float4 va0, va1, vb0, vb1;
    int nk = K >> 4;

    // load tile 0
    va0 = *(const float4*)(gA0);
    va1 = *(const float4*)(gA1);
    vb0 = *(const float4*)(gB0);
    vb1 = *(const float4*)(gB1);
    // store tile 0
    *(float4*)&As[0][offA0] = make_float4(to_tf32(va0.x), to_tf32(va0.y), to_tf32(va0.z), to_tf32(va0.w));
    *(float4*)&As[0][offA1] = make_float4(to_tf32(va1.x), to_tf32(va1.y), to_tf32(va1.z), to_tf32(va1.w));
    *(float4*)&Bs[0][offB0] = make_float4(to_tf32(vb0.x), to_tf32(vb0.y), to_tf32(vb0.z), to_tf32(vb0.w));
    *(float4*)&Bs[0][offB1] = make_float4(to_tf32(vb1.x), to_tf32(vb1.y), to_tf32(vb1.z), to_tf32(vb1.w));
    // load tile 1
    if (nk > 1) {
        va0 = *(const float4*)(gA0 + 16);
        va1 = *(const float4*)(gA1 + 16);
        if (!TRANSB) { vb0 = *(const float4*)(gB0 + (size_t)16 * ldb); vb1 = *(const float4*)(gB1 + (size_t)16 * ldb); }
        else         { vb0 = *(const float4*)(gB0 + 16); vb1 = *(const float4*)(gB1 + 16); }
    }

    int s = 0;
    for (int i = 0; i < nk; i++) {
        __syncthreads();
        if (i + 1 < nk) {
            int d = s ^ 1;
            *(float4*)&As[d][offA0] = make_float4(to_tf32(va0.x), to_tf32(va0.y), to_tf32(va0.z), to_tf32(va0.w));
            *(float4*)&As[d][offA1] = make_float4(to_tf32(va1.x), to_tf32(va1.y), to_tf32(va1.z), to_tf32(va1.w));
            *(float4*)&Bs[d][offB0] = make_float4(to_tf32(vb0.x), to_tf32(vb0.y), to_tf32(vb0.z), to_tf32(vb0.w));
            *(float4*)&Bs[d][offB1] = make_float4(to_tf32(vb1.x), to_tf32(vb1.y), to_tf32(vb1.z), to_tf32(vb1.w));
            if (i + 2 < nk) {
                int k0 = (i + 2) * 16;
                va0 = *(const float4*)(gA0 + k0);
                va1 = *(const float4*)(gA1 + k0);
                if (!TRANSB) { vb0 = *(const float4*)(gB0 + (size_t)k0 * ldb); vb1 = *(const float4*)(gB1 + (size_t)k0 * ldb); }
                else         { vb0 = *(const float4*)(gB0 + k0); vb1 = *(const float4*)(gB1 + k0); }
            }
        }
        const float* as = As[s];
        const float* bs = Bs[s];
        #pragma unroll
        for (int kk = 0; kk < 16; kk += 8) {
            int ck = kk >> 2;
            uint32_t af[4][4];
            #pragma unroll
            for (int fm = 0; fm < 4; fm++) {
                int r = mbase + fm * 16 + grp;
                int sw = (r >> 1) & 3;
                const float* ap = as + r * 16;
                af[fm][0] = __float_as_uint(ap[((ck ^ sw) << 2) + tig]);
                af[fm][2] = __float_as_uint(ap[(((ck + 1) ^ sw) << 2) + tig]);
                int r8 = r + 8;
                int sw8 = (r8 >> 1) & 3;
                const float* ap8 = as + r8 * 16;
                af[fm][1] = __float_as_uint(ap8[((ck ^ sw8) << 2) + tig]);
                af[fm][3] = __float_as_uint(ap8[(((ck + 1) ^ sw8) << 2) + tig]);
            }
            uint32_t bf[4][2];
            #pragma unroll
            for (int fn = 0; fn < 4; fn++) {
                int c = nbase + fn * 8 + grp;
                if (!TRANSB) {
                    bf[fn][0] = __float_as_uint(bs[(kk + tig) * 136 + c]);
                    bf[fn][1] = __float_as_uint(bs[(kk + tig + 4) * 136 + c]);
                } else {
                    int sw = (c >> 1) & 3;
                    const float* bp = bs + c * 16;
                    bf[fn][0] = __float_as_uint(bp[((ck ^ sw) << 2) + tig]);
                    bf[fn][1] = __float_as_uint(bp[(((ck + 1) ^ sw) << 2) + tig]);
                }
            }
            #pragma unroll
            for (int fm = 0; fm < 4; fm++)
                #pragma unroll
                for (int fn = 0; fn < 4; fn++)
                    mma_tf32(acc[fm][fn], af[fm], bf[fn]);
        }
        s ^= 1;
    }

    // epilogue
    #pragma unroll
    for (int fm = 0; fm < 4; fm++) {
        int row0 = m0 + mbase + fm * 16 + grp;
        #pragma unroll
        for (int fn = 0; fn < 4; fn++) {
            int col = n0 + nbase + fn * 8 + 2 * tig;
            float v0 = acc[fm][fn][0], v1 = acc[fm][fn][1];
            float v2 = acc[fm][fn][2], v3 = acc[fm][fn][3];
            if (FLAGS & F_BIAS) {
                float bb0 = bias[col], bb1 = bias[col + 1];
                v0 += bb0; v1 += bb1; v2 += bb0; v3 += bb1;
            }
            if (FLAGS & F_RELU) {
                v0 = fmaxf(v0, 0.f); v1 = fmaxf(v1, 0.f);
                v2 = fmaxf(v2, 0.f); v3 = fmaxf(v3, 0.f);
            }
            if (FLAGS & F_AUX) {
                const float* ar = aux + (size_t)row0 * auxld + col;
                const float* ar8 = aux + (size_t)(row0 + 8) * auxld + col;
                v0 += ar[0]; v1 += ar[1]; v2 += ar8[0]; v3 += ar8[1];
            }
            if (FLAGS & F_SIG) {
                const unsigned char* q0p = adjp + (size_t)row0 * ldc + col;
                const unsigned char* q8p = adjp + (size_t)(row0 + 8) * ldc + col;
                v0 = q0p[0] ? 1.f / (1.f + __expf(-v0 * 0.0625f)) : 0.f;
                v1 = q0p[1] ? 1.f / (1.f + __expf(-v1 * 0.0625f)) : 0.f;
                v2 = q8p[0] ? 1.f / (1.f + __expf(-v2 * 0.0625f)) : 0.f;
                v3 = q8p[1] ? 1.f / (1.f + __expf(-v3 * 0.0625f)) : 0.f;
                if (FLAGS & F_DIAG) {
                    if (row0 == col) v0 = 0.f;
                    if (row0 == col + 1) v1 = 0.f;
                    if (row0 + 8 == col) v2 = 0.f;
                    if (row0 + 8 == col + 1) v3 = 0.f;
                }
            }
            *(float2*)&C[(size_t)row0 * ldc + col] = make_float2(v0, v1);
            *(float2*)&C[(size_t)(row0 + 8) * ldc + col] = make_float2(v2, v3);
        }
    }
}

// ---------------------------------------------------------------------------
// AGG GEMM (N tile 64): x = 0.5*elu(alpha@h) + 0.5*aux, batched per (b,head).
// CTA 128x64, warp tile 32x32 (known-good R1 mapping).
// ---------------------------------------------------------------------------
__global__ __launch_bounds__(256)
void sgemm_agg(const float* __restrict__ A, int lda, long long sA1, long long sA2,
               const float* __restrict__ B, int ldb, long long sB1, long long sB2,
               float* __restrict__ C, int ldc, long long sC1, long long sC2,
               int K, int bdiv, const float* __restrict__ aux)
{
    int bz = blockIdx.z;
    int bat1 = bz / bdiv, bat2 = bz - bat1 * bdiv;
    A += (long long)bat1 * sA1 + (long long)bat2 * sA2;
    B += (long long)bat1 * sB1 + (long long)bat2 * sB2;
    C += (long long)bat1 * sC1 + (long long)bat2 * sC2;
    aux += (long long)bat1 * sC1 + (long long)bat2 * sC2;

    int m0 = blockIdx.y * 128, n0 = blockIdx.x * 64;
    __shared__ float As[128 * 20];
    __shared__ float Bs[16 * 72];
    int tid = threadIdx.x;

    const float* aptr0 = A + (size_t)(m0 + (tid >> 2)) * lda + (tid & 3) * 4;
    const float* aptr1 = aptr0 + (size_t)64 * lda;
    const float* bptr = B + (size_t)(tid >> 4) * ldb + n0 + (tid & 15) * 4;

    float* as0 = &As[(tid >> 2) * 20 + (tid & 3) * 4];
    float* as1 = &As[((tid >> 2) + 64) * 20 + (tid & 3) * 4];
    float* bs = &Bs[(tid >> 4) * 72 + (tid & 15) * 4];

    int w = tid >> 5, l = tid & 31;
    int wm = w >> 1, wn = w & 1;
    int mrow = wm * 32, ncol = wn * 32;
    int grp = l >> 2, tig = l & 3;

    float acc[2][4][4];
    #pragma unroll
    for (int i = 0; i < 2; i++)
        #pragma unroll
        for (int j = 0; j < 4; j++)
            #pragma unroll
            for (int q = 0; q < 4; q++) acc[i][j][q] = 0.f;

    float4 ra0 = *(const float4*)(aptr0);
    float4 ra1 = *(const float4*)(aptr1);
    float4 rb = *(const float4*)(bptr);

    for (int k0 = 0; k0 < K; k0 += 16) {
        as0[0] = to_tf32(ra0.x); as0[1] = to_tf32(ra0.y); as0[2] = to_tf32(ra0.z); as0[3] = to_tf32(ra0.w);
        as1[0] = to_tf32(ra1.x); as1[1] = to_tf32(ra1.y); as1[2] = to_tf32(ra1.z); as1[3] = to_tf32(ra1.w);
        bs[0] = to_tf32(rb.x); bs[1] = to_tf32(rb.y); bs[2] = to_tf32(rb.z); bs[3] = to_tf32(rb.w);
        __syncthreads();
        if (k0 + 16 < K) {
            ra0 = *(const float4*)(aptr0 + k0 + 16);
            ra1 = *(const float4*)(aptr1 + k0 + 16);
            rb = *(const float4*)(bptr + (size_t)(k0 + 16) * ldb);
        }
        #pragma unroll
        for (int kk = 0; kk < 16; kk += 8) {
            uint32_t af[2][4];
            #pragma unroll
            for (int fm = 0; fm < 2; fm++) {
                int r = (mrow + fm * 16 + grp) * 20;
                af[fm][0] = __float_as_uint(As[r + kk + tig]);
                af[fm][1] = __float_as_uint(As[r + 160 + kk + tig]);
                af[fm][2] = __float_as_uint(As[r + kk + tig + 4]);
                af[fm][3] = __float_as_uint(As[r + 160 + kk + tig + 4]);
            }
            uint32_t bf[4][2];
            #pragma unroll
            for (int fn = 0; fn < 4; fn++) {
                int c = ncol + fn * 8 + grp;
                bf[fn][0] = __float_as_uint(Bs[(kk + tig) * 72 + c]);
                bf[fn][1] = __float_as_uint(Bs[(kk + tig + 4) * 72 + c]);
            }
            #pragma unroll
            for (int fm = 0; fm < 2; fm++)
                #pragma unroll
                for (int fn = 0; fn < 4; fn++)
                    mma_tf32(acc[fm][fn], af[fm], bf[fn]);
        }
        __syncthreads();
    }

    #pragma unroll
    for (int fm = 0; fm < 2; fm++) {
        int row = m0 + mrow + fm * 16 + grp;
        #pragma unroll
        for (int fn = 0; fn < 4; fn++) {
            int col = n0 + ncol + fn * 8 + 2 * tig;
            float v0 = acc[fm][fn][0], v1 = acc[fm][fn][1];
            float v2 = acc[fm][fn][2], v3 = acc[fm][fn][3];
            v0 = (v0 > 0.f) ? v0 : expm1f(v0);
            v1 = (v1 > 0.f) ? v1 : expm1f(v1);
            v2 = (v2 > 0.f) ? v2 : expm1f(v2);
            v3 = (v3 > 0.f) ? v3 : expm1f(v3);
            float2 x0 = *(const float2*)&aux[(size_t)row * ldc + col];
            float2 x1 = *(const float2*)&aux[(size_t)(row + 8) * ldc + col];
            *(float2*)&C[(size_t)row * ldc + col] =
                make_float2(0.5f * v0 + 0.5f * x0.x, 0.5f * v1 + 0.5f * x0.y);
            *(float2*)&C[(size_t)(row + 8) * ldc + col] =
                make_float2(0.5f * v2 + 0.5f * x1.x, 0.5f * v3 + 0.5f * x1.y);
        }
    }
}

// ---------------------------------------------------------------------------
// Small kernels
// ---------------------------------------------------------------------------
__global__ void k_feat1(const float* __restrict__ x, const float* __restrict__ W1,
                        const float* __restrict__ b1, float* __restrict__ out)
{
    size_t idx = (size_t)blockIdx.x * 256 + threadIdx.x;
    size_t row = idx >> 8;
    int d = idx & 255;
    const float* xr = x + row * 4;
    float v = b1[d] + xr[0]*W1[d] + xr[1]*W1[256+d] + xr[2]*W1[512+d] + xr[3]*W1[768+d];
    out[idx] = (v > 0.f) ? v : expm1f(v);
}

__global__ void k_ln(const float* __restrict__ in, float* __restrict__ out)
{
    size_t row = blockIdx.x;
    int t = threadIdx.x;
    float v = in[row * 256 + t];
    float a = v, b = v * v;
    #pragma unroll
    for (int o = 16; o; o >>= 1) {
        a += __shfl_xor_sync(0xffffffff, a, o);
        b += __shfl_xor_sync(0xffffffff, b, o);
    }
    __shared__ float sa[8], sb[8];
    if ((t & 31) == 0) { sa[t >> 5] = a; sb[t >> 5] = b; }
    __syncthreads();
    if (t < 32) {
        a = (t < 8) ? sa[t] : 0.f;
        b = (t < 8) ? sb[t] : 0.f;
        #pragma unroll
        for (int o = 4; o; o >>= 1) {
            a += __shfl_xor_sync(0xffffffff, a, o);
            b += __shfl_xor_sync(0xffffffff, b, o);
        }
        if (t == 0) { sa[0] = a; sb[0] = b; }
    }
    __syncthreads();
    float mean = sa[0] * (1.f / 256.f);
    float var = sb[0] * (1.f / 256.f) - mean * mean;
    out[row * 256 + t] = (v - mean) * rsqrtf(var + 1e-5f);
}

__global__ void k_attn(const float* __restrict__ q0, const float* __restrict__ kv,
                       float* __restrict__ o0)
{
    size_t t = blockIdx.x;
    int d = threadIdx.x;
    int h = d >> 6;
    __shared__ float logits[4][8];
    __shared__ float red[8];
    float qd = q0[t * 256 + d];
    for (int s = 0; s < 8; s++) {
        float p = qd * kv[(t * 8 + s) * 512 + d];
        #pragma unroll
        for (int o = 16; o; o >>= 1) p += __shfl_xor_sync(0xffffffff, p, o);
        if ((d & 31) == 0) red[d >> 5] = p;
        __syncthreads();
        if (d < 4) logits[d][s] = (red[2 * d] + red[2 * d + 1]) * 0.125f;
        __syncthreads();
    }
    float m = -1e30f;
    #pragma unroll
    for (int s = 0; s < 8; s++) m = fmaxf(m, logits[h][s]);
    float w[8], sum = 0.f;
    #pragma unroll
    for (int s = 0; s < 8; s++) { w[s] = __expf(logits[h][s] - m); sum += w[s]; }
    float inv = 1.f / sum;
    float o = 0.f;
    #pragma unroll
    for (int s = 0; s < 8; s++) o += w[s] * inv * kv[(t * 8 + s) * 512 + 256 + d];
    o0[t * 256 + d] = o;
}

__global__ void k_feat0(const float* __restrict__ tr_emb, const float* __restrict__ x1,
                        const float* __restrict__ ffout, const float* __restrict__ det_emb,
                        float* __restrict__ feat0, float* __restrict__ x)
{
    size_t idx = (size_t)blockIdx.x * 256 + threadIdx.x;
    int d = idx & 255;
    size_t row = idx >> 8;
    int i = row & 1023;
    int b = row >> 10;
    float v;
    if (i < 512) {
        size_t t = (size_t)b * 512 + i;
        v = tr_emb[t * 2048 + d] + 0.9f * (x1[t * 256 + d] + ffout[t * 256 + d]);
    } else {
        size_t t = (size_t)b * 512 + (i - 512);
        v = det_emb[t * 256 + d];
    }
    feat0[idx] = v;
    x[idx] = v;
}

__global__ void k_posvm(const float* __restrict__ tracks, const float* __restrict__ dets,
                        const int* __restrict__ tmarks, const int* __restrict__ dmarks,
                        float* __restrict__ pos, unsigned char* __restrict__ vm)
{
    int idx = blockIdx.x * 256 + threadIdx.x;
    if (idx >= BB * NN1) return;
    int b = idx >> 10, i = idx & 1023;
    float x, y; unsigned char v;
    if (i < 512) {
        const float* p = tracks + ((size_t)(b * 512 + i)) * 8 * 4;
        x = p[0]; y = p[1];
        v = (i < tmarks[b]);
    } else {
        int n = i - 512;
        const float* p = dets + ((size_t)(b * 512 + n)) * 4;
        x = p[0]; y = p[1];
        v = (n < dmarks[b]);
    }
    pos[idx * 2] = x; pos[idx * 2 + 1] = y; vm[idx] = v;
}

// adjacency: grid (NN1, BB), 256 threads, each writes one uchar4
__global__ void k_adj(const float* __restrict__ pos, const unsigned char* __restrict__ vm,
                      unsigned char* __restrict__ adj)
{
    int i = blockIdx.x, b = blockIdx.y;
    size_t base = (size_t)b * NN1;
    const float2* p2 = (const float2*)pos;
    float2 pi = p2[base + i];
    unsigned char vi = vm[base + i];
    int j0 = threadIdx.x * 4;
    uchar4 r;
    unsigned char* rp = &r.x;
    #pragma unroll
    for (int u = 0; u < 4; u++) {
        int j = j0 + u;
        float2 pj = p2[base + j];
        float dx = pi.x - pj.x, dy = pi.y - pj.y;
        rp[u] = (unsigned char)((dx * dx + dy * dy < 4.0f) && vi && vm[base + j]);
    }
    ((uchar4*)(adj + ((size_t)b * NN1 + i) * NN1))[threadIdx.x] = r;
}

// det adjacency: grid (NNd, BB), 128 threads
__global__ void k_adjd(const float* __restrict__ pos, const unsigned char* __restrict__ vm,
                       unsigned char* __restrict__ adjd)
{
    int i = blockIdx.x, b = blockIdx.y;
    size_t base = (size_t)b * NN1 + 512;
    const float2* p2 = (const float2*)pos;
    float2 pi = p2[base + i];
    unsigned char vi = vm[base + i];
    int j0 = threadIdx.x * 4;
    uchar4 r;
    unsigned char* rp = &r.x;
    #pragma unroll
    for (int u = 0; u < 4; u++) {
        int j = j0 + u;
        float2 pj = p2[base + j];
        float dx = pi.x - pj.x, dy = pi.y - pj.y;
        rp[u] = (unsigned char)((dx * dx + dy * dy < 4.0f) && vi && vm[base + j]);
    }
    ((uchar4*)(adjd + ((size_t)b * NNd + i) * NNd))[threadIdx.x] = r;
}

__global__ void k_srcdst(const float* __restrict__ Hm, const float* __restrict__ a0,
                         float* __restrict__ src, float* __restrict__ dst)
{
    size_t row = blockIdx.x;
    int d = threadIdx.x;
    float hv = Hm[row * 256 + d];
    float s = hv * a0[d];
    float t2 = hv * a0[256 + d];
    #pragma unroll
    for (int o = 16; o; o >>= 1) {
        s  += __shfl_xor_sync(0xffffffff, s, o);
        t2 += __shfl_xor_sync(0xffffffff, t2, o);
    }
    __shared__ float ps[8], pt[8];
    if ((d & 31) == 0) { ps[d >> 5] = s; pt[d >> 5] = t2; }
    __syncthreads();
    if (d < 4) {
        src[row * 4 + d] = ps[2 * d] + ps[2 * d + 1];
        dst[row * 4 + d] = pt[2 * d] + pt[2 * d + 1];
    }
}

// GAT edge softmax: alpha[b,h,i,:]; grid (NN, BB), 128 threads.
// e smem is [h][j] so softmax passes are float4-vectorized.
__global__ void k_alpha(const float* __restrict__ src, const float* __restrict__ dst,
                        const unsigned char* __restrict__ adj, float* __restrict__ alpha,
                        int NN)
{
    int i = blockIdx.x, b = blockIdx.y;
    __shared__ float e[4 * 1024];
    const float* srci = src + ((size_t)b * NN + i) * 4;
    float s0 = srci[0], s1 = srci[1], s2 = srci[2], s3 = srci[3];
    const unsigned char* adjrow = adj + ((size_t)b * NN + i) * NN;
    const float4* dst4 = (const float4*)(dst + (size_t)b * NN * 4);
    int nq = NN >> 2;
    for (int jq = threadIdx.x; jq < nq; jq += 128) {
        uchar4 a4 = ((const uchar4*)adjrow)[jq];
        const unsigned char* ap = &a4.x;
        #pragma unroll
        for (int u = 0; u < 4; u++) {
            int j = jq * 4 + u;
            float4 d = dst4[j];
            float v0 = s0 + d.x; v0 = v0 > 0.f ? v0 : 0.2f * v0;
            float v1 = s1 + d.y; v1 = v1 > 0.f ? v1 : 0.2f * v1;
            float v2 = s2 + d.z; v2 = v2 > 0.f ? v2 : 0.2f * v2;
            float v3 = s3 + d.w; v3 = v3 > 0.f ? v3 : 0.2f * v3;
            bool m = ap[u] != 0;
            e[j]          = m ? v0 : -1e9f;
            e[NN + j]     = m ? v1 : -1e9f;
            e[2 * NN + j] = m ? v2 : -1e9f;
            e[3 * NN + j] = m ? v3 : -1e9f;
        }
    }
    __syncthreads();
    int h = threadIdx.x >> 5, lane = threadIdx.x & 31;
    float4* eh = (float4*)(e + h * NN);
    float mx = -1e30f;
    for (int jq = lane; jq < nq; jq += 32) {
        float4 v = eh[jq];
        mx = fmaxf(mx, fmaxf(fmaxf(v.x, v.y), fmaxf(v.z, v.w)));
    }
    #pragma unroll
    for (int o = 16; o; o >>= 1) mx = fmaxf(mx, __shfl_xor_sync(0xffffffff, mx, o));
    float sum = 0.f;
    for (int jq = lane; jq < nq; jq += 32) {
        float4 v = eh[jq];
        v.x = __expf(v.x - mx); v.y = __expf(v.y - mx);
        v.z = __expf(v.z - mx); v.w = __expf(v.w - mx);
        eh[jq] = v;
        sum += v.x + v.y + v.z + v.w;
    }
    #pragma unroll
    for (int o = 16; o; o >>= 1) sum += __shfl_xor_sync(0xffffffff, sum, o);
    float inv = 1.f / sum;
    float4* arow = (float4*)(alpha + (((size_t)b * 4 + h) * NN + i) * (size_t)NN);
    for (int jq = lane; jq < nq; jq += 32) {
        float4 v = eh[jq];
        v.x *= inv; v.y *= inv; v.z *= inv; v.w *= inv;
        arow[jq] = v;
    }
}

__global__ void k_asso(const float* __restrict__ scores, float* __restrict__ out)
{
    size_t idx = (size_t)blockIdx.x * 256 + threadIdx.x;
    int j = idx & 511;
    size_t r = idx >> 9;
    int m = r & 511;
    int b = (int)(r >> 9);
    out[idx] = scores[(((size_t)b * 1024 + m) * 1024) + 512 + j];
}

// ---------------------------------------------------------------------------
// Host side
// ---------------------------------------------------------------------------
static void run_big(const float* A, int lda, long long sA1, long long sA2,
                    const float* B, int ldb, long long sB1, long long sB2,
                    float* C, int ldc, long long sC1, long long sC2,
                    int M, int N, int K, int batch, int bdiv,
                    const float* bias, const float* aux, int auxld,
                    const unsigned char* adjp, long long sAdj,
                    int flags, bool transb)
{
    dim3 g(N / 128, M / 128, batch);
#define CALLBIG(T, F) tgemm_big<T, F><<<g, 256>>>(A, lda, sA1, sA2, B, ldb, sB1, sB2, \
        C, ldc, sC1, sC2, K, bdiv, bias, aux, auxld, adjp, sAdj)
    if (!transb) {
        if (flags == 0)           CALLBIG(false, 0);
        else if (flags == F_BIAS) CALLBIG(false, F_BIAS);
        else if (flags == F_RELU) CALLBIG(false, F_RELU);
        else                      CALLBIG(false, F_AUX);
    } else {
        if (flags == F_SIG)       CALLBIG(true, F_SIG);
        else                      CALLBIG(true, F_SIG | F_DIAG);
    }
#undef CALLBIG
}

#define SYM(p, s) cudaGetSymbolAddress((void**)&p, s)

extern "C" void kernel_launch(void* const* d_in, const int* in_sizes, int n_in,
                              void* d_out, int out_size)
{
    (void)in_sizes; (void)n_in; (void)out_size;
    const float* tracks = (const float*)d_in[0];
    const float* dets   = (const float*)d_in[1];
    const int* tmarks   = (const int*)d_in[2];
    const int* dmarks   = (const int*)d_in[3];
    const float* W1     = (const float*)d_in[4];
    const float* b1     = (const float*)d_in[5];
    const float* W2     = (const float*)d_in[6];
    const float* b2     = (const float*)d_in[7];
    const float* Wqkv   = (const float*)d_in[8];
    const float* Wo     = (const float*)d_in[9];
    const float* ff1    = (const float*)d_in[10];
    const float* ff2    = (const float*)d_in[11];
    const float* gatW   = (const float*)d_in[12];
    const float* gata   = (const float*)d_in[13];
    const float* dgatW  = (const float*)d_in[14];
    const float* dgata  = (const float*)d_in[15];
    const float* clsWq  = (const float*)d_in[16];
    const float* clsWk  = (const float*)d_in[17];

    float* out = (float*)d_out;
    float* out_scores = out;
    float* out_det    = out + (size_t)BB * NN1 * NN1;
    float* out_asso   = out_det + (size_t)BB * NNd * NNd;

    float *tr_h1, *tr_emb, *ln, *kv, *det_h1, *det_emb, *q0, *o0, *x1,
          *ln2, *ffh, *ffout, *feat0, *x, *h, *src, *dst, *alpha,
          *pos, *xq, *xk;
    unsigned char *adj, *adjd, *vm;
    SYM(tr_h1, g_tr_h1);   SYM(tr_emb, g_tr_emb); SYM(ln, g_ln);
    SYM(kv, g_kv);         SYM(det_h1, g_det_h1); SYM(det_emb, g_det_emb);
    SYM(q0, g_q0);         SYM(o0, g_o0);
    SYM(x1, g_x1);         SYM(ln2, g_ln2);       SYM(ffh, g_ffh);
    SYM(ffout, g_ffout);   SYM(feat0, g_feat0);   SYM(x, g_x);
    SYM(h, g_h);           SYM(src, g_src);
    SYM(dst, g_dst);       SYM(alpha, g_alpha);   SYM(adj, g_adj);
    SYM(adjd, g_adjd);     SYM(pos, g_pos);       SYM(vm, g_vm);
    SYM(xq, g_xq);         SYM(xk, g_xk);

    // ---- feature MLP ----
    k_feat1<<<TM, 256>>>(tracks, W1, b1, tr_h1);
    run_big(tr_h1, 256, 0, 0, W2, 256, 0, 0, tr_emb, 256, 0, 0,
            TM, 256, 256, 1, 1, b2, nullptr, 0, nullptr, 0, F_BIAS, false);
    k_feat1<<<ND, 256>>>(dets, W1, b1, det_h1);
    run_big(det_h1, 256, 0, 0, W2, 256, 0, 0, det_emb, 256, 0, 0,
            ND, 256, 256, 1, 1, b2, nullptr, 0, nullptr, 0, F_BIAS, false);

    // ---- encoder (only r=0 outputs needed downstream) ----
    k_ln<<<TM, 256>>>(tr_emb, ln);
    run_big(ln, 256, 0, 0, Wqkv + 256, 768, 0, 0, kv, 512, 0, 0,
            TM, 512, 256, 1, 1, nullptr, nullptr, 0, nullptr, 0, 0, false);
    run_big(ln, 2048, 0, 0, Wqkv, 768, 0, 0, q0, 256, 0, 0,
            TT, 256, 256, 1, 1, nullptr, nullptr, 0, nullptr, 0, 0, false);
    k_attn<<<TT, 256>>>(q0, kv, o0);
    // x1 = tr_emb(r0) + o0 @ Wo   (AUX add fused)
    run_big(o0, 256, 0, 0, Wo, 256, 0, 0, x1, 256, 0, 0,
            TT, 256, 256, 1, 1, nullptr, tr_emb, 2048, nullptr, 0, F_AUX, false);
    k_ln<<<TT, 256>>>(x1, ln2);
    run_big(ln2, 256, 0, 0, ff1, 1024, 0, 0, ffh, 1024, 0, 0,
            TT, 1024, 256, 1, 1, nullptr, nullptr, 0, nullptr, 0, F_RELU, false);
    run_big(ffh, 1024, 0, 0, ff2, 256, 0, 0, ffout, 256, 0, 0,
            TT, 256, 1024, 1, 1, nullptr, nullptr, 0, nullptr, 0, 0, false);
    k_feat0<<<ROWS1, 256>>>(tr_emb, x1, ffout, det_emb, feat0, x);

    // ---- adjacency ----
    k_posvm<<<64, 256>>>(tracks, dets, tmarks, dmarks, pos, vm);
    k_adj<<<dim3(NN1, BB), 256>>>(pos, vm, adj);
    k_adjd<<<dim3(NNd, BB), 128>>>(pos, vm, adjd);

    // ---- main GAT x2 ----
    for (int l = 0; l < 2; l++) {
        run_big(x, 256, 0, 0, gatW + (size_t)l * 256 * 256, 256, 0, 0,
                h, 256, 0, 0, ROWS1, 256, 256, 1, 1,
                nullptr, nullptr, 0, nullptr, 0, 0, false);
        k_srcdst<<<ROWS1, 256>>>(h, gata + (size_t)l * 512, src, dst);
        k_alpha<<<dim3(NN1, BB), 128>>>(src, dst, adj, alpha, NN1);
        // x = 0.5*elu(alpha@h) + 0.5*feat0 (fused)
        sgemm_agg<<<dim3(1, NN1 / 128, BB * HH), 256>>>(
            alpha, NN1, 4LL * NN1 * NN1, (long long)NN1 * NN1,
            h, 256, (long long)NN1 * 256, 64,
            x, 256, (long long)NN1 * 256, 64,
            NN1, HH, feat0);
    }

    // ---- main scores ----
    run_big(x, 256, 0, 0, clsWq, 256, 0, 0, xq, 256, 0, 0,
            ROWS1, 256, 256, 1, 1, nullptr, nullptr, 0, nullptr, 0, 0, false);
    run_big(x, 256, 0, 0, clsWk, 256, 0, 0, xk, 256, 0, 0,
            ROWS1, 256, 256, 1, 1, nullptr, nullptr, 0, nullptr, 0, 0, false);
    run_big(xq, 256, (long long)NN1 * 256, 0,
            xk, 256, (long long)NN1 * 256, 0,
            out_scores, NN1, (long long)NN1 * NN1, 0,
            NN1, NN1, 256, BB, 1,
            nullptr, nullptr, 0, adj, (long long)NN1 * NN1, F_SIG, true);
    k_asso<<<(int)(((size_t)BB * 512 * 512) / 256), 256>>>(out_scores, out_asso);

    // ---- detection GAT x2 ----
    for (int l = 0; l < 2; l++) {
        const float* xin = (l == 0) ? det_emb : x;
        run_big(xin, 256, 0, 0, dgatW + (size_t)l * 256 * 256, 256, 0, 0,
                h, 256, 0, 0, ND, 256, 256, 1, 1,
                nullptr, nullptr, 0, nullptr, 0, 0, false);
        k_srcdst<<<ND, 256>>>(h, dgata + (size_t)l * 512, src, dst);
        k_alpha<<<dim3(NNd, BB), 128>>>(src, dst, adjd, alpha, NNd);
        sgemm_agg<<<dim3(1, NNd / 128, BB * HH), 256>>>(
            alpha, NNd, 4LL * NNd * NNd, (long long)NNd * NNd,
            h, 256, (long long)NNd * 256, 64,
            x, 256, (long long)NNd * 256, 64,
            NNd, HH, det_emb);
    }

    // ---- detection scores ----
    run_big(x, 256, 0, 0, clsWq + 256 * 256, 256, 0, 0, xq, 256, 0, 0,
            ND, 256, 256, 1, 1, nullptr, nullptr, 0, nullptr, 0, 0, false);
    run_big(x, 256, 0, 0, clsWk + 256 * 256, 256, 0, 0, xk, 256, 0, 0,
            ND, 256, 256, 1, 1, nullptr, nullptr, 0, nullptr, 0, 0, false);
    run_big(xq, 256, (long long)NNd * 256, 0,
            xk, 256, (long long)NNd * 256, 0,
            out_det, NNd, (long long)NNd * NNd, 0,
            NNd, NNd, 256, BB, 1,
            nullptr, nullptr, 0, adjd, (long long)NNd * NNd, F_SIG | F_DIAG, true);
}

// round 5
// speedup vs baseline: 2.8347x; 1.0345x over previous
#include <cuda_runtime.h>
#include <math.h>
#include <stdint.h>

// ---------------------------------------------------------------------------
// Problem dims (compile-time)
// ---------------------------------------------------------------------------
#define BB 16
#define MM 512
#define NNd 512
#define RR 8
#define DD 256
#define HH 4
#define NN1 1024          // M + N
#define TM  (BB*MM*RR)    // 65536 track-feature rows
#define TT  (BB*MM)       // 8192 tokens
#define ND  (BB*NNd)      // 8192 detection rows
#define ROWS1 (BB*NN1)    // 16384 graph rows

// epilogue flags
#define F_BIAS 1
#define F_RELU 2
#define F_AUX  4
#define F_SIG  8
#define F_DIAG 16

// ---------------------------------------------------------------------------
// Scratch (device globals — no allocation allowed)
// ---------------------------------------------------------------------------
__device__ float g_tr_h1[TM*DD];
__device__ float g_tr_emb[TM*DD];
__device__ float g_ln[TM*DD];
__device__ float g_kv[TM*512];
__device__ float g_det_h1[ND*DD];
__device__ float g_det_emb[ND*DD];
__device__ float g_q0[TT*DD];
__device__ float g_o0[TT*DD];
__device__ float g_x1[TT*DD];
__device__ float g_ln2[TT*DD];
__device__ float g_ffh[TT*1024];
__device__ float g_ffout[TT*DD];
__device__ float g_feat0[ROWS1*DD];
__device__ float g_x[ROWS1*DD];
__device__ float g_h[ROWS1*DD];
__device__ float g_src[ROWS1*HH];
__device__ float g_dstT[BB*HH*NN1];      // [b][h][i]
__device__ float2 g_stat[BB*HH*NN1];     // (rowmax, invsum)
__device__ unsigned char g_adj[(size_t)BB*NN1*NN1];
__device__ unsigned char g_adjd[(size_t)BB*NNd*NNd];
__device__ float g_pos[BB*NN1*2];
__device__ unsigned char g_vm[BB*NN1];
__device__ float g_xq[ROWS1*DD];
__device__ float g_xk[ROWS1*DD];

// ---------------------------------------------------------------------------
// MMA helpers
// ---------------------------------------------------------------------------
__device__ __forceinline__ float to_tf32(float x) {
    float r;
    asm("cvt.rna.tf32.f32 %0, %1;" : "=f"(r) : "f"(x));
    return r;
}

__device__ __forceinline__ void mma_tf32(float* c, const uint32_t* a, const uint32_t* b) {
    asm volatile(
        "mma.sync.aligned.m16n8k8.row.col.f32.tf32.tf32.f32 "
        "{%0,%1,%2,%3}, {%4,%5,%6,%7}, {%8,%9}, {%0,%1,%2,%3};\n"
        : "+f"(c[0]), "+f"(c[1]), "+f"(c[2]), "+f"(c[3])
        : "r"(a[0]), "r"(a[1]), "r"(a[2]), "r"(a[3]), "r"(b[0]), "r"(b[1]));
}

// ---------------------------------------------------------------------------
// BIG GEMM: CTA 128x128, BK=16, 256 thr, warp grid 2x4, warp tile 64x32,
// 2-stage double buffer, XOR-swizzled A (and B if TRANSB) smem.
// ---------------------------------------------------------------------------
template<bool TRANSB, int FLAGS>
__global__ __launch_bounds__(256, 2)
void tgemm_big(const float* __restrict__ A, int lda, long long sA1, long long sA2,
               const float* __restrict__ B, int ldb, long long sB1, long long sB2,
               float* __restrict__ C, int ldc, long long sC1, long long sC2,
               int K, int bdiv,
               const float* __restrict__ bias,
               const float* __restrict__ aux, int auxld,
               const unsigned char* __restrict__ adjp, long long sAdj)
{
    int bz = blockIdx.z;
    int bat1 = bz / bdiv, bat2 = bz - bat1 * bdiv;
    A += (long long)bat1 * sA1 + (long long)bat2 * sA2;
    B += (long long)bat1 * sB1 + (long long)bat2 * sB2;
    C += (long long)bat1 * sC1 + (long long)bat2 * sC2;
    if (FLAGS & F_SIG) adjp += (long long)bat1 * sAdj;

    int m0 = blockIdx.y * 128, n0 = blockIdx.x * 128;

    __shared__ float As[2][2048];
    __shared__ float Bs[2][2176];

    int tid = threadIdx.x;
    int ra = tid >> 2, ca = tid & 3;
    int swa = (ra >> 1) & 3;
    const float* gA0 = A + (size_t)(m0 + ra) * lda + ca * 4;
    const float* gA1 = gA0 + (size_t)64 * lda;
    int offA0 = ra * 16 + ((ca ^ swa) << 2);
    int offA1 = (ra + 64) * 16 + ((ca ^ swa) << 2);

    const float* gB0;
    const float* gB1;
    int offB0, offB1;
    if (!TRANSB) {
        int kb = tid >> 4, nb = (tid & 15) * 4;
        gB0 = B + (size_t)kb * ldb + n0 + nb;
        gB1 = gB0 + 64;
        offB0 = kb * 136 + nb;
        offB1 = offB0 + 64;
    } else {
        gB0 = B + (size_t)(n0 + ra) * ldb + ca * 4;
        gB1 = gB0 + (size_t)64 * ldb;
        offB0 = offA0;
        offB1 = offA1;
    }

    int w = tid >> 5, l = tid & 31;
    int mbase = (w >> 2) * 64, nbase = (w & 3) * 32;
    int grp = l >> 2, tig = l & 3;

    float acc[4][4][4];
    #pragma unroll
    for (int i = 0; i < 4; i++)
        #pragma unroll
        for (int j = 0; j < 4; j++)
            #pragma unroll
            for (int q = 0; q < 4; q++) acc[i][j][q] = 0.f;

    float4 va0, va1, vb0, vb1;
    int nk = K >> 4;

    va0 = *(const float4*)(gA0);
    va1 = *(const float4*)(gA1);
    vb0 = *(const float4*)(gB0);
    vb1 = *(const float4*)(gB1);
    *(float4*)&As[0][offA0] = make_float4(to_tf32(va0.x), to_tf32(va0.y), to_tf32(va0.z), to_tf32(va0.w));
    *(float4*)&As[0][offA1] = make_float4(to_tf32(va1.x), to_tf32(va1.y), to_tf32(va1.z), to_tf32(va1.w));
    *(float4*)&Bs[0][offB0] = make_float4(to_tf32(vb0.x), to_tf32(vb0.y), to_tf32(vb0.z), to_tf32(vb0.w));
    *(float4*)&Bs[0][offB1] = make_float4(to_tf32(vb1.x), to_tf32(vb1.y), to_tf32(vb1.z), to_tf32(vb1.w));
    if (nk > 1) {
        va0 = *(const float4*)(gA0 + 16);
        va1 = *(const float4*)(gA1 + 16);
        if (!TRANSB) { vb0 = *(const float4*)(gB0 + (size_t)16 * ldb); vb1 = *(const float4*)(gB1 + (size_t)16 * ldb); }
        else         { vb0 = *(const float4*)(gB0 + 16); vb1 = *(const float4*)(gB1 + 16); }
    }

    int s = 0;
    for (int i = 0; i < nk; i++) {
        __syncthreads();
        if (i + 1 < nk) {
            int d = s ^ 1;
            *(float4*)&As[d][offA0] = make_float4(to_tf32(va0.x), to_tf32(va0.y), to_tf32(va0.z), to_tf32(va0.w));
            *(float4*)&As[d][offA1] = make_float4(to_tf32(va1.x), to_tf32(va1.y), to_tf32(va1.z), to_tf32(va1.w));
            *(float4*)&Bs[d][offB0] = make_float4(to_tf32(vb0.x), to_tf32(vb0.y), to_tf32(vb0.z), to_tf32(vb0.w));
            *(float4*)&Bs[d][offB1] = make_float4(to_tf32(vb1.x), to_tf32(vb1.y), to_tf32(vb1.z), to_tf32(vb1.w));
            if (i + 2 < nk) {
                int k0 = (i + 2) * 16;
                va0 = *(const float4*)(gA0 + k0);
                va1 = *(const float4*)(gA1 + k0);
                if (!TRANSB) { vb0 = *(const float4*)(gB0 + (size_t)k0 * ldb); vb1 = *(const float4*)(gB1 + (size_t)k0 * ldb); }
                else         { vb0 = *(const float4*)(gB0 + k0); vb1 = *(const float4*)(gB1 + k0); }
            }
        }
        const float* as = As[s];
        const float* bs = Bs[s];
        #pragma unroll
        for (int kk = 0; kk < 16; kk += 8) {
            int ck = kk >> 2;
            uint32_t af[4][4];
            #pragma unroll
            for (int fm = 0; fm < 4; fm++) {
                int r = mbase + fm * 16 + grp;
                int sw = (r >> 1) & 3;
                const float* ap = as + r * 16;
                af[fm][0] = __float_as_uint(ap[((ck ^ sw) << 2) + tig]);
                af[fm][2] = __float_as_uint(ap[(((ck + 1) ^ sw) << 2) + tig]);
                int r8 = r + 8;
                int sw8 = (r8 >> 1) & 3;
                const float* ap8 = as + r8 * 16;
                af[fm][1] = __float_as_uint(ap8[((ck ^ sw8) << 2) + tig]);
                af[fm][3] = __float_as_uint(ap8[(((ck + 1) ^ sw8) << 2) + tig]);
            }
            uint32_t bf[4][2];
            #pragma unroll
            for (int fn = 0; fn < 4; fn++) {
                int c = nbase + fn * 8 + grp;
                if (!TRANSB) {
                    bf[fn][0] = __float_as_uint(bs[(kk + tig) * 136 + c]);
                    bf[fn][1] = __float_as_uint(bs[(kk + tig + 4) * 136 + c]);
                } else {
                    int sw = (c >> 1) & 3;
                    const float* bp = bs + c * 16;
                    bf[fn][0] = __float_as_uint(bp[((ck ^ sw) << 2) + tig]);
                    bf[fn][1] = __float_as_uint(bp[(((ck + 1) ^ sw) << 2) + tig]);
                }
            }
            #pragma unroll
            for (int fm = 0; fm < 4; fm++)
                #pragma unroll
                for (int fn = 0; fn < 4; fn++)
                    mma_tf32(acc[fm][fn], af[fm], bf[fn]);
        }
        s ^= 1;
    }

    #pragma unroll
    for (int fm = 0; fm < 4; fm++) {
        int row0 = m0 + mbase + fm * 16 + grp;
        #pragma unroll
        for (int fn = 0; fn < 4; fn++) {
            int col = n0 + nbase + fn * 8 + 2 * tig;
            float v0 = acc[fm][fn][0], v1 = acc[fm][fn][1];
            float v2 = acc[fm][fn][2], v3 = acc[fm][fn][3];
            if (FLAGS & F_BIAS) {
                float bb0 = bias[col], bb1 = bias[col + 1];
                v0 += bb0; v1 += bb1; v2 += bb0; v3 += bb1;
            }
            if (FLAGS & F_RELU) {
                v0 = fmaxf(v0, 0.f); v1 = fmaxf(v1, 0.f);
                v2 = fmaxf(v2, 0.f); v3 = fmaxf(v3, 0.f);
            }
            if (FLAGS & F_AUX) {
                const float* ar = aux + (size_t)row0 * auxld + col;
                const float* ar8 = aux + (size_t)(row0 + 8) * auxld + col;
                v0 += ar[0]; v1 += ar[1]; v2 += ar8[0]; v3 += ar8[1];
            }
            if (FLAGS & F_SIG) {
                const unsigned char* q0p = adjp + (size_t)row0 * ldc + col;
                const unsigned char* q8p = adjp + (size_t)(row0 + 8) * ldc + col;
                v0 = q0p[0] ? 1.f / (1.f + __expf(-v0 * 0.0625f)) : 0.f;
                v1 = q0p[1] ? 1.f / (1.f + __expf(-v1 * 0.0625f)) : 0.f;
                v2 = q8p[0] ? 1.f / (1.f + __expf(-v2 * 0.0625f)) : 0.f;
                v3 = q8p[1] ? 1.f / (1.f + __expf(-v3 * 0.0625f)) : 0.f;
                if (FLAGS & F_DIAG) {
                    if (row0 == col) v0 = 0.f;
                    if (row0 == col + 1) v1 = 0.f;
                    if (row0 + 8 == col) v2 = 0.f;
                    if (row0 + 8 == col + 1) v3 = 0.f;
                }
            }
            *(float2*)&C[(size_t)row0 * ldc + col] = make_float2(v0, v1);
            *(float2*)&C[(size_t)(row0 + 8) * ldc + col] = make_float2(v2, v3);
        }
    }
}

// ---------------------------------------------------------------------------
// Fused GAT aggregation: x[b,:,h*64:] = 0.5*elu(alpha @ h) + 0.5*aux,
// alpha recomputed on the fly from src/dstT/adj + row stats.
// CTA 128xN(=64), warp tile 32x32. grid (1, NN/128, BB*HH).
// ---------------------------------------------------------------------------
__global__ __launch_bounds__(256)
void agg_fused(const float* __restrict__ hmat, const float* __restrict__ src,
               const float2* __restrict__ stat, const float* __restrict__ dstT,
               const unsigned char* __restrict__ adj,
               const float* __restrict__ aux, float* __restrict__ xout, int NN)
{
    int z = blockIdx.z;
    int b = z >> 2, h = z & 3;
    const float* B = hmat + (size_t)b * NN * 256 + h * 64;
    float* C = xout + (size_t)b * NN * 256 + h * 64;
    const float* auxp = aux + (size_t)b * NN * 256 + h * 64;

    int m0 = blockIdx.y * 128;
    __shared__ float As[128 * 20];
    __shared__ float Bs[16 * 72];
    int tid = threadIdx.x;

    // two rows per thread for A staging
    int r0 = m0 + (tid >> 2);
    int r1 = r0 + 64;
    size_t gi0 = (size_t)b * NN + r0;
    size_t gi1 = (size_t)b * NN + r1;
    float s0v = src[gi0 * 4 + h];
    float s1v = src[gi1 * 4 + h];
    float2 st0 = stat[((size_t)b * 4 + h) * NN + r0];
    float2 st1 = stat[((size_t)b * 4 + h) * NN + r1];
    const unsigned char* adj0 = adj + gi0 * NN;
    const unsigned char* adj1 = adj + gi1 * NN;
    const float* dsth = dstT + ((size_t)b * 4 + h) * NN;
    int jc = (tid & 3) * 4;

    const float* bptr = B + (size_t)(tid >> 4) * 256 + (tid & 15) * 4;
    float* as0 = &As[(tid >> 2) * 20 + (tid & 3) * 4];
    float* as1 = &As[((tid >> 2) + 64) * 20 + (tid & 3) * 4];
    float* bs = &Bs[(tid >> 4) * 72 + (tid & 15) * 4];

    int w = tid >> 5, l = tid & 31;
    int wm = w >> 1, wn = w & 1;
    int mrow = wm * 32, ncol = wn * 32;
    int grp = l >> 2, tig = l & 3;

    float acc[2][4][4];
    #pragma unroll
    for (int i = 0; i < 2; i++)
        #pragma unroll
        for (int j = 0; j < 4; j++)
            #pragma unroll
            for (int q = 0; q < 4; q++) acc[i][j][q] = 0.f;

    for (int k0 = 0; k0 < NN; k0 += 16) {
        int j0 = k0 + jc;
        uchar4 a40 = *(const uchar4*)(adj0 + j0);
        uchar4 a41 = *(const uchar4*)(adj1 + j0);
        float4 d4 = *(const float4*)(dsth + j0);
        float4 rb = *(const float4*)(bptr + (size_t)k0 * 256);
        const unsigned char* ap0 = &a40.x;
        const unsigned char* ap1 = &a41.x;
        const float* dp = &d4.x;
        #pragma unroll
        for (int u = 0; u < 4; u++) {
            float e0 = s0v + dp[u]; e0 = e0 > 0.f ? e0 : 0.2f * e0;
            float e1 = s1v + dp[u]; e1 = e1 > 0.f ? e1 : 0.2f * e1;
            e0 = ap0[u] ? e0 : -1e9f;
            e1 = ap1[u] ? e1 : -1e9f;
            as0[u] = to_tf32(__expf(e0 - st0.x) * st0.y);
            as1[u] = to_tf32(__expf(e1 - st1.x) * st1.y);
        }
        bs[0] = to_tf32(rb.x); bs[1] = to_tf32(rb.y); bs[2] = to_tf32(rb.z); bs[3] = to_tf32(rb.w);
        __syncthreads();
        #pragma unroll
        for (int kk = 0; kk < 16; kk += 8) {
            uint32_t af[2][4];
            #pragma unroll
            for (int fm = 0; fm < 2; fm++) {
                int r = (mrow + fm * 16 + grp) * 20;
                af[fm][0] = __float_as_uint(As[r + kk + tig]);
                af[fm][1] = __float_as_uint(As[r + 160 + kk + tig]);
                af[fm][2] = __float_as_uint(As[r + kk + tig + 4]);
                af[fm][3] = __float_as_uint(As[r + 160 + kk + tig + 4]);
            }
            uint32_t bf[4][2];
            #pragma unroll
            for (int fn = 0; fn < 4; fn++) {
                int c = ncol + fn * 8 + grp;
                bf[fn][0] = __float_as_uint(Bs[(kk + tig) * 72 + c]);
                bf[fn][1] = __float_as_uint(Bs[(kk + tig + 4) * 72 + c]);
            }
            #pragma unroll
            for (int fm = 0; fm < 2; fm++)
                #pragma unroll
                for (int fn = 0; fn < 4; fn++)
                    mma_tf32(acc[fm][fn], af[fm], bf[fn]);
        }
        __syncthreads();
    }

    #pragma unroll
    for (int fm = 0; fm < 2; fm++) {
        int row = m0 + mrow + fm * 16 + grp;
        #pragma unroll
        for (int fn = 0; fn < 4; fn++) {
            int col = ncol + fn * 8 + 2 * tig;
            float v0 = acc[fm][fn][0], v1 = acc[fm][fn][1];
            float v2 = acc[fm][fn][2], v3 = acc[fm][fn][3];
            v0 = (v0 > 0.f) ? v0 : expm1f(v0);
            v1 = (v1 > 0.f) ? v1 : expm1f(v1);
            v2 = (v2 > 0.f) ? v2 : expm1f(v2);
            v3 = (v3 > 0.f) ? v3 : expm1f(v3);
            float2 x0 = *(const float2*)&auxp[(size_t)row * 256 + col];
            float2 x1 = *(const float2*)&auxp[(size_t)(row + 8) * 256 + col];
            *(float2*)&C[(size_t)row * 256 + col] =
                make_float2(0.5f * v0 + 0.5f * x0.x, 0.5f * v1 + 0.5f * x0.y);
            *(float2*)&C[(size_t)(row + 8) * 256 + col] =
                make_float2(0.5f * v2 + 0.5f * x1.x, 0.5f * v3 + 0.5f * x1.y);
        }
    }
}

// ---------------------------------------------------------------------------
// Small kernels
// ---------------------------------------------------------------------------
__global__ void k_feat1(const float* __restrict__ x, const float* __restrict__ W1,
                        const float* __restrict__ b1, float* __restrict__ out)
{
    size_t idx = (size_t)blockIdx.x * 256 + threadIdx.x;
    size_t row = idx >> 8;
    int d = idx & 255;
    const float* xr = x + row * 4;
    float v = b1[d] + xr[0]*W1[d] + xr[1]*W1[256+d] + xr[2]*W1[512+d] + xr[3]*W1[768+d];
    out[idx] = (v > 0.f) ? v : expm1f(v);
}

__global__ void k_ln(const float* __restrict__ in, float* __restrict__ out)
{
    size_t row = blockIdx.x;
    int t = threadIdx.x;
    float v = in[row * 256 + t];
    float a = v, b = v * v;
    #pragma unroll
    for (int o = 16; o; o >>= 1) {
        a += __shfl_xor_sync(0xffffffff, a, o);
        b += __shfl_xor_sync(0xffffffff, b, o);
    }
    __shared__ float sa[8], sb[8];
    if ((t & 31) == 0) { sa[t >> 5] = a; sb[t >> 5] = b; }
    __syncthreads();
    if (t < 32) {
        a = (t < 8) ? sa[t] : 0.f;
        b = (t < 8) ? sb[t] : 0.f;
        #pragma unroll
        for (int o = 4; o; o >>= 1) {
            a += __shfl_xor_sync(0xffffffff, a, o);
            b += __shfl_xor_sync(0xffffffff, b, o);
        }
        if (t == 0) { sa[0] = a; sb[0] = b; }
    }
    __syncthreads();
    float mean = sa[0] * (1.f / 256.f);
    float var = sb[0] * (1.f / 256.f) - mean * mean;
    out[row * 256 + t] = (v - mean) * rsqrtf(var + 1e-5f);
}

__global__ void k_attn(const float* __restrict__ q0, const float* __restrict__ kv,
                       float* __restrict__ o0)
{
    size_t t = blockIdx.x;
    int d = threadIdx.x;
    int h = d >> 6;
    __shared__ float logits[4][8];
    __shared__ float red[8];
    float qd = q0[t * 256 + d];
    for (int s = 0; s < 8; s++) {
        float p = qd * kv[(t * 8 + s) * 512 + d];
        #pragma unroll
        for (int o = 16; o; o >>= 1) p += __shfl_xor_sync(0xffffffff, p, o);
        if ((d & 31) == 0) red[d >> 5] = p;
        __syncthreads();
        if (d < 4) logits[d][s] = (red[2 * d] + red[2 * d + 1]) * 0.125f;
        __syncthreads();
    }
    float m = -1e30f;
    #pragma unroll
    for (int s = 0; s < 8; s++) m = fmaxf(m, logits[h][s]);
    float w[8], sum = 0.f;
    #pragma unroll
    for (int s = 0; s < 8; s++) { w[s] = __expf(logits[h][s] - m); sum += w[s]; }
    float inv = 1.f / sum;
    float o = 0.f;
    #pragma unroll
    for (int s = 0; s < 8; s++) o += w[s] * inv * kv[(t * 8 + s) * 512 + 256 + d];
    o0[t * 256 + d] = o;
}

__global__ void k_feat0(const float* __restrict__ tr_emb, const float* __restrict__ x1,
                        const float* __restrict__ ffout, const float* __restrict__ det_emb,
                        float* __restrict__ feat0, float* __restrict__ x)
{
    size_t idx = (size_t)blockIdx.x * 256 + threadIdx.x;
    int d = idx & 255;
    size_t row = idx >> 8;
    int i = row & 1023;
    int b = row >> 10;
    float v;
    if (i < 512) {
        size_t t = (size_t)b * 512 + i;
        v = tr_emb[t * 2048 + d] + 0.9f * (x1[t * 256 + d] + ffout[t * 256 + d]);
    } else {
        size_t t = (size_t)b * 512 + (i - 512);
        v = det_emb[t * 256 + d];
    }
    feat0[idx] = v;
    x[idx] = v;
}

__global__ void k_posvm(const float* __restrict__ tracks, const float* __restrict__ dets,
                        const int* __restrict__ tmarks, const int* __restrict__ dmarks,
                        float* __restrict__ pos, unsigned char* __restrict__ vm)
{
    int idx = blockIdx.x * 256 + threadIdx.x;
    if (idx >= BB * NN1) return;
    int b = idx >> 10, i = idx & 1023;
    float x, y; unsigned char v;
    if (i < 512) {
        const float* p = tracks + ((size_t)(b * 512 + i)) * 8 * 4;
        x = p[0]; y = p[1];
        v = (i < tmarks[b]);
    } else {
        int n = i - 512;
        const float* p = dets + ((size_t)(b * 512 + n)) * 4;
        x = p[0]; y = p[1];
        v = (n < dmarks[b]);
    }
    pos[idx * 2] = x; pos[idx * 2 + 1] = y; vm[idx] = v;
}

__global__ void k_adj(const float* __restrict__ pos, const unsigned char* __restrict__ vm,
                      unsigned char* __restrict__ adj)
{
    int i = blockIdx.x, b = blockIdx.y;
    size_t base = (size_t)b * NN1;
    const float2* p2 = (const float2*)pos;
    float2 pi = p2[base + i];
    unsigned char vi = vm[base + i];
    int j0 = threadIdx.x * 4;
    uchar4 r;
    unsigned char* rp = &r.x;
    #pragma unroll
    for (int u = 0; u < 4; u++) {
        int j = j0 + u;
        float2 pj = p2[base + j];
        float dx = pi.x - pj.x, dy = pi.y - pj.y;
        rp[u] = (unsigned char)((dx * dx + dy * dy < 4.0f) && vi && vm[base + j]);
    }
    ((uchar4*)(adj + ((size_t)b * NN1 + i) * NN1))[threadIdx.x] = r;
}

__global__ void k_adjd(const float* __restrict__ pos, const unsigned char* __restrict__ vm,
                       unsigned char* __restrict__ adjd)
{
    int i = blockIdx.x, b = blockIdx.y;
    size_t base = (size_t)b * NN1 + 512;
    const float2* p2 = (const float2*)pos;
    float2 pi = p2[base + i];
    unsigned char vi = vm[base + i];
    int j0 = threadIdx.x * 4;
    uchar4 r;
    unsigned char* rp = &r.x;
    #pragma unroll
    for (int u = 0; u < 4; u++) {
        int j = j0 + u;
        float2 pj = p2[base + j];
        float dx = pi.x - pj.x, dy = pi.y - pj.y;
        rp[u] = (unsigned char)((dx * dx + dy * dy < 4.0f) && vi && vm[base + j]);
    }
    ((uchar4*)(adjd + ((size_t)b * NNd + i) * NNd))[threadIdx.x] = r;
}

// src/dst projections; writes src[row*4+h] and dstT[(b*4+h)*NN + i]
__global__ void k_srcdst(const float* __restrict__ Hm, const float* __restrict__ a0,
                         float* __restrict__ src, float* __restrict__ dstT, int NN)
{
    size_t row = blockIdx.x;
    int d = threadIdx.x;
    float hv = Hm[row * 256 + d];
    float s = hv * a0[d];
    float t2 = hv * a0[256 + d];
    #pragma unroll
    for (int o = 16; o; o >>= 1) {
        s  += __shfl_xor_sync(0xffffffff, s, o);
        t2 += __shfl_xor_sync(0xffffffff, t2, o);
    }
    __shared__ float ps[8], pt[8];
    if ((d & 31) == 0) { ps[d >> 5] = s; pt[d >> 5] = t2; }
    __syncthreads();
    if (d < 4) {
        int b = (int)(row / NN);
        int i = (int)(row - (size_t)b * NN);
        src[row * 4 + d] = ps[2 * d] + ps[2 * d + 1];
        dstT[((size_t)b * 4 + d) * NN + i] = pt[2 * d] + pt[2 * d + 1];
    }
}

// row softmax stats: stat[(b*4+h)*NN + i] = (rowmax, 1/sum). grid (NN,B), 128thr
__global__ void k_rowstat(const float* __restrict__ src, const float* __restrict__ dstT,
                          const unsigned char* __restrict__ adj, float2* __restrict__ stat,
                          int NN)
{
    int i = blockIdx.x, b = blockIdx.y;
    int h = threadIdx.x >> 5, lane = threadIdx.x & 31;
    float s = src[((size_t)b * NN + i) * 4 + h];
    const uchar4* adjrow = (const uchar4*)(adj + ((size_t)b * NN + i) * NN);
    const float4* dsth = (const float4*)(dstT + ((size_t)b * 4 + h) * NN);
    int nq = NN >> 2;
    float mx = -1e30f;
    for (int jq = lane; jq < nq; jq += 32) {
        uchar4 a4 = adjrow[jq];
        float4 d4 = dsth[jq];
        float e0 = s + d4.x; e0 = e0 > 0.f ? e0 : 0.2f * e0; e0 = a4.x ? e0 : -1e9f;
        float e1 = s + d4.y; e1 = e1 > 0.f ? e1 : 0.2f * e1; e1 = a4.y ? e1 : -1e9f;
        float e2 = s + d4.z; e2 = e2 > 0.f ? e2 : 0.2f * e2; e2 = a4.z ? e2 : -1e9f;
        float e3 = s + d4.w; e3 = e3 > 0.f ? e3 : 0.2f * e3; e3 = a4.w ? e3 : -1e9f;
        mx = fmaxf(mx, fmaxf(fmaxf(e0, e1), fmaxf(e2, e3)));
    }
    #pragma unroll
    for (int o = 16; o; o >>= 1) mx = fmaxf(mx, __shfl_xor_sync(0xffffffff, mx, o));
    float sum = 0.f;
    for (int jq = lane; jq < nq; jq += 32) {
        uchar4 a4 = adjrow[jq];
        float4 d4 = dsth[jq];
        float e0 = s + d4.x; e0 = e0 > 0.f ? e0 : 0.2f * e0; e0 = a4.x ? e0 : -1e9f;
        float e1 = s + d4.y; e1 = e1 > 0.f ? e1 : 0.2f * e1; e1 = a4.y ? e1 : -1e9f;
        float e2 = s + d4.z; e2 = e2 > 0.f ? e2 : 0.2f * e2; e2 = a4.z ? e2 : -1e9f;
        float e3 = s + d4.w; e3 = e3 > 0.f ? e3 : 0.2f * e3; e3 = a4.w ? e3 : -1e9f;
        sum += __expf(e0 - mx) + __expf(e1 - mx) + __expf(e2 - mx) + __expf(e3 - mx);
    }
    #pragma unroll
    for (int o = 16; o; o >>= 1) sum += __shfl_xor_sync(0xffffffff, sum, o);
    if (lane == 0)
        stat[((size_t)b * 4 + h) * NN + i] = make_float2(mx, 1.f / sum);
}

__global__ void k_asso(const float* __restrict__ scores, float* __restrict__ out)
{
    size_t idx = (size_t)blockIdx.x * 256 + threadIdx.x;
    int j = idx & 511;
    size_t r = idx >> 9;
    int m = r & 511;
    int b = (int)(r >> 9);
    out[idx] = scores[(((size_t)b * 1024 + m) * 1024) + 512 + j];
}

// ---------------------------------------------------------------------------
// Host side
// ---------------------------------------------------------------------------
static void run_big(const float* A, int lda, long long sA1, long long sA2,
                    const float* B, int ldb, long long sB1, long long sB2,
                    float* C, int ldc, long long sC1, long long sC2,
                    int M, int N, int K, int batch, int bdiv,
                    const float* bias, const float* aux, int auxld,
                    const unsigned char* adjp, long long sAdj,
                    int flags, bool transb)
{
    dim3 g(N / 128, M / 128, batch);
#define CALLBIG(T, F) tgemm_big<T, F><<<g, 256>>>(A, lda, sA1, sA2, B, ldb, sB1, sB2, \
        C, ldc, sC1, sC2, K, bdiv, bias, aux, auxld, adjp, sAdj)
    if (!transb) {
        if (flags == 0)           CALLBIG(false, 0);
        else if (flags == F_BIAS) CALLBIG(false, F_BIAS);
        else if (flags == F_RELU) CALLBIG(false, F_RELU);
        else                      CALLBIG(false, F_AUX);
    } else {
        if (flags == F_SIG)       CALLBIG(true, F_SIG);
        else                      CALLBIG(true, F_SIG | F_DIAG);
    }
#undef CALLBIG
}

#define SYM(p, s) cudaGetSymbolAddress((void**)&p, s)

extern "C" void kernel_launch(void* const* d_in, const int* in_sizes, int n_in,
                              void* d_out, int out_size)
{
    (void)in_sizes; (void)n_in; (void)out_size;
    const float* tracks = (const float*)d_in[0];
    const float* dets   = (const float*)d_in[1];
    const int* tmarks   = (const int*)d_in[2];
    const int* dmarks   = (const int*)d_in[3];
    const float* W1     = (const float*)d_in[4];
    const float* b1     = (const float*)d_in[5];
    const float* W2     = (const float*)d_in[6];
    const float* b2     = (const float*)d_in[7];
    const float* Wqkv   = (const float*)d_in[8];
    const float* Wo     = (const float*)d_in[9];
    const float* ff1    = (const float*)d_in[10];
    const float* ff2    = (const float*)d_in[11];
    const float* gatW   = (const float*)d_in[12];
    const float* gata   = (const float*)d_in[13];
    const float* dgatW  = (const float*)d_in[14];
    const float* dgata  = (const float*)d_in[15];
    const float* clsWq  = (const float*)d_in[16];
    const float* clsWk  = (const float*)d_in[17];

    float* out = (float*)d_out;
    float* out_scores = out;
    float* out_det    = out + (size_t)BB * NN1 * NN1;
    float* out_asso   = out_det + (size_t)BB * NNd * NNd;

    float *tr_h1, *tr_emb, *ln, *kv, *det_h1, *det_emb, *q0, *o0, *x1,
          *ln2, *ffh, *ffout, *feat0, *x, *h, *src, *dstT, *pos, *xq, *xk;
    float2* stat;
    unsigned char *adj, *adjd, *vm;
    SYM(tr_h1, g_tr_h1);   SYM(tr_emb, g_tr_emb); SYM(ln, g_ln);
    SYM(kv, g_kv);         SYM(det_h1, g_det_h1); SYM(det_emb, g_det_emb);
    SYM(q0, g_q0);         SYM(o0, g_o0);
    SYM(x1, g_x1);         SYM(ln2, g_ln2);       SYM(ffh, g_ffh);
    SYM(ffout, g_ffout);   SYM(feat0, g_feat0);   SYM(x, g_x);
    SYM(h, g_h);           SYM(src, g_src);       SYM(dstT, g_dstT);
    SYM(stat, g_stat);     SYM(adj, g_adj);
    SYM(adjd, g_adjd);     SYM(pos, g_pos);       SYM(vm, g_vm);
    SYM(xq, g_xq);         SYM(xk, g_xk);

    // ---- feature MLP ----
    k_feat1<<<TM, 256>>>(tracks, W1, b1, tr_h1);
    run_big(tr_h1, 256, 0, 0, W2, 256, 0, 0, tr_emb, 256, 0, 0,
            TM, 256, 256, 1, 1, b2, nullptr, 0, nullptr, 0, F_BIAS, false);
    k_feat1<<<ND, 256>>>(dets, W1, b1, det_h1);
    run_big(det_h1, 256, 0, 0, W2, 256, 0, 0, det_emb, 256, 0, 0,
            ND, 256, 256, 1, 1, b2, nullptr, 0, nullptr, 0, F_BIAS, false);

    // ---- encoder (only r=0 outputs needed downstream) ----
    k_ln<<<TM, 256>>>(tr_emb, ln);
    run_big(ln, 256, 0, 0, Wqkv + 256, 768, 0, 0, kv, 512, 0, 0,
            TM, 512, 256, 1, 1, nullptr, nullptr, 0, nullptr, 0, 0, false);
    run_big(ln, 2048, 0, 0, Wqkv, 768, 0, 0, q0, 256, 0, 0,
            TT, 256, 256, 1, 1, nullptr, nullptr, 0, nullptr, 0, 0, false);
    k_attn<<<TT, 256>>>(q0, kv, o0);
    run_big(o0, 256, 0, 0, Wo, 256, 0, 0, x1, 256, 0, 0,
            TT, 256, 256, 1, 1, nullptr, tr_emb, 2048, nullptr, 0, F_AUX, false);
    k_ln<<<TT, 256>>>(x1, ln2);
    run_big(ln2, 256, 0, 0, ff1, 1024, 0, 0, ffh, 1024, 0, 0,
            TT, 1024, 256, 1, 1, nullptr, nullptr, 0, nullptr, 0, F_RELU, false);
    run_big(ffh, 1024, 0, 0, ff2, 256, 0, 0, ffout, 256, 0, 0,
            TT, 256, 1024, 1, 1, nullptr, nullptr, 0, nullptr, 0, 0, false);
    k_feat0<<<ROWS1, 256>>>(tr_emb, x1, ffout, det_emb, feat0, x);

    // ---- adjacency ----
    k_posvm<<<64, 256>>>(tracks, dets, tmarks, dmarks, pos, vm);
    k_adj<<<dim3(NN1, BB), 256>>>(pos, vm, adj);
    k_adjd<<<dim3(NNd, BB), 128>>>(pos, vm, adjd);

    // ---- main GAT x2 ----
    for (int l = 0; l < 2; l++) {
        run_big(x, 256, 0, 0, gatW + (size_t)l * 256 * 256, 256, 0, 0,
                h, 256, 0, 0, ROWS1, 256, 256, 1, 1,
                nullptr, nullptr, 0, nullptr, 0, 0, false);
        k_srcdst<<<ROWS1, 256>>>(h, gata + (size_t)l * 512, src, dstT, NN1);
        k_rowstat<<<dim3(NN1, BB), 128>>>(src, dstT, adj, stat, NN1);
        agg_fused<<<dim3(1, NN1 / 128, BB * HH), 256>>>(
            h, src, stat, dstT, adj, feat0, x, NN1);
    }

    // ---- main scores ----
    run_big(x, 256, 0, 0, clsWq, 256, 0, 0, xq, 256, 0, 0,
            ROWS1, 256, 256, 1, 1, nullptr, nullptr, 0, nullptr, 0, 0, false);
    run_big(x, 256, 0, 0, clsWk, 256, 0, 0, xk, 256, 0, 0,
            ROWS1, 256, 256, 1, 1, nullptr, nullptr, 0, nullptr, 0, 0, false);
    run_big(xq, 256, (long long)NN1 * 256, 0,
            xk, 256, (long long)NN1 * 256, 0,
            out_scores, NN1, (long long)NN1 * NN1, 0,
            NN1, NN1, 256, BB, 1,
            nullptr, nullptr, 0, adj, (long long)NN1 * NN1, F_SIG, true);
    k_asso<<<(int)(((size_t)BB * 512 * 512) / 256), 256>>>(out_scores, out_asso);

    // ---- detection GAT x2 ----
    for (int l = 0; l < 2; l++) {
        const float* xin = (l == 0) ? det_emb : x;
        run_big(xin, 256, 0, 0, dgatW + (size_t)l * 256 * 256, 256, 0, 0,
                h, 256, 0, 0, ND, 256, 256, 1, 1,
                nullptr, nullptr, 0, nullptr, 0, 0, false);
        k_srcdst<<<ND, 256>>>(h, dgata + (size_t)l * 512, src, dstT, NNd);
        k_rowstat<<<dim3(NNd, BB), 128>>>(src, dstT, adjd, stat, NNd);
        agg_fused<<<dim3(1, NNd / 128, BB * HH), 256>>>(
            h, src, stat, dstT, adjd, (l == 0) ? det_emb : det_emb, x, NNd);
    }

    // ---- detection scores ----
    run_big(x, 256, 0, 0, clsWq + 256 * 256, 256, 0, 0, xq, 256, 0, 0,
            ND, 256, 256, 1, 1, nullptr, nullptr, 0, nullptr, 0, 0, false);
    run_big(x, 256, 0, 0, clsWk + 256 * 256, 256, 0, 0, xk, 256, 0, 0,
            ND, 256, 256, 1, 1, nullptr, nullptr, 0, nullptr, 0, 0, false);
    run_big(xq, 256, (long long)NNd * 256, 0,
            xk, 256, (long long)NNd * 256, 0,
            out_det, NNd, (long long)NNd * NNd, 0,
            NNd, NNd, 256, BB, 1,
            nullptr, nullptr, 0, adjd, (long long)NNd * NNd, F_SIG | F_DIAG, true);
}

// round 8
// speedup vs baseline: 3.3358x; 1.1768x over previous
#include <cuda_runtime.h>
#include <cuda_fp16.h>
#include <math.h>
#include <stdint.h>

// ---------------------------------------------------------------------------
// Problem dims
// ---------------------------------------------------------------------------
#define BB 16
#define MM 512
#define NNd 512
#define RR 8
#define DD 256
#define HH 4
#define NN1 1024
#define TM  (BB*MM*RR)    // 65536
#define TT  (BB*MM)       // 8192
#define ND  (BB*NNd)      // 8192
#define ROWS1 (BB*NN1)    // 16384

#define F_BIAS 1
#define F_RELU 2
#define F_AUX  4
#define F_SIG  8
#define F_DIAG 16

// ---------------------------------------------------------------------------
// Scratch
// ---------------------------------------------------------------------------
__device__ float g_tr_h1[TM*DD];
__device__ float g_tr_emb[TM*DD];
__device__ float g_ln[TM*DD];
__device__ float g_kv[TM*512];
__device__ float g_det_h1[ND*DD];
__device__ float g_det_emb[ND*DD];
__device__ float g_q0[TT*DD];
__device__ float g_o0[TT*DD];
__device__ float g_x1[TT*DD];
__device__ float g_ln2[TT*DD];
__device__ float g_ffh[TT*1024];
__device__ float g_ffout[TT*DD];
__device__ float g_feat0[ROWS1*DD];
__device__ float g_x[ROWS1*DD];
__device__ float g_h[ROWS1*DD];
__device__ float g_src[ROWS1*HH];
__device__ float g_dstT[BB*HH*NN1];
__device__ float2 g_stat[BB*HH*NN1];
__device__ unsigned char g_adj[(size_t)BB*NN1*NN1];
__device__ unsigned char g_adjd[(size_t)BB*NNd*NNd];
__device__ float g_pos[BB*NN1*2];
__device__ unsigned char g_vm[BB*NN1];
__device__ float g_xq[ROWS1*DD];
__device__ float g_xk[ROWS1*DD];

// ---------------------------------------------------------------------------
// fp16 helpers
// ---------------------------------------------------------------------------
__device__ __forceinline__ uint32_t pk(float lo, float hi) {
    __half2 v = __floats2half2_rn(lo, hi);
    return *reinterpret_cast<uint32_t*>(&v);
}
__device__ __forceinline__ void mma_f16(float* c, const uint32_t* a, const uint32_t* b) {
    asm volatile(
        "mma.sync.aligned.m16n8k16.row.col.f32.f16.f16.f32 "
        "{%0,%1,%2,%3}, {%4,%5,%6,%7}, {%8,%9}, {%0,%1,%2,%3};\n"
        : "+f"(c[0]), "+f"(c[1]), "+f"(c[2]), "+f"(c[3])
        : "r"(a[0]), "r"(a[1]), "r"(a[2]), "r"(a[3]), "r"(b[0]), "r"(b[1]));
}

// ---------------------------------------------------------------------------
// BIG GEMM (fp16 m16n8k16): CTA 128x128, BK=16, 256 thr, warp tile 64x32,
// double-buffered. A smem [128 rows][8 k-pairs] stride 12 words (conflict-free
// frag loads). B normal: [8 kp][128 n] stride 136; B trans: like A.
// Requires M%128==0, N%128==0, K%16==0.
// ---------------------------------------------------------------------------
template<bool TRANSB, int FLAGS>
__global__ __launch_bounds__(256, 2)
void tgemm_big(const float* __restrict__ A, int lda, long long sA,
               const float* __restrict__ B, int ldb, long long sB,
               float* __restrict__ C, int ldc, long long sC,
               int K,
               const float* __restrict__ bias,
               const float* __restrict__ aux, int auxld,
               const unsigned char* __restrict__ adjp, long long sAdj)
{
    int bz = blockIdx.z;
    A += (long long)bz * sA;
    B += (long long)bz * sB;
    C += (long long)bz * sC;
    if (FLAGS & F_SIG) adjp += (long long)bz * sAdj;

    int m0 = blockIdx.y * 128, n0 = blockIdx.x * 128;

    __shared__ uint32_t As[2][128 * 12];
    __shared__ uint32_t Bs[2][1536];   // trans: 128*12; normal: 8*136=1088

    int tid = threadIdx.x;
    // A staging: row = tid>>1, half = tid&1 covers cols half*8 .. +7
    int arow = tid >> 1, ahalf = tid & 1;
    const float* gA = A + (size_t)(m0 + arow) * lda + ahalf * 8;

    // B staging
    const float* gB;
    int boff;
    if (!TRANSB) {
        int kp = tid >> 5, nq = tid & 31;
        gB = B + (size_t)(2 * kp) * ldb + n0 + nq * 4;
        boff = kp * 136 + nq * 4;
    } else {
        gB = B + (size_t)(n0 + arow) * ldb + ahalf * 8;
        boff = arow * 12 + ahalf * 4;
    }

    int w = tid >> 5, l = tid & 31;
    int mbase = (w >> 2) * 64, nbase = (w & 3) * 32;
    int grp = l >> 2, tig = l & 3;

    float acc[4][4][4];
    #pragma unroll
    for (int i = 0; i < 4; i++)
        #pragma unroll
        for (int j = 0; j < 4; j++)
            #pragma unroll
            for (int q = 0; q < 4; q++) acc[i][j][q] = 0.f;

    int nk = K >> 4;
    float4 va0, va1, vb0, vb1;

    // load stage 0
    va0 = *(const float4*)(gA);
    va1 = *(const float4*)(gA + 4);
    if (!TRANSB) { vb0 = *(const float4*)(gB); vb1 = *(const float4*)(gB + ldb); }
    else         { vb0 = *(const float4*)(gB); vb1 = *(const float4*)(gB + 4); }
    // store stage 0
    {
        uint32_t* ap = &As[0][arow * 12 + ahalf * 4];
        ap[0] = pk(va0.x, va0.y); ap[1] = pk(va0.z, va0.w);
        ap[2] = pk(va1.x, va1.y); ap[3] = pk(va1.z, va1.w);
        uint32_t* bp = &Bs[0][boff];
        if (!TRANSB) {
            bp[0] = pk(vb0.x, vb1.x); bp[1] = pk(vb0.y, vb1.y);
            bp[2] = pk(vb0.z, vb1.z); bp[3] = pk(vb0.w, vb1.w);
        } else {
            bp[0] = pk(vb0.x, vb0.y); bp[1] = pk(vb0.z, vb0.w);
            bp[2] = pk(vb1.x, vb1.y); bp[3] = pk(vb1.z, vb1.w);
        }
    }
    // load stage 1
    if (nk > 1) {
        va0 = *(const float4*)(gA + 16);
        va1 = *(const float4*)(gA + 20);
        if (!TRANSB) { vb0 = *(const float4*)(gB + (size_t)16 * ldb); vb1 = *(const float4*)(gB + (size_t)17 * ldb); }
        else         { vb0 = *(const float4*)(gB + 16); vb1 = *(const float4*)(gB + 20); }
    }

    int s = 0;
    for (int i = 0; i < nk; i++) {
        __syncthreads();
        if (i + 1 < nk) {
            int d = s ^ 1;
            uint32_t* ap = &As[d][arow * 12 + ahalf * 4];
            ap[0] = pk(va0.x, va0.y); ap[1] = pk(va0.z, va0.w);
            ap[2] = pk(va1.x, va1.y); ap[3] = pk(va1.z, va1.w);
            uint32_t* bp = &Bs[d][boff];
            if (!TRANSB) {
                bp[0] = pk(vb0.x, vb1.x); bp[1] = pk(vb0.y, vb1.y);
                bp[2] = pk(vb0.z, vb1.z); bp[3] = pk(vb0.w, vb1.w);
            } else {
                bp[0] = pk(vb0.x, vb0.y); bp[1] = pk(vb0.z, vb0.w);
                bp[2] = pk(vb1.x, vb1.y); bp[3] = pk(vb1.z, vb1.w);
            }
            if (i + 2 < nk) {
                int k0 = (i + 2) * 16;
                va0 = *(const float4*)(gA + k0);
                va1 = *(const float4*)(gA + k0 + 4);
                if (!TRANSB) {
                    vb0 = *(const float4*)(gB + (size_t)k0 * ldb);
                    vb1 = *(const float4*)(gB + (size_t)(k0 + 1) * ldb);
                } else {
                    vb0 = *(const float4*)(gB + k0);
                    vb1 = *(const float4*)(gB + k0 + 4);
                }
            }
        }
        const uint32_t* as = As[s];
        const uint32_t* bs = Bs[s];
        uint32_t af[4][4];
        #pragma unroll
        for (int fm = 0; fm < 4; fm++) {
            int r = mbase + fm * 16 + grp;
            af[fm][0] = as[r * 12 + tig];
            af[fm][1] = as[(r + 8) * 12 + tig];
            af[fm][2] = as[r * 12 + 4 + tig];
            af[fm][3] = as[(r + 8) * 12 + 4 + tig];
        }
        uint32_t bfr[4][2];
        #pragma unroll
        for (int fn = 0; fn < 4; fn++) {
            int c = nbase + fn * 8 + grp;
            if (!TRANSB) {
                bfr[fn][0] = bs[tig * 136 + c];
                bfr[fn][1] = bs[(4 + tig) * 136 + c];
            } else {
                bfr[fn][0] = bs[c * 12 + tig];
                bfr[fn][1] = bs[c * 12 + 4 + tig];
            }
        }
        #pragma unroll
        for (int fm = 0; fm < 4; fm++)
            #pragma unroll
            for (int fn = 0; fn < 4; fn++)
                mma_f16(acc[fm][fn], af[fm], bfr[fn]);
        s ^= 1;
    }

    // epilogue
    #pragma unroll
    for (int fm = 0; fm < 4; fm++) {
        int row0 = m0 + mbase + fm * 16 + grp;
        #pragma unroll
        for (int fn = 0; fn < 4; fn++) {
            int col = n0 + nbase + fn * 8 + 2 * tig;
            float v0 = acc[fm][fn][0], v1 = acc[fm][fn][1];
            float v2 = acc[fm][fn][2], v3 = acc[fm][fn][3];
            if (FLAGS & F_BIAS) {
                float bb0 = bias[col], bb1 = bias[col + 1];
                v0 += bb0; v1 += bb1; v2 += bb0; v3 += bb1;
            }
            if (FLAGS & F_RELU) {
                v0 = fmaxf(v0, 0.f); v1 = fmaxf(v1, 0.f);
                v2 = fmaxf(v2, 0.f); v3 = fmaxf(v3, 0.f);
            }
            if (FLAGS & F_AUX) {
                const float* ar = aux + (size_t)row0 * auxld + col;
                const float* ar8 = aux + (size_t)(row0 + 8) * auxld + col;
                v0 += ar[0]; v1 += ar[1]; v2 += ar8[0]; v3 += ar8[1];
            }
            if (FLAGS & F_SIG) {
                const unsigned char* q0p = adjp + (size_t)row0 * ldc + col;
                const unsigned char* q8p = adjp + (size_t)(row0 + 8) * ldc + col;
                v0 = q0p[0] ? 1.f / (1.f + __expf(-v0 * 0.0625f)) : 0.f;
                v1 = q0p[1] ? 1.f / (1.f + __expf(-v1 * 0.0625f)) : 0.f;
                v2 = q8p[0] ? 1.f / (1.f + __expf(-v2 * 0.0625f)) : 0.f;
                v3 = q8p[1] ? 1.f / (1.f + __expf(-v3 * 0.0625f)) : 0.f;
                if (FLAGS & F_DIAG) {
                    if (row0 == col) v0 = 0.f;
                    if (row0 == col + 1) v1 = 0.f;
                    if (row0 + 8 == col) v2 = 0.f;
                    if (row0 + 8 == col + 1) v3 = 0.f;
                }
            }
            *(float2*)&C[(size_t)row0 * ldc + col] = make_float2(v0, v1);
            *(float2*)&C[(size_t)(row0 + 8) * ldc + col] = make_float2(v2, v3);
        }
    }
}

// ---------------------------------------------------------------------------
// Fused GAT aggregation (fp16 m16n8k16, alpha recomputed on the fly):
// x[b,:,h*64:+64] = 0.5*elu(alpha @ h) + 0.5*aux. CTA 128x64, warp 32x32.
// grid (1, NN/128, BB*HH).
// ---------------------------------------------------------------------------
__global__ __launch_bounds__(256)
void agg_fused(const float* __restrict__ hmat, const float* __restrict__ src,
               const float2* __restrict__ stat, const float* __restrict__ dstT,
               const unsigned char* __restrict__ adj,
               const float* __restrict__ aux, float* __restrict__ xout, int NN)
{
    int z = blockIdx.z;
    int b = z >> 2, h = z & 3;
    const float* B = hmat + (size_t)b * NN * 256 + h * 64;
    float* C = xout + (size_t)b * NN * 256 + h * 64;
    const float* auxp = aux + (size_t)b * NN * 256 + h * 64;

    int m0 = blockIdx.y * 128;
    __shared__ uint32_t As[128 * 12];
    __shared__ uint32_t Bs[8 * 72];
    int tid = threadIdx.x;

    int rowA = tid >> 2;
    int jc = (tid & 3) * 4;
    int pb = (tid & 3) * 2;
    int r0 = m0 + rowA;
    int r1 = r0 + 64;
    size_t gi0 = (size_t)b * NN + r0;
    size_t gi1 = (size_t)b * NN + r1;
    float s0v = src[gi0 * 4 + h];
    float s1v = src[gi1 * 4 + h];
    float2 st0 = stat[((size_t)b * 4 + h) * NN + r0];
    float2 st1 = stat[((size_t)b * 4 + h) * NN + r1];
    const unsigned char* adj0 = adj + gi0 * NN;
    const unsigned char* adj1 = adj + gi1 * NN;
    const float* dsth = dstT + ((size_t)b * 4 + h) * NN;

    int kp = tid >> 5, nq = tid & 31;
    const float* gB = B + (size_t)(2 * kp) * 256 + 2 * nq;

    int w = tid >> 5, l = tid & 31;
    int wm = w >> 1, wn = w & 1;
    int mrow = wm * 32, ncol = wn * 32;
    int grp = l >> 2, tig = l & 3;

    float acc[2][4][4];
    #pragma unroll
    for (int i = 0; i < 2; i++)
        #pragma unroll
        for (int j = 0; j < 4; j++)
            #pragma unroll
            for (int q = 0; q < 4; q++) acc[i][j][q] = 0.f;

    for (int k0 = 0; k0 < NN; k0 += 16) {
        int j0 = k0 + jc;
        uchar4 a40 = *(const uchar4*)(adj0 + j0);
        uchar4 a41 = *(const uchar4*)(adj1 + j0);
        float4 d4 = *(const float4*)(dsth + j0);
        const unsigned char* ap0 = &a40.x;
        const unsigned char* ap1 = &a41.x;
        const float* dp = &d4.x;
        float al0[4], al1[4];
        #pragma unroll
        for (int u = 0; u < 4; u++) {
            float e0 = s0v + dp[u]; e0 = e0 > 0.f ? e0 : 0.2f * e0;
            float e1 = s1v + dp[u]; e1 = e1 > 0.f ? e1 : 0.2f * e1;
            e0 = ap0[u] ? e0 : -1e9f;
            e1 = ap1[u] ? e1 : -1e9f;
            al0[u] = __expf(e0 - st0.x) * st0.y;
            al1[u] = __expf(e1 - st1.x) * st1.y;
        }
        As[rowA * 12 + pb]            = pk(al0[0], al0[1]);
        As[rowA * 12 + pb + 1]        = pk(al0[2], al0[3]);
        As[(rowA + 64) * 12 + pb]     = pk(al1[0], al1[1]);
        As[(rowA + 64) * 12 + pb + 1] = pk(al1[2], al1[3]);
        {
            const float* bp0 = gB + (size_t)k0 * 256;
            float2 rb0 = *(const float2*)(bp0);
            float2 rb1 = *(const float2*)(bp0 + 256);
            Bs[kp * 72 + 2 * nq]     = pk(rb0.x, rb1.x);
            Bs[kp * 72 + 2 * nq + 1] = pk(rb0.y, rb1.y);
        }
        __syncthreads();
        uint32_t af[2][4];
        #pragma unroll
        for (int fm = 0; fm < 2; fm++) {
            int r = mrow + fm * 16 + grp;
            af[fm][0] = As[r * 12 + tig];
            af[fm][1] = As[(r + 8) * 12 + tig];
            af[fm][2] = As[r * 12 + 4 + tig];
            af[fm][3] = As[(r + 8) * 12 + 4 + tig];
        }
        uint32_t bfr[4][2];
        #pragma unroll
        for (int fn = 0; fn < 4; fn++) {
            int c = ncol + fn * 8 + grp;
            bfr[fn][0] = Bs[tig * 72 + c];
            bfr[fn][1] = Bs[(4 + tig) * 72 + c];
        }
        #pragma unroll
        for (int fm = 0; fm < 2; fm++)
            #pragma unroll
            for (int fn = 0; fn < 4; fn++)
                mma_f16(acc[fm][fn], af[fm], bfr[fn]);
        __syncthreads();
    }

    #pragma unroll
    for (int fm = 0; fm < 2; fm++) {
        int row = m0 + mrow + fm * 16 + grp;
        #pragma unroll
        for (int fn = 0; fn < 4; fn++) {
            int col = ncol + fn * 8 + 2 * tig;
            float v0 = acc[fm][fn][0], v1 = acc[fm][fn][1];
            float v2 = acc[fm][fn][2], v3 = acc[fm][fn][3];
            v0 = (v0 > 0.f) ? v0 : expm1f(v0);
            v1 = (v1 > 0.f) ? v1 : expm1f(v1);
            v2 = (v2 > 0.f) ? v2 : expm1f(v2);
            v3 = (v3 > 0.f) ? v3 : expm1f(v3);
            float2 x0 = *(const float2*)&auxp[(size_t)row * 256 + col];
            float2 x1 = *(const float2*)&auxp[(size_t)(row + 8) * 256 + col];
            *(float2*)&C[(size_t)row * 256 + col] =
                make_float2(0.5f * v0 + 0.5f * x0.x, 0.5f * v1 + 0.5f * x0.y);
            *(float2*)&C[(size_t)(row + 8) * 256 + col] =
                make_float2(0.5f * v2 + 0.5f * x1.x, 0.5f * v3 + 0.5f * x1.y);
        }
    }
}

// ---------------------------------------------------------------------------
// Small kernels
// ---------------------------------------------------------------------------
__global__ void k_feat1(const float* __restrict__ x, const float* __restrict__ W1,
                        const float* __restrict__ b1, float* __restrict__ out)
{
    size_t idx = (size_t)blockIdx.x * 256 + threadIdx.x;
    size_t row = idx >> 8;
    int d = idx & 255;
    const float* xr = x + row * 4;
    float v = b1[d] + xr[0]*W1[d] + xr[1]*W1[256+d] + xr[2]*W1[512+d] + xr[3]*W1[768+d];
    out[idx] = (v > 0.f) ? v : expm1f(v);
}

__global__ void k_ln(const float* __restrict__ in, float* __restrict__ out)
{
    size_t row = blockIdx.x;
    int t = threadIdx.x;
    float v = in[row * 256 + t];
    float a = v, b = v * v;
    #pragma unroll
    for (int o = 16; o; o >>= 1) {
        a += __shfl_xor_sync(0xffffffff, a, o);
        b += __shfl_xor_sync(0xffffffff, b, o);
    }
    __shared__ float sa[8], sb[8];
    if ((t & 31) == 0) { sa[t >> 5] = a; sb[t >> 5] = b; }
    __syncthreads();
    if (t < 32) {
        a = (t < 8) ? sa[t] : 0.f;
        b = (t < 8) ? sb[t] : 0.f;
        #pragma unroll
        for (int o = 4; o; o >>= 1) {
            a += __shfl_xor_sync(0xffffffff, a, o);
            b += __shfl_xor_sync(0xffffffff, b, o);
        }
        if (t == 0) { sa[0] = a; sb[0] = b; }
    }
    __syncthreads();
    float mean = sa[0] * (1.f / 256.f);
    float var = sb[0] * (1.f / 256.f) - mean * mean;
    out[row * 256 + t] = (v - mean) * rsqrtf(var + 1e-5f);
}

__global__ void k_attn(const float* __restrict__ q0, const float* __restrict__ kv,
                       float* __restrict__ o0)
{
    size_t t = blockIdx.x;
    int d = threadIdx.x;
    int h = d >> 6;
    __shared__ float logits[4][8];
    __shared__ float red[8];
    float qd = q0[t * 256 + d];
    for (int s = 0; s < 8; s++) {
        float p = qd * kv[(t * 8 + s) * 512 + d];
        #pragma unroll
        for (int o = 16; o; o >>= 1) p += __shfl_xor_sync(0xffffffff, p, o);
        if ((d & 31) == 0) red[d >> 5] = p;
        __syncthreads();
        if (d < 4) logits[d][s] = (red[2 * d] + red[2 * d + 1]) * 0.125f;
        __syncthreads();
    }
    float m = -1e30f;
    #pragma unroll
    for (int s = 0; s < 8; s++) m = fmaxf(m, logits[h][s]);
    float w[8], sum = 0.f;
    #pragma unroll
    for (int s = 0; s < 8; s++) { w[s] = __expf(logits[h][s] - m); sum += w[s]; }
    float inv = 1.f / sum;
    float o = 0.f;
    #pragma unroll
    for (int s = 0; s < 8; s++) o += w[s] * inv * kv[(t * 8 + s) * 512 + 256 + d];
    o0[t * 256 + d] = o;
}

__global__ void k_feat0(const float* __restrict__ tr_emb, const float* __restrict__ x1,
                        const float* __restrict__ ffout, const float* __restrict__ det_emb,
                        float* __restrict__ feat0, float* __restrict__ x)
{
    size_t idx = (size_t)blockIdx.x * 256 + threadIdx.x;
    int d = idx & 255;
    size_t row = idx >> 8;
    int i = row & 1023;
    int b = row >> 10;
    float v;
    if (i < 512) {
        size_t t = (size_t)b * 512 + i;
        v = tr_emb[t * 2048 + d] + 0.9f * (x1[t * 256 + d] + ffout[t * 256 + d]);
    } else {
        size_t t = (size_t)b * 512 + (i - 512);
        v = det_emb[t * 256 + d];
    }
    feat0[idx] = v;
    x[idx] = v;
}

__global__ void k_posvm(const float* __restrict__ tracks, const float* __restrict__ dets,
                        const int* __restrict__ tmarks, const int* __restrict__ dmarks,
                        float* __restrict__ pos, unsigned char* __restrict__ vm)
{
    int idx = blockIdx.x * 256 + threadIdx.x;
    if (idx >= BB * NN1) return;
    int b = idx >> 10, i = idx & 1023;
    float x, y; unsigned char v;
    if (i < 512) {
        const float* p = tracks + ((size_t)(b * 512 + i)) * 8 * 4;
        x = p[0]; y = p[1];
        v = (i < tmarks[b]);
    } else {
        int n = i - 512;
        const float* p = dets + ((size_t)(b * 512 + n)) * 4;
        x = p[0]; y = p[1];
        v = (n < dmarks[b]);
    }
    pos[idx * 2] = x; pos[idx * 2 + 1] = y; vm[idx] = v;
}

__global__ void k_adj(const float* __restrict__ pos, const unsigned char* __restrict__ vm,
                      unsigned char* __restrict__ adj)
{
    int i = blockIdx.x, b = blockIdx.y;
    size_t base = (size_t)b * NN1;
    const float2* p2 = (const float2*)pos;
    float2 pi = p2[base + i];
    unsigned char vi = vm[base + i];
    int j0 = threadIdx.x * 4;
    uchar4 r;
    unsigned char* rp = &r.x;
    #pragma unroll
    for (int u = 0; u < 4; u++) {
        int j = j0 + u;
        float2 pj = p2[base + j];
        float dx = pi.x - pj.x, dy = pi.y - pj.y;
        rp[u] = (unsigned char)((dx * dx + dy * dy < 4.0f) && vi && vm[base + j]);
    }
    ((uchar4*)(adj + ((size_t)b * NN1 + i) * NN1))[threadIdx.x] = r;
}

__global__ void k_adjd(const float* __restrict__ pos, const unsigned char* __restrict__ vm,
                       unsigned char* __restrict__ adjd)
{
    int i = blockIdx.x, b = blockIdx.y;
    size_t base = (size_t)b * NN1 + 512;
    const float2* p2 = (const float2*)pos;
    float2 pi = p2[base + i];
    unsigned char vi = vm[base + i];
    int j0 = threadIdx.x * 4;
    uchar4 r;
    unsigned char* rp = &r.x;
    #pragma unroll
    for (int u = 0; u < 4; u++) {
        int j = j0 + u;
        float2 pj = p2[base + j];
        float dx = pi.x - pj.x, dy = pi.y - pj.y;
        rp[u] = (unsigned char)((dx * dx + dy * dy < 4.0f) && vi && vm[base + j]);
    }
    ((uchar4*)(adjd + ((size_t)b * NNd + i) * NNd))[threadIdx.x] = r;
}

__global__ void k_srcdst(const float* __restrict__ Hm, const float* __restrict__ a0,
                         float* __restrict__ src, float* __restrict__ dstT, int NN)
{
    size_t row = blockIdx.x;
    int d = threadIdx.x;
    float hv = Hm[row * 256 + d];
    float s = hv * a0[d];
    float t2 = hv * a0[256 + d];
    #pragma unroll
    for (int o = 16; o; o >>= 1) {
        s  += __shfl_xor_sync(0xffffffff, s, o);
        t2 += __shfl_xor_sync(0xffffffff, t2, o);
    }
    __shared__ float ps[8], pt[8];
    if ((d & 31) == 0) { ps[d >> 5] = s; pt[d >> 5] = t2; }
    __syncthreads();
    if (d < 4) {
        int b = (int)(row / NN);
        int i = (int)(row - (size_t)b * NN);
        src[row * 4 + d] = ps[2 * d] + ps[2 * d + 1];
        dstT[((size_t)b * 4 + d) * NN + i] = pt[2 * d] + pt[2 * d + 1];
    }
}

__global__ void k_rowstat(const float* __restrict__ src, const float* __restrict__ dstT,
                          const unsigned char* __restrict__ adj, float2* __restrict__ stat,
                          int NN)
{
    int i = blockIdx.x, b = blockIdx.y;
    int h = threadIdx.x >> 5, lane = threadIdx.x & 31;
    float s = src[((size_t)b * NN + i) * 4 + h];
    const uchar4* adjrow = (const uchar4*)(adj + ((size_t)b * NN + i) * NN);
    const float4* dsth = (const float4*)(dstT + ((size_t)b * 4 + h) * NN);
    int nq = NN >> 2;
    float mx = -1e30f;
    for (int jq = lane; jq < nq; jq += 32) {
        uchar4 a4 = adjrow[jq];
        float4 d4 = dsth[jq];
        float e0 = s + d4.x; e0 = e0 > 0.f ? e0 : 0.2f * e0; e0 = a4.x ? e0 : -1e9f;
        float e1 = s + d4.y; e1 = e1 > 0.f ? e1 : 0.2f * e1; e1 = a4.y ? e1 : -1e9f;
        float e2 = s + d4.z; e2 = e2 > 0.f ? e2 : 0.2f * e2; e2 = a4.z ? e2 : -1e9f;
        float e3 = s + d4.w; e3 = e3 > 0.f ? e3 : 0.2f * e3; e3 = a4.w ? e3 : -1e9f;
        mx = fmaxf(mx, fmaxf(fmaxf(e0, e1), fmaxf(e2, e3)));
    }
    #pragma unroll
    for (int o = 16; o; o >>= 1) mx = fmaxf(mx, __shfl_xor_sync(0xffffffff, mx, o));
    float sum = 0.f;
    for (int jq = lane; jq < nq; jq += 32) {
        uchar4 a4 = adjrow[jq];
        float4 d4 = dsth[jq];
        float e0 = s + d4.x; e0 = e0 > 0.f ? e0 : 0.2f * e0; e0 = a4.x ? e0 : -1e9f;
        float e1 = s + d4.y; e1 = e1 > 0.f ? e1 : 0.2f * e1; e1 = a4.y ? e1 : -1e9f;
        float e2 = s + d4.z; e2 = e2 > 0.f ? e2 : 0.2f * e2; e2 = a4.z ? e2 : -1e9f;
        float e3 = s + d4.w; e3 = e3 > 0.f ? e3 : 0.2f * e3; e3 = a4.w ? e3 : -1e9f;
        sum += __expf(e0 - mx) + __expf(e1 - mx) + __expf(e2 - mx) + __expf(e3 - mx);
    }
    #pragma unroll
    for (int o = 16; o; o >>= 1) sum += __shfl_xor_sync(0xffffffff, sum, o);
    if (lane == 0)
        stat[((size_t)b * 4 + h) * NN + i] = make_float2(mx, 1.f / sum);
}

__global__ void k_asso(const float* __restrict__ scores, float* __restrict__ out)
{
    size_t idx = (size_t)blockIdx.x * 256 + threadIdx.x;
    int j = idx & 511;
    size_t r = idx >> 9;
    int m = r & 511;
    int b = (int)(r >> 9);
    out[idx] = scores[(((size_t)b * 1024 + m) * 1024) + 512 + j];
}

// ---------------------------------------------------------------------------
// Host side
// ---------------------------------------------------------------------------
static void run_big(const float* A, int lda, long long sA,
                    const float* B, int ldb, long long sB,
                    float* C, int ldc, long long sC,
                    int M, int N, int K, int batch,
                    const float* bias, const float* aux, int auxld,
                    const unsigned char* adjp, long long sAdj,
                    int flags, bool transb)
{
    dim3 g(N / 128, M / 128, batch);
#define CALLBIG(T, F) tgemm_big<T, F><<<g, 256>>>(A, lda, sA, B, ldb, sB, \
        C, ldc, sC, K, bias, aux, auxld, adjp, sAdj)
    if (!transb) {
        if (flags == 0)           CALLBIG(false, 0);
        else if (flags == F_BIAS) CALLBIG(false, F_BIAS);
        else if (flags == F_RELU) CALLBIG(false, F_RELU);
        else                      CALLBIG(false, F_AUX);
    } else {
        if (flags == F_SIG)       CALLBIG(true, F_SIG);
        else                      CALLBIG(true, F_SIG | F_DIAG);
    }
#undef CALLBIG
}

#define SYM(p, s) cudaGetSymbolAddress((void**)&p, s)

extern "C" void kernel_launch(void* const* d_in, const int* in_sizes, int n_in,
                              void* d_out, int out_size)
{
    (void)in_sizes; (void)n_in; (void)out_size;
    const float* tracks = (const float*)d_in[0];
    const float* dets   = (const float*)d_in[1];
    const int* tmarks   = (const int*)d_in[2];
    const int* dmarks   = (const int*)d_in[3];
    const float* W1     = (const float*)d_in[4];
    const float* b1     = (const float*)d_in[5];
    const float* W2     = (const float*)d_in[6];
    const float* b2     = (const float*)d_in[7];
    const float* Wqkv   = (const float*)d_in[8];
    const float* Wo     = (const float*)d_in[9];
    const float* ff1    = (const float*)d_in[10];
    const float* ff2    = (const float*)d_in[11];
    const float* gatW   = (const float*)d_in[12];
    const float* gata   = (const float*)d_in[13];
    const float* dgatW  = (const float*)d_in[14];
    const float* dgata  = (const float*)d_in[15];
    const float* clsWq  = (const float*)d_in[16];
    const float* clsWk  = (const float*)d_in[17];

    float* out = (float*)d_out;
    float* out_scores = out;
    float* out_det    = out + (size_t)BB * NN1 * NN1;
    float* out_asso   = out_det + (size_t)BB * NNd * NNd;

    float *tr_h1, *tr_emb, *ln, *kv, *det_h1, *det_emb, *q0, *o0, *x1,
          *ln2, *ffh, *ffout, *feat0, *x, *h, *src, *dstT, *pos, *xq, *xk;
    float2* stat;
    unsigned char *adj, *adjd, *vm;
    SYM(tr_h1, g_tr_h1);   SYM(tr_emb, g_tr_emb); SYM(ln, g_ln);
    SYM(kv, g_kv);         SYM(det_h1, g_det_h1); SYM(det_emb, g_det_emb);
    SYM(q0, g_q0);         SYM(o0, g_o0);
    SYM(x1, g_x1);         SYM(ln2, g_ln2);       SYM(ffh, g_ffh);
    SYM(ffout, g_ffout);   SYM(feat0, g_feat0);   SYM(x, g_x);
    SYM(h, g_h);           SYM(src, g_src);       SYM(dstT, g_dstT);
    SYM(stat, g_stat);     SYM(adj, g_adj);
    SYM(adjd, g_adjd);     SYM(pos, g_pos);       SYM(vm, g_vm);
    SYM(xq, g_xq);         SYM(xk, g_xk);

    // ---- feature MLP ----
    k_feat1<<<TM, 256>>>(tracks, W1, b1, tr_h1);
    run_big(tr_h1, 256, 0, W2, 256, 0, tr_emb, 256, 0,
            TM, 256, 256, 1, b2, nullptr, 0, nullptr, 0, F_BIAS, false);
    k_feat1<<<ND, 256>>>(dets, W1, b1, det_h1);
    run_big(det_h1, 256, 0, W2, 256, 0, det_emb, 256, 0,
            ND, 256, 256, 1, b2, nullptr, 0, nullptr, 0, F_BIAS, false);

    // ---- encoder (only r=0 outputs needed downstream) ----
    k_ln<<<TM, 256>>>(tr_emb, ln);
    run_big(ln, 256, 0, Wqkv + 256, 768, 0, kv, 512, 0,
            TM, 512, 256, 1, nullptr, nullptr, 0, nullptr, 0, 0, false);
    run_big(ln, 2048, 0, Wqkv, 768, 0, q0, 256, 0,
            TT, 256, 256, 1, nullptr, nullptr, 0, nullptr, 0, 0, false);
    k_attn<<<TT, 256>>>(q0, kv, o0);
    run_big(o0, 256, 0, Wo, 256, 0, x1, 256, 0,
            TT, 256, 256, 1, nullptr, tr_emb, 2048, nullptr, 0, F_AUX, false);
    k_ln<<<TT, 256>>>(x1, ln2);
    run_big(ln2, 256, 0, ff1, 1024, 0, ffh, 1024, 0,
            TT, 1024, 256, 1, nullptr, nullptr, 0, nullptr, 0, F_RELU, false);
    run_big(ffh, 1024, 0, ff2, 256, 0, ffout, 256, 0,
            TT, 256, 1024, 1, nullptr, nullptr, 0, nullptr, 0, 0, false);
    k_feat0<<<ROWS1, 256>>>(tr_emb, x1, ffout, det_emb, feat0, x);

    // ---- adjacency ----
    k_posvm<<<64, 256>>>(tracks, dets, tmarks, dmarks, pos, vm);
    k_adj<<<dim3(NN1, BB), 256>>>(pos, vm, adj);
    k_adjd<<<dim3(NNd, BB), 128>>>(pos, vm, adjd);

    // ---- main GAT x2 ----
    for (int l = 0; l < 2; l++) {
        run_big(x, 256, 0, gatW + (size_t)l * 65536, 256, 0, h, 256, 0,
                ROWS1, 256, 256, 1, nullptr, nullptr, 0, nullptr, 0, 0, false);
        k_srcdst<<<ROWS1, 256>>>(h, gata + (size_t)l * 512, src, dstT, NN1);
        k_rowstat<<<dim3(NN1, BB), 128>>>(src, dstT, adj, stat, NN1);
        agg_fused<<<dim3(1, NN1 / 128, BB * HH), 256>>>(
            h, src, stat, dstT, adj, feat0, x, NN1);
    }

    // ---- main scores ----
    run_big(x, 256, 0, clsWq, 256, 0, xq, 256, 0,
            ROWS1, 256, 256, 1, nullptr, nullptr, 0, nullptr, 0, 0, false);
    run_big(x, 256, 0, clsWk, 256, 0, xk, 256, 0,
            ROWS1, 256, 256, 1, nullptr, nullptr, 0, nullptr, 0, 0, false);
    run_big(xq, 256, (long long)NN1 * 256, xk, 256, (long long)NN1 * 256,
            out_scores, NN1, (long long)NN1 * NN1,
            NN1, NN1, 256, BB, nullptr, nullptr, 0,
            adj, (long long)NN1 * NN1, F_SIG, true);
    k_asso<<<(int)(((size_t)BB * 512 * 512) / 256), 256>>>(out_scores, out_asso);

    // ---- detection GAT x2 ----
    for (int l = 0; l < 2; l++) {
        const float* xin = (l == 0) ? det_emb : x;
        run_big(xin, 256, 0, dgatW + (size_t)l * 65536, 256, 0, h, 256, 0,
                ND, 256, 256, 1, nullptr, nullptr, 0, nullptr, 0, 0, false);
        k_srcdst<<<ND, 256>>>(h, dgata + (size_t)l * 512, src, dstT, NNd);
        k_rowstat<<<dim3(NNd, BB), 128>>>(src, dstT, adjd, stat, NNd);
        agg_fused<<<dim3(1, NNd / 128, BB * HH), 256>>>(
            h, src, stat, dstT, adjd, det_emb, x, NNd);
    }

    // ---- detection scores ----
    run_big(x, 256, 0, clsWq + 65536, 256, 0, xq, 256, 0,
            ND, 256, 256, 1, nullptr, nullptr, 0, nullptr, 0, 0, false);
    run_big(x, 256, 0, clsWk + 65536, 256, 0, xk, 256, 0,
            ND, 256, 256, 1, nullptr, nullptr, 0, nullptr, 0, 0, false);
    run_big(xq, 256, (long long)NNd * 256, xk, 256, (long long)NNd * 256,
            out_det, NNd, (long long)NNd * NNd,
            NNd, NNd, 256, BB, nullptr, nullptr, 0,
            adjd, (long long)NNd * NNd, F_SIG | F_DIAG, true);
}

// round 9
// speedup vs baseline: 3.5410x; 1.0615x over previous
#include <cuda_runtime.h>
#include <cuda_fp16.h>
#include <math.h>
#include <stdint.h>

// ---------------------------------------------------------------------------
// Problem dims
// ---------------------------------------------------------------------------
#define BB 16
#define MM 512
#define NNd 512
#define RR 8
#define DD 256
#define HH 4
#define NN1 1024
#define TM  (BB*MM*RR)    // 65536
#define TT  (BB*MM)       // 8192
#define ND  (BB*NNd)      // 8192
#define ROWS1 (BB*NN1)    // 16384

#define F_BIAS 1
#define F_RELU 2
#define F_AUX  4
#define F_SIG  8
#define F_DIAG 16

// ---------------------------------------------------------------------------
// Scratch
// ---------------------------------------------------------------------------
__device__ float g_h1[(TM+ND)*DD];       // combined tr+det hidden
__device__ float g_emb[(TM+ND)*DD];      // combined tr_emb | det_emb
__device__ float g_ln[TM*DD];
__device__ float g_kv[TM*512];
__device__ float g_q0[TT*DD];
__device__ float g_o0[TT*DD];
__device__ float g_x1[TT*DD];
__device__ float g_ln2[TT*DD];
__device__ float g_ffh[TT*1024];
__device__ float g_ffout[TT*DD];
__device__ float g_feat0[ROWS1*DD];
__device__ float g_x[ROWS1*DD];
__device__ float g_h[ROWS1*DD];
__device__ float g_src[ROWS1*HH];
__device__ float g_dstT[BB*HH*NN1];
__device__ float2 g_stat[BB*HH*NN1];
__device__ unsigned char g_adj[(size_t)BB*NN1*NN1];
__device__ unsigned char g_adjd[(size_t)BB*NNd*NNd];
__device__ float g_pos[BB*NN1*2];
__device__ unsigned char g_vm[BB*NN1];
__device__ float g_xq[ROWS1*DD];
__device__ float g_xk[ROWS1*DD];

// ---------------------------------------------------------------------------
// fp16 / ldmatrix helpers
// ---------------------------------------------------------------------------
__device__ __forceinline__ uint32_t pk(float lo, float hi) {
    __half2 v = __floats2half2_rn(lo, hi);
    return *reinterpret_cast<uint32_t*>(&v);
}
__device__ __forceinline__ void mma_f16(float* c, const uint32_t* a, const uint32_t* b) {
    asm volatile(
        "mma.sync.aligned.m16n8k16.row.col.f32.f16.f16.f32 "
        "{%0,%1,%2,%3}, {%4,%5,%6,%7}, {%8,%9}, {%0,%1,%2,%3};\n"
        : "+f"(c[0]), "+f"(c[1]), "+f"(c[2]), "+f"(c[3])
        : "r"(a[0]), "r"(a[1]), "r"(a[2]), "r"(a[3]), "r"(b[0]), "r"(b[1]));
}
__device__ __forceinline__ void ldm_x4(uint32_t* r, uint32_t addr) {
    asm volatile("ldmatrix.sync.aligned.m8n8.x4.shared.b16 {%0,%1,%2,%3}, [%4];"
        : "=r"(r[0]), "=r"(r[1]), "=r"(r[2]), "=r"(r[3]) : "r"(addr));
}
__device__ __forceinline__ void ldm_x4_t(uint32_t* r, uint32_t addr) {
    asm volatile("ldmatrix.sync.aligned.m8n8.x4.trans.shared.b16 {%0,%1,%2,%3}, [%4];"
        : "=r"(r[0]), "=r"(r[1]), "=r"(r[2]), "=r"(r[3]) : "r"(addr));
}
__device__ __forceinline__ uint32_t cvs(const void* p) {
    return (uint32_t)__cvta_generic_to_shared(p);
}

// ---------------------------------------------------------------------------
// BIG GEMM (fp16 m16n8k16 + ldmatrix): CTA 128x128, BK=16, 256 thr,
// warp tile 64x32, double-buffered.
// A smem: packed k-pair words [row][kp] stride 12 (= half [row][k] rs 24).
// B TRANSB: same layout as A. B normal: half [k][n], row stride 136 halves.
// ---------------------------------------------------------------------------
template<bool TRANSB, int FLAGS>
__global__ __launch_bounds__(256, 2)
void tgemm_big(const float* __restrict__ A, int lda, long long sA,
               const float* __restrict__ B, int ldb, long long sB,
               float* __restrict__ C, int ldc, long long sC,
               int K,
               const float* __restrict__ bias,
               const float* __restrict__ aux, int auxld,
               const unsigned char* __restrict__ adjp, long long sAdj,
               const float* __restrict__ B2, float* __restrict__ C2, int dual)
{
    int bz = blockIdx.z;
    if (dual && bz) { B = B2; C = C2; bz = 0; }
    A += (long long)bz * sA;
    B += (long long)bz * sB;
    C += (long long)bz * sC;
    if (FLAGS & F_SIG) adjp += (long long)bz * sAdj;

    int m0 = blockIdx.y * 128, n0 = blockIdx.x * 128;

    __shared__ uint32_t As[2][1536];   // 128*12
    __shared__ uint32_t Bs[2][1536];   // trans: 128*12; normal: 16*68=1088

    int tid = threadIdx.x;
    int arow = tid >> 1, ahalf = tid & 1;
    const float* gA = A + (size_t)(m0 + arow) * lda + ahalf * 8;

    const float* gB;
    if (!TRANSB) {
        int kp = tid >> 5, nq = tid & 31;
        gB = B + (size_t)(2 * kp) * ldb + n0 + nq * 4;
    } else {
        gB = B + (size_t)(n0 + arow) * ldb + ahalf * 8;
    }
    int kp = tid >> 5, nq = tid & 31;

    int w = tid >> 5, l = tid & 31;
    int mbase = (w >> 2) * 64, nbase = (w & 3) * 32;
    int grp = l >> 2, tig = l & 3;

    // ldmatrix lane addressing
    int lrowA = ((l >> 3) & 1) * 8 + (l & 7);
    int khalf = l >> 4;
    uint32_t aBase[4];
    #pragma unroll
    for (int fm = 0; fm < 4; fm++)
        aBase[fm] = cvs(&As[0][(mbase + fm * 16 + lrowA) * 12 + khalf * 4]);
    uint32_t bBase[2];
    if (!TRANSB) {
        int krow = ((l >> 4) & 1) * 8 + (l & 7);
        int nblk = ((l >> 3) & 1) * 8;
        #pragma unroll
        for (int fp = 0; fp < 2; fp++)
            bBase[fp] = cvs(&Bs[0][krow * 68 + ((nbase + fp * 16 + nblk) >> 1)]);
    } else {
        #pragma unroll
        for (int fp = 0; fp < 2; fp++)
            bBase[fp] = cvs(&Bs[0][(nbase + fp * 16 + lrowA) * 12 + khalf * 4]);
    }

    float acc[4][4][4];
    #pragma unroll
    for (int i = 0; i < 4; i++)
        #pragma unroll
        for (int j = 0; j < 4; j++)
            #pragma unroll
            for (int q = 0; q < 4; q++) acc[i][j][q] = 0.f;

    int nk = K >> 4;
    float4 va0, va1, vb0, vb1;

    // load + store stage 0
    va0 = *(const float4*)(gA);
    va1 = *(const float4*)(gA + 4);
    if (!TRANSB) { vb0 = *(const float4*)(gB); vb1 = *(const float4*)(gB + ldb); }
    else         { vb0 = *(const float4*)(gB); vb1 = *(const float4*)(gB + 4); }
    {
        uint32_t* ap = &As[0][arow * 12 + ahalf * 4];
        ap[0] = pk(va0.x, va0.y); ap[1] = pk(va0.z, va0.w);
        ap[2] = pk(va1.x, va1.y); ap[3] = pk(va1.z, va1.w);
        if (!TRANSB) {
            uint32_t* bh = &Bs[0][0];
            int w0 = (2 * kp) * 68 + nq * 2;
            bh[w0]      = pk(vb0.x, vb0.y);
            bh[w0 + 1]  = pk(vb0.z, vb0.w);
            bh[w0 + 68] = pk(vb1.x, vb1.y);
            bh[w0 + 69] = pk(vb1.z, vb1.w);
        } else {
            uint32_t* bp = &Bs[0][arow * 12 + ahalf * 4];
            bp[0] = pk(vb0.x, vb0.y); bp[1] = pk(vb0.z, vb0.w);
            bp[2] = pk(vb1.x, vb1.y); bp[3] = pk(vb1.z, vb1.w);
        }
    }
    if (nk > 1) {
        va0 = *(const float4*)(gA + 16);
        va1 = *(const float4*)(gA + 20);
        if (!TRANSB) { vb0 = *(const float4*)(gB + (size_t)16 * ldb); vb1 = *(const float4*)(gB + (size_t)17 * ldb); }
        else         { vb0 = *(const float4*)(gB + 16); vb1 = *(const float4*)(gB + 20); }
    }

    int s = 0;
    for (int i = 0; i < nk; i++) {
        __syncthreads();
        if (i + 1 < nk) {
            int d = s ^ 1;
            uint32_t* ap = &As[d][arow * 12 + ahalf * 4];
            ap[0] = pk(va0.x, va0.y); ap[1] = pk(va0.z, va0.w);
            ap[2] = pk(va1.x, va1.y); ap[3] = pk(va1.z, va1.w);
            if (!TRANSB) {
                uint32_t* bh = &Bs[d][0];
                int w0 = (2 * kp) * 68 + nq * 2;
                bh[w0]      = pk(vb0.x, vb0.y);
                bh[w0 + 1]  = pk(vb0.z, vb0.w);
                bh[w0 + 68] = pk(vb1.x, vb1.y);
                bh[w0 + 69] = pk(vb1.z, vb1.w);
            } else {
                uint32_t* bp = &Bs[d][arow * 12 + ahalf * 4];
                bp[0] = pk(vb0.x, vb0.y); bp[1] = pk(vb0.z, vb0.w);
                bp[2] = pk(vb1.x, vb1.y); bp[3] = pk(vb1.z, vb1.w);
            }
            if (i + 2 < nk) {
                int k0 = (i + 2) * 16;
                va0 = *(const float4*)(gA + k0);
                va1 = *(const float4*)(gA + k0 + 4);
                if (!TRANSB) {
                    vb0 = *(const float4*)(gB + (size_t)k0 * ldb);
                    vb1 = *(const float4*)(gB + (size_t)(k0 + 1) * ldb);
                } else {
                    vb0 = *(const float4*)(gB + k0);
                    vb1 = *(const float4*)(gB + k0 + 4);
                }
            }
        }
        uint32_t soff = (uint32_t)(s * 6144);
        uint32_t af[4][4];
        #pragma unroll
        for (int fm = 0; fm < 4; fm++) ldm_x4(af[fm], aBase[fm] + soff);
        uint32_t bfr[4][2];
        #pragma unroll
        for (int fp = 0; fp < 2; fp++) {
            uint32_t t4[4];
            if (!TRANSB) ldm_x4_t(t4, bBase[fp] + soff);
            else         ldm_x4(t4, bBase[fp] + soff);
            bfr[fp * 2][0] = t4[0]; bfr[fp * 2 + 1][0] = t4[1];
            bfr[fp * 2][1] = t4[2]; bfr[fp * 2 + 1][1] = t4[3];
        }
        #pragma unroll
        for (int fm = 0; fm < 4; fm++)
            #pragma unroll
            for (int fn = 0; fn < 4; fn++)
                mma_f16(acc[fm][fn], af[fm], bfr[fn]);
        s ^= 1;
    }

    // epilogue
    #pragma unroll
    for (int fm = 0; fm < 4; fm++) {
        int row0 = m0 + mbase + fm * 16 + grp;
        #pragma unroll
        for (int fn = 0; fn < 4; fn++) {
            int col = n0 + nbase + fn * 8 + 2 * tig;
            float v0 = acc[fm][fn][0], v1 = acc[fm][fn][1];
            float v2 = acc[fm][fn][2], v3 = acc[fm][fn][3];
            if (FLAGS & F_BIAS) {
                float bb0 = bias[col], bb1 = bias[col + 1];
                v0 += bb0; v1 += bb1; v2 += bb0; v3 += bb1;
            }
            if (FLAGS & F_RELU) {
                v0 = fmaxf(v0, 0.f); v1 = fmaxf(v1, 0.f);
                v2 = fmaxf(v2, 0.f); v3 = fmaxf(v3, 0.f);
            }
            if (FLAGS & F_AUX) {
                const float* ar = aux + (size_t)row0 * auxld + col;
                const float* ar8 = aux + (size_t)(row0 + 8) * auxld + col;
                v0 += ar[0]; v1 += ar[1]; v2 += ar8[0]; v3 += ar8[1];
            }
            if (FLAGS & F_SIG) {
                const unsigned char* q0p = adjp + (size_t)row0 * ldc + col;
                const unsigned char* q8p = adjp + (size_t)(row0 + 8) * ldc + col;
                v0 = q0p[0] ? 1.f / (1.f + __expf(-v0 * 0.0625f)) : 0.f;
                v1 = q0p[1] ? 1.f / (1.f + __expf(-v1 * 0.0625f)) : 0.f;
                v2 = q8p[0] ? 1.f / (1.f + __expf(-v2 * 0.0625f)) : 0.f;
                v3 = q8p[1] ? 1.f / (1.f + __expf(-v3 * 0.0625f)) : 0.f;
                if (FLAGS & F_DIAG) {
                    if (row0 == col) v0 = 0.f;
                    if (row0 == col + 1) v1 = 0.f;
                    if (row0 + 8 == col) v2 = 0.f;
                    if (row0 + 8 == col + 1) v3 = 0.f;
                }
            }
            *(float2*)&C[(size_t)row0 * ldc + col] = make_float2(v0, v1);
            *(float2*)&C[(size_t)(row0 + 8) * ldc + col] = make_float2(v2, v3);
        }
    }
}

// ---------------------------------------------------------------------------
// Fused GAT aggregation (fp16 + ldmatrix): x = 0.5*elu(alpha@h) + 0.5*aux.
// CTA 128x64, warp 32x32. A packed pairs [row][kp] stride 12;
// B half [k][n] row stride 72 halves (36 words). grid (1, NN/128, BB*HH).
// ---------------------------------------------------------------------------
__global__ __launch_bounds__(256)
void agg_fused(const float* __restrict__ hmat, const float* __restrict__ src,
               const float2* __restrict__ stat, const float* __restrict__ dstT,
               const unsigned char* __restrict__ adj,
               const float* __restrict__ aux, float* __restrict__ xout, int NN)
{
    int z = blockIdx.z;
    int b = z >> 2, h = z & 3;
    const float* B = hmat + (size_t)b * NN * 256 + h * 64;
    float* C = xout + (size_t)b * NN * 256 + h * 64;
    const float* auxp = aux + (size_t)b * NN * 256 + h * 64;

    int m0 = blockIdx.y * 128;
    __shared__ uint32_t As[128 * 12];
    __shared__ uint32_t Bs[16 * 36];
    int tid = threadIdx.x;

    int rowA = tid >> 2;
    int jc = (tid & 3) * 4;
    int pb = (tid & 3) * 2;
    int r0 = m0 + rowA;
    int r1 = r0 + 64;
    size_t gi0 = (size_t)b * NN + r0;
    size_t gi1 = (size_t)b * NN + r1;
    float s0v = src[gi0 * 4 + h];
    float s1v = src[gi1 * 4 + h];
    float2 st0 = stat[((size_t)b * 4 + h) * NN + r0];
    float2 st1 = stat[((size_t)b * 4 + h) * NN + r1];
    const unsigned char* adj0 = adj + gi0 * NN;
    const unsigned char* adj1 = adj + gi1 * NN;
    const float* dsth = dstT + ((size_t)b * 4 + h) * NN;

    int kp = tid >> 5, nq = tid & 31;
    const float* gB = B + (size_t)(2 * kp) * 256 + 2 * nq;

    int w = tid >> 5, l = tid & 31;
    int wm = w >> 1, wn = w & 1;
    int mrow = wm * 32, ncol = wn * 32;
    int grp = l >> 2, tig = l & 3;

    int lrowA = ((l >> 3) & 1) * 8 + (l & 7);
    int khalf = l >> 4;
    uint32_t aBase[2];
    #pragma unroll
    for (int fm = 0; fm < 2; fm++)
        aBase[fm] = cvs(&As[(mrow + fm * 16 + lrowA) * 12 + khalf * 4]);
    int krow = ((l >> 4) & 1) * 8 + (l & 7);
    int nblk = ((l >> 3) & 1) * 8;
    uint32_t bBase[2];
    #pragma unroll
    for (int fp = 0; fp < 2; fp++)
        bBase[fp] = cvs(&Bs[krow * 36 + ((ncol + fp * 16 + nblk) >> 1)]);

    float acc[2][4][4];
    #pragma unroll
    for (int i = 0; i < 2; i++)
        #pragma unroll
        for (int j = 0; j < 4; j++)
            #pragma unroll
            for (int q = 0; q < 4; q++) acc[i][j][q] = 0.f;

    for (int k0 = 0; k0 < NN; k0 += 16) {
        int j0 = k0 + jc;
        uchar4 a40 = *(const uchar4*)(adj0 + j0);
        uchar4 a41 = *(const uchar4*)(adj1 + j0);
        float4 d4 = *(const float4*)(dsth + j0);
        const unsigned char* ap0 = &a40.x;
        const unsigned char* ap1 = &a41.x;
        const float* dp = &d4.x;
        float al0[4], al1[4];
        #pragma unroll
        for (int u = 0; u < 4; u++) {
            float e0 = s0v + dp[u]; e0 = e0 > 0.f ? e0 : 0.2f * e0;
            float e1 = s1v + dp[u]; e1 = e1 > 0.f ? e1 : 0.2f * e1;
            e0 = ap0[u] ? e0 : -1e9f;
            e1 = ap1[u] ? e1 : -1e9f;
            al0[u] = __expf(e0 - st0.x) * st0.y;
            al1[u] = __expf(e1 - st1.x) * st1.y;
        }
        As[rowA * 12 + pb]            = pk(al0[0], al0[1]);
        As[rowA * 12 + pb + 1]        = pk(al0[2], al0[3]);
        As[(rowA + 64) * 12 + pb]     = pk(al1[0], al1[1]);
        As[(rowA + 64) * 12 + pb + 1] = pk(al1[2], al1[3]);
        {
            const float* bp0 = gB + (size_t)k0 * 256;
            float2 rb0 = *(const float2*)(bp0);
            float2 rb1 = *(const float2*)(bp0 + 256);
            Bs[(2 * kp) * 36 + nq]     = pk(rb0.x, rb0.y);
            Bs[(2 * kp + 1) * 36 + nq] = pk(rb1.x, rb1.y);
        }
        __syncthreads();
        uint32_t af[2][4];
        #pragma unroll
        for (int fm = 0; fm < 2; fm++) ldm_x4(af[fm], aBase[fm]);
        uint32_t bfr[4][2];
        #pragma unroll
        for (int fp = 0; fp < 2; fp++) {
            uint32_t t4[4];
            ldm_x4_t(t4, bBase[fp]);
            bfr[fp * 2][0] = t4[0]; bfr[fp * 2 + 1][0] = t4[1];
            bfr[fp * 2][1] = t4[2]; bfr[fp * 2 + 1][1] = t4[3];
        }
        #pragma unroll
        for (int fm = 0; fm < 2; fm++)
            #pragma unroll
            for (int fn = 0; fn < 4; fn++)
                mma_f16(acc[fm][fn], af[fm], bfr[fn]);
        __syncthreads();
    }

    #pragma unroll
    for (int fm = 0; fm < 2; fm++) {
        int row = m0 + mrow + fm * 16 + grp;
        #pragma unroll
        for (int fn = 0; fn < 4; fn++) {
            int col = ncol + fn * 8 + 2 * tig;
            float v0 = acc[fm][fn][0], v1 = acc[fm][fn][1];
            float v2 = acc[fm][fn][2], v3 = acc[fm][fn][3];
            v0 = (v0 > 0.f) ? v0 : expm1f(v0);
            v1 = (v1 > 0.f) ? v1 : expm1f(v1);
            v2 = (v2 > 0.f) ? v2 : expm1f(v2);
            v3 = (v3 > 0.f) ? v3 : expm1f(v3);
            float2 x0 = *(const float2*)&auxp[(size_t)row * 256 + col];
            float2 x1 = *(const float2*)&auxp[(size_t)(row + 8) * 256 + col];
            *(float2*)&C[(size_t)row * 256 + col] =
                make_float2(0.5f * v0 + 0.5f * x0.x, 0.5f * v1 + 0.5f * x0.y);
            *(float2*)&C[(size_t)(row + 8) * 256 + col] =
                make_float2(0.5f * v2 + 0.5f * x1.x, 0.5f * v3 + 0.5f * x1.y);
        }
    }
}

// ---------------------------------------------------------------------------
// Small kernels
// ---------------------------------------------------------------------------
__global__ void k_feat1(const float* __restrict__ x, const float* __restrict__ W1,
                        const float* __restrict__ b1, float* __restrict__ out)
{
    size_t idx = (size_t)blockIdx.x * 256 + threadIdx.x;
    size_t row = idx >> 8;
    int d = idx & 255;
    const float* xr = x + row * 4;
    float v = b1[d] + xr[0]*W1[d] + xr[1]*W1[256+d] + xr[2]*W1[512+d] + xr[3]*W1[768+d];
    out[idx] = (v > 0.f) ? v : expm1f(v);
}

__global__ void k_ln(const float* __restrict__ in, float* __restrict__ out)
{
    size_t row = blockIdx.x;
    int t = threadIdx.x;
    float v = in[row * 256 + t];
    float a = v, b = v * v;
    #pragma unroll
    for (int o = 16; o; o >>= 1) {
        a += __shfl_xor_sync(0xffffffff, a, o);
        b += __shfl_xor_sync(0xffffffff, b, o);
    }
    __shared__ float sa[8], sb[8];
    if ((t & 31) == 0) { sa[t >> 5] = a; sb[t >> 5] = b; }
    __syncthreads();
    if (t < 32) {
        a = (t < 8) ? sa[t] : 0.f;
        b = (t < 8) ? sb[t] : 0.f;
        #pragma unroll
        for (int o = 4; o; o >>= 1) {
            a += __shfl_xor_sync(0xffffffff, a, o);
            b += __shfl_xor_sync(0xffffffff, b, o);
        }
        if (t == 0) { sa[0] = a; sb[0] = b; }
    }
    __syncthreads();
    float mean = sa[0] * (1.f / 256.f);
    float var = sb[0] * (1.f / 256.f) - mean * mean;
    out[row * 256 + t] = (v - mean) * rsqrtf(var + 1e-5f);
}

__global__ void k_attn(const float* __restrict__ q0, const float* __restrict__ kv,
                       float* __restrict__ o0)
{
    size_t t = blockIdx.x;
    int d = threadIdx.x;
    int h = d >> 6;
    __shared__ float logits[4][8];
    __shared__ float red[8];
    float qd = q0[t * 256 + d];
    for (int s = 0; s < 8; s++) {
        float p = qd * kv[(t * 8 + s) * 512 + d];
        #pragma unroll
        for (int o = 16; o; o >>= 1) p += __shfl_xor_sync(0xffffffff, p, o);
        if ((d & 31) == 0) red[d >> 5] = p;
        __syncthreads();
        if (d < 4) logits[d][s] = (red[2 * d] + red[2 * d + 1]) * 0.125f;
        __syncthreads();
    }
    float m = -1e30f;
    #pragma unroll
    for (int s = 0; s < 8; s++) m = fmaxf(m, logits[h][s]);
    float w[8], sum = 0.f;
    #pragma unroll
    for (int s = 0; s < 8; s++) { w[s] = __expf(logits[h][s] - m); sum += w[s]; }
    float inv = 1.f / sum;
    float o = 0.f;
    #pragma unroll
    for (int s = 0; s < 8; s++) o += w[s] * inv * kv[(t * 8 + s) * 512 + 256 + d];
    o0[t * 256 + d] = o;
}

__global__ void k_feat0(const float* __restrict__ tr_emb, const float* __restrict__ x1,
                        const float* __restrict__ ffout, const float* __restrict__ det_emb,
                        float* __restrict__ feat0, float* __restrict__ x)
{
    size_t idx = (size_t)blockIdx.x * 256 + threadIdx.x;
    int d = idx & 255;
    size_t row = idx >> 8;
    int i = row & 1023;
    int b = row >> 10;
    float v;
    if (i < 512) {
        size_t t = (size_t)b * 512 + i;
        v = tr_emb[t * 2048 + d] + 0.9f * (x1[t * 256 + d] + ffout[t * 256 + d]);
    } else {
        size_t t = (size_t)b * 512 + (i - 512);
        v = det_emb[t * 256 + d];
    }
    feat0[idx] = v;
    x[idx] = v;
}

__global__ void k_posvm(const float* __restrict__ tracks, const float* __restrict__ dets,
                        const int* __restrict__ tmarks, const int* __restrict__ dmarks,
                        float* __restrict__ pos, unsigned char* __restrict__ vm)
{
    int idx = blockIdx.x * 256 + threadIdx.x;
    if (idx >= BB * NN1) return;
    int b = idx >> 10, i = idx & 1023;
    float x, y; unsigned char v;
    if (i < 512) {
        const float* p = tracks + ((size_t)(b * 512 + i)) * 8 * 4;
        x = p[0]; y = p[1];
        v = (i < tmarks[b]);
    } else {
        int n = i - 512;
        const float* p = dets + ((size_t)(b * 512 + n)) * 4;
        x = p[0]; y = p[1];
        v = (n < dmarks[b]);
    }
    pos[idx * 2] = x; pos[idx * 2 + 1] = y; vm[idx] = v;
}

__global__ void k_adj(const float* __restrict__ pos, const unsigned char* __restrict__ vm,
                      unsigned char* __restrict__ adj)
{
    int i = blockIdx.x, b = blockIdx.y;
    size_t base = (size_t)b * NN1;
    const float2* p2 = (const float2*)pos;
    float2 pi = p2[base + i];
    unsigned char vi = vm[base + i];
    int j0 = threadIdx.x * 4;
    uchar4 r;
    unsigned char* rp = &r.x;
    #pragma unroll
    for (int u = 0; u < 4; u++) {
        int j = j0 + u;
        float2 pj = p2[base + j];
        float dx = pi.x - pj.x, dy = pi.y - pj.y;
        rp[u] = (unsigned char)((dx * dx + dy * dy < 4.0f) && vi && vm[base + j]);
    }
    ((uchar4*)(adj + ((size_t)b * NN1 + i) * NN1))[threadIdx.x] = r;
}

__global__ void k_adjd(const float* __restrict__ pos, const unsigned char* __restrict__ vm,
                       unsigned char* __restrict__ adjd)
{
    int i = blockIdx.x, b = blockIdx.y;
    size_t base = (size_t)b * NN1 + 512;
    const float2* p2 = (const float2*)pos;
    float2 pi = p2[base + i];
    unsigned char vi = vm[base + i];
    int j0 = threadIdx.x * 4;
    uchar4 r;
    unsigned char* rp = &r.x;
    #pragma unroll
    for (int u = 0; u < 4; u++) {
        int j = j0 + u;
        float2 pj = p2[base + j];
        float dx = pi.x - pj.x, dy = pi.y - pj.y;
        rp[u] = (unsigned char)((dx * dx + dy * dy < 4.0f) && vi && vm[base + j]);
    }
    ((uchar4*)(adjd + ((size_t)b * NNd + i) * NNd))[threadIdx.x] = r;
}

__global__ void k_srcdst(const float* __restrict__ Hm, const float* __restrict__ a0,
                         float* __restrict__ src, float* __restrict__ dstT, int NN)
{
    size_t row = blockIdx.x;
    int d = threadIdx.x;
    float hv = Hm[row * 256 + d];
    float s = hv * a0[d];
    float t2 = hv * a0[256 + d];
    #pragma unroll
    for (int o = 16; o; o >>= 1) {
        s  += __shfl_xor_sync(0xffffffff, s, o);
        t2 += __shfl_xor_sync(0xffffffff, t2, o);
    }
    __shared__ float ps[8], pt[8];
    if ((d & 31) == 0) { ps[d >> 5] = s; pt[d >> 5] = t2; }
    __syncthreads();
    if (d < 4) {
        int b = (int)(row / NN);
        int i = (int)(row - (size_t)b * NN);
        src[row * 4 + d] = ps[2 * d] + ps[2 * d + 1];
        dstT[((size_t)b * 4 + d) * NN + i] = pt[2 * d] + pt[2 * d + 1];
    }
}

__global__ void k_rowstat(const float* __restrict__ src, const float* __restrict__ dstT,
                          const unsigned char* __restrict__ adj, float2* __restrict__ stat,
                          int NN)
{
    int i = blockIdx.x, b = blockIdx.y;
    int h = threadIdx.x >> 5, lane = threadIdx.x & 31;
    float s = src[((size_t)b * NN + i) * 4 + h];
    const uchar4* adjrow = (const uchar4*)(adj + ((size_t)b * NN + i) * NN);
    const float4* dsth = (const float4*)(dstT + ((size_t)b * 4 + h) * NN);
    int nq = NN >> 2;
    float mx = -1e30f;
    for (int jq = lane; jq < nq; jq += 32) {
        uchar4 a4 = adjrow[jq];
        float4 d4 = dsth[jq];
        float e0 = s + d4.x; e0 = e0 > 0.f ? e0 : 0.2f * e0; e0 = a4.x ? e0 : -1e9f;
        float e1 = s + d4.y; e1 = e1 > 0.f ? e1 : 0.2f * e1; e1 = a4.y ? e1 : -1e9f;
        float e2 = s + d4.z; e2 = e2 > 0.f ? e2 : 0.2f * e2; e2 = a4.z ? e2 : -1e9f;
        float e3 = s + d4.w; e3 = e3 > 0.f ? e3 : 0.2f * e3; e3 = a4.w ? e3 : -1e9f;
        mx = fmaxf(mx, fmaxf(fmaxf(e0, e1), fmaxf(e2, e3)));
    }
    #pragma unroll
    for (int o = 16; o; o >>= 1) mx = fmaxf(mx, __shfl_xor_sync(0xffffffff, mx, o));
    float sum = 0.f;
    for (int jq = lane; jq < nq; jq += 32) {
        uchar4 a4 = adjrow[jq];
        float4 d4 = dsth[jq];
        float e0 = s + d4.x; e0 = e0 > 0.f ? e0 : 0.2f * e0; e0 = a4.x ? e0 : -1e9f;
        float e1 = s + d4.y; e1 = e1 > 0.f ? e1 : 0.2f * e1; e1 = a4.y ? e1 : -1e9f;
        float e2 = s + d4.z; e2 = e2 > 0.f ? e2 : 0.2f * e2; e2 = a4.z ? e2 : -1e9f;
        float e3 = s + d4.w; e3 = e3 > 0.f ? e3 : 0.2f * e3; e3 = a4.w ? e3 : -1e9f;
        sum += __expf(e0 - mx) + __expf(e1 - mx) + __expf(e2 - mx) + __expf(e3 - mx);
    }
    #pragma unroll
    for (int o = 16; o; o >>= 1) sum += __shfl_xor_sync(0xffffffff, sum, o);
    if (lane == 0)
        stat[((size_t)b * 4 + h) * NN + i] = make_float2(mx, 1.f / sum);
}

__global__ void k_asso(const float* __restrict__ scores, float* __restrict__ out)
{
    size_t idx = (size_t)blockIdx.x * 256 + threadIdx.x;
    int j = idx & 511;
    size_t r = idx >> 9;
    int m = r & 511;
    int b = (int)(r >> 9);
    out[idx] = scores[(((size_t)b * 1024 + m) * 1024) + 512 + j];
}

// ---------------------------------------------------------------------------
// Host side
// ---------------------------------------------------------------------------
static void run_big(const float* A, int lda, long long sA,
                    const float* B, int ldb, long long sB,
                    float* C, int ldc, long long sC,
                    int M, int N, int K, int batch,
                    const float* bias, const float* aux, int auxld,
                    const unsigned char* adjp, long long sAdj,
                    int flags, bool transb,
                    const float* B2 = nullptr, float* C2 = nullptr, int dual = 0)
{
    dim3 g(N / 128, M / 128, batch);
#define CALLBIG(T, F) tgemm_big<T, F><<<g, 256>>>(A, lda, sA, B, ldb, sB, \
        C, ldc, sC, K, bias, aux, auxld, adjp, sAdj, B2, C2, dual)
    if (!transb) {
        if (flags == 0)           CALLBIG(false, 0);
        else if (flags == F_BIAS) CALLBIG(false, F_BIAS);
        else if (flags == F_RELU) CALLBIG(false, F_RELU);
        else                      CALLBIG(false, F_AUX);
    } else {
        if (flags == F_SIG)       CALLBIG(true, F_SIG);
        else                      CALLBIG(true, F_SIG | F_DIAG);
    }
#undef CALLBIG
}

#define SYM(p, s) cudaGetSymbolAddress((void**)&p, s)

extern "C" void kernel_launch(void* const* d_in, const int* in_sizes, int n_in,
                              void* d_out, int out_size)
{
    (void)in_sizes; (void)n_in; (void)out_size;
    const float* tracks = (const float*)d_in[0];
    const float* dets   = (const float*)d_in[1];
    const int* tmarks   = (const int*)d_in[2];
    const int* dmarks   = (const int*)d_in[3];
    const float* W1     = (const float*)d_in[4];
    const float* b1     = (const float*)d_in[5];
    const float* W2     = (const float*)d_in[6];
    const float* b2     = (const float*)d_in[7];
    const float* Wqkv   = (const float*)d_in[8];
    const float* Wo     = (const float*)d_in[9];
    const float* ff1    = (const float*)d_in[10];
    const float* ff2    = (const float*)d_in[11];
    const float* gatW   = (const float*)d_in[12];
    const float* gata   = (const float*)d_in[13];
    const float* dgatW  = (const float*)d_in[14];
    const float* dgata  = (const float*)d_in[15];
    const float* clsWq  = (const float*)d_in[16];
    const float* clsWk  = (const float*)d_in[17];

    float* out = (float*)d_out;
    float* out_scores = out;
    float* out_det    = out + (size_t)BB * NN1 * NN1;
    float* out_asso   = out_det + (size_t)BB * NNd * NNd;

    float *h1, *emb, *ln, *kv, *q0, *o0, *x1,
          *ln2, *ffh, *ffout, *feat0, *x, *h, *src, *dstT, *pos, *xq, *xk;
    float2* stat;
    unsigned char *adj, *adjd, *vm;
    SYM(h1, g_h1);         SYM(emb, g_emb);       SYM(ln, g_ln);
    SYM(kv, g_kv);
    SYM(q0, g_q0);         SYM(o0, g_o0);
    SYM(x1, g_x1);         SYM(ln2, g_ln2);       SYM(ffh, g_ffh);
    SYM(ffout, g_ffout);   SYM(feat0, g_feat0);   SYM(x, g_x);
    SYM(h, g_h);           SYM(src, g_src);       SYM(dstT, g_dstT);
    SYM(stat, g_stat);     SYM(adj, g_adj);
    SYM(adjd, g_adjd);     SYM(pos, g_pos);       SYM(vm, g_vm);
    SYM(xq, g_xq);         SYM(xk, g_xk);

    float* tr_emb = emb;
    float* det_emb = emb + (size_t)TM * DD;

    // ---- feature MLP (tr + det combined into one big GEMM) ----
    k_feat1<<<TM, 256>>>(tracks, W1, b1, h1);
    k_feat1<<<ND, 256>>>(dets, W1, b1, h1 + (size_t)TM * DD);
    run_big(h1, 256, 0, W2, 256, 0, emb, 256, 0,
            TM + ND, 256, 256, 1, b2, nullptr, 0, nullptr, 0, F_BIAS, false);

    // ---- encoder (only r=0 outputs needed downstream) ----
    k_ln<<<TM, 256>>>(tr_emb, ln);
    run_big(ln, 256, 0, Wqkv + 256, 768, 0, kv, 512, 0,
            TM, 512, 256, 1, nullptr, nullptr, 0, nullptr, 0, 0, false);
    run_big(ln, 2048, 0, Wqkv, 768, 0, q0, 256, 0,
            TT, 256, 256, 1, nullptr, nullptr, 0, nullptr, 0, 0, false);
    k_attn<<<TT, 256>>>(q0, kv, o0);
    run_big(o0, 256, 0, Wo, 256, 0, x1, 256, 0,
            TT, 256, 256, 1, nullptr, tr_emb, 2048, nullptr, 0, F_AUX, false);
    k_ln<<<TT, 256>>>(x1, ln2);
    run_big(ln2, 256, 0, ff1, 1024, 0, ffh, 1024, 0,
            TT, 1024, 256, 1, nullptr, nullptr, 0, nullptr, 0, F_RELU, false);
    run_big(ffh, 1024, 0, ff2, 256, 0, ffout, 256, 0,
            TT, 256, 1024, 1, nullptr, nullptr, 0, nullptr, 0, 0, false);
    k_feat0<<<ROWS1, 256>>>(tr_emb, x1, ffout, det_emb, feat0, x);

    // ---- adjacency ----
    k_posvm<<<64, 256>>>(tracks, dets, tmarks, dmarks, pos, vm);
    k_adj<<<dim3(NN1, BB), 256>>>(pos, vm, adj);
    k_adjd<<<dim3(NNd, BB), 128>>>(pos, vm, adjd);

    // ---- main GAT x2 ----
    for (int l = 0; l < 2; l++) {
        run_big(x, 256, 0, gatW + (size_t)l * 65536, 256, 0, h, 256, 0,
                ROWS1, 256, 256, 1, nullptr, nullptr, 0, nullptr, 0, 0, false);
        k_srcdst<<<ROWS1, 256>>>(h, gata + (size_t)l * 512, src, dstT, NN1);
        k_rowstat<<<dim3(NN1, BB), 128>>>(src, dstT, adj, stat, NN1);
        agg_fused<<<dim3(1, NN1 / 128, BB * HH), 256>>>(
            h, src, stat, dstT, adj, feat0, x, NN1);
    }

    // ---- main scores (xq & xk fused into one dual launch) ----
    run_big(x, 256, 0, clsWq, 256, 0, xq, 256, 0,
            ROWS1, 256, 256, 2, nullptr, nullptr, 0, nullptr, 0, 0, false,
            clsWk, xk, 1);
    run_big(xq, 256, (long long)NN1 * 256, xk, 256, (long long)NN1 * 256,
            out_scores, NN1, (long long)NN1 * NN1,
            NN1, NN1, 256, BB, nullptr, nullptr, 0,
            adj, (long long)NN1 * NN1, F_SIG, true);
    k_asso<<<(int)(((size_t)BB * 512 * 512) / 256), 256>>>(out_scores, out_asso);

    // ---- detection GAT x2 ----
    for (int l = 0; l < 2; l++) {
        const float* xin = (l == 0) ? det_emb : x;
        run_big(xin, 256, 0, dgatW + (size_t)l * 65536, 256, 0, h, 256, 0,
                ND, 256, 256, 1, nullptr, nullptr, 0, nullptr, 0, 0, false);
        k_srcdst<<<ND, 256>>>(h, dgata + (size_t)l * 512, src, dstT, NNd);
        k_rowstat<<<dim3(NNd, BB), 128>>>(src, dstT, adjd, stat, NNd);
        agg_fused<<<dim3(1, NNd / 128, BB * HH), 256>>>(
            h, src, stat, dstT, adjd, det_emb, x, NNd);
    }

    // ---- detection scores (dual xq/xk) ----
    run_big(x, 256, 0, clsWq + 65536, 256, 0, xq, 256, 0,
            ND, 256, 256, 2, nullptr, nullptr, 0, nullptr, 0, 0, false,
            clsWk + 65536, xk, 1);
    run_big(xq, 256, (long long)NNd * 256, xk, 256, (long long)NNd * 256,
            out_det, NNd, (long long)NNd * NNd,
            NNd, NNd, 256, BB, nullptr, nullptr, 0,
            adjd, (long long)NNd * NNd, F_SIG | F_DIAG, true);
}

// round 10
// speedup vs baseline: 3.8781x; 1.0952x over previous
#include <cuda_runtime.h>
#include <cuda_fp16.h>
#include <math.h>
#include <stdint.h>

// ---------------------------------------------------------------------------
// Problem dims
// ---------------------------------------------------------------------------
#define BB 16
#define MM 512
#define NNd 512
#define RR 8
#define DD 256
#define HH 4
#define NN1 1024
#define TM  (BB*MM*RR)    // 65536
#define TT  (BB*MM)       // 8192
#define ND  (BB*NNd)      // 8192
#define ROWS1 (BB*NN1)    // 16384

#define F_BIAS 1
#define F_RELU 2
#define F_AUX  4
#define F_SIG  8
#define F_DIAG 16

// ---------------------------------------------------------------------------
// Scratch
// ---------------------------------------------------------------------------
__device__ float g_h1[(TM+ND)*DD];
__device__ float g_emb[(TM+ND)*DD];
__device__ float g_ln[TM*DD];
__device__ float g_kv[TM*512];
__device__ float g_q0[TT*DD];
__device__ float g_o0[TT*DD];
__device__ float g_x1[TT*DD];
__device__ float g_ln2[TT*DD];
__device__ float g_ffh[TT*1024];
__device__ float g_ffout[TT*DD];
__device__ float g_feat0[ROWS1*DD];
__device__ float g_x[ROWS1*DD];
__device__ float g_h[ROWS1*DD];
__device__ float g_src[ROWS1*HH];
__device__ float g_dstT[BB*HH*NN1];
__device__ float2 g_stat[BB*HH*NN1];
__device__ __half g_anum[(size_t)BB*HH*NN1*NN1];   // fp16 softmax numerators
__device__ unsigned char g_adj[(size_t)BB*NN1*NN1];
__device__ unsigned char g_adjd[(size_t)BB*NNd*NNd];
__device__ float g_pos[BB*NN1*2];
__device__ unsigned char g_vm[BB*NN1];
__device__ float g_xq[ROWS1*DD];
__device__ float g_xk[ROWS1*DD];

// ---------------------------------------------------------------------------
// fp16 / ldmatrix helpers
// ---------------------------------------------------------------------------
__device__ __forceinline__ uint32_t pk(float lo, float hi) {
    __half2 v = __floats2half2_rn(lo, hi);
    return *reinterpret_cast<uint32_t*>(&v);
}
__device__ __forceinline__ void mma_f16(float* c, const uint32_t* a, const uint32_t* b) {
    asm volatile(
        "mma.sync.aligned.m16n8k16.row.col.f32.f16.f16.f32 "
        "{%0,%1,%2,%3}, {%4,%5,%6,%7}, {%8,%9}, {%0,%1,%2,%3};\n"
        : "+f"(c[0]), "+f"(c[1]), "+f"(c[2]), "+f"(c[3])
        : "r"(a[0]), "r"(a[1]), "r"(a[2]), "r"(a[3]), "r"(b[0]), "r"(b[1]));
}
__device__ __forceinline__ void ldm_x4(uint32_t* r, uint32_t addr) {
    asm volatile("ldmatrix.sync.aligned.m8n8.x4.shared.b16 {%0,%1,%2,%3}, [%4];"
        : "=r"(r[0]), "=r"(r[1]), "=r"(r[2]), "=r"(r[3]) : "r"(addr));
}
__device__ __forceinline__ void ldm_x4_t(uint32_t* r, uint32_t addr) {
    asm volatile("ldmatrix.sync.aligned.m8n8.x4.trans.shared.b16 {%0,%1,%2,%3}, [%4];"
        : "=r"(r[0]), "=r"(r[1]), "=r"(r[2]), "=r"(r[3]) : "r"(addr));
}
__device__ __forceinline__ uint32_t cvs(const void* p) {
    return (uint32_t)__cvta_generic_to_shared(p);
}

// ---------------------------------------------------------------------------
// BIG GEMM (fp16 m16n8k16 + ldmatrix): unchanged from R9 (passing).
// ---------------------------------------------------------------------------
template<bool TRANSB, int FLAGS>
__global__ __launch_bounds__(256, 2)
void tgemm_big(const float* __restrict__ A, int lda, long long sA,
               const float* __restrict__ B, int ldb, long long sB,
               float* __restrict__ C, int ldc, long long sC,
               int K,
               const float* __restrict__ bias,
               const float* __restrict__ aux, int auxld,
               const unsigned char* __restrict__ adjp, long long sAdj,
               const float* __restrict__ B2, float* __restrict__ C2, int dual)
{
    int bz = blockIdx.z;
    if (dual && bz) { B = B2; C = C2; bz = 0; }
    A += (long long)bz * sA;
    B += (long long)bz * sB;
    C += (long long)bz * sC;
    if (FLAGS & F_SIG) adjp += (long long)bz * sAdj;

    int m0 = blockIdx.y * 128, n0 = blockIdx.x * 128;

    __shared__ uint32_t As[2][1536];
    __shared__ uint32_t Bs[2][1536];

    int tid = threadIdx.x;
    int arow = tid >> 1, ahalf = tid & 1;
    const float* gA = A + (size_t)(m0 + arow) * lda + ahalf * 8;

    const float* gB;
    if (!TRANSB) {
        int kpp = tid >> 5, nqq = tid & 31;
        gB = B + (size_t)(2 * kpp) * ldb + n0 + nqq * 4;
    } else {
        gB = B + (size_t)(n0 + arow) * ldb + ahalf * 8;
    }
    int kp = tid >> 5, nq = tid & 31;

    int w = tid >> 5, l = tid & 31;
    int mbase = (w >> 2) * 64, nbase = (w & 3) * 32;
    int grp = l >> 2, tig = l & 3;

    int lrowA = ((l >> 3) & 1) * 8 + (l & 7);
    int khalf = l >> 4;
    uint32_t aBase[4];
    #pragma unroll
    for (int fm = 0; fm < 4; fm++)
        aBase[fm] = cvs(&As[0][(mbase + fm * 16 + lrowA) * 12 + khalf * 4]);
    uint32_t bBase[2];
    if (!TRANSB) {
        int krow = ((l >> 4) & 1) * 8 + (l & 7);
        int nblk = ((l >> 3) & 1) * 8;
        #pragma unroll
        for (int fp = 0; fp < 2; fp++)
            bBase[fp] = cvs(&Bs[0][krow * 68 + ((nbase + fp * 16 + nblk) >> 1)]);
    } else {
        #pragma unroll
        for (int fp = 0; fp < 2; fp++)
            bBase[fp] = cvs(&Bs[0][(nbase + fp * 16 + lrowA) * 12 + khalf * 4]);
    }

    float acc[4][4][4];
    #pragma unroll
    for (int i = 0; i < 4; i++)
        #pragma unroll
        for (int j = 0; j < 4; j++)
            #pragma unroll
            for (int q = 0; q < 4; q++) acc[i][j][q] = 0.f;

    int nk = K >> 4;
    float4 va0, va1, vb0, vb1;

    va0 = *(const float4*)(gA);
    va1 = *(const float4*)(gA + 4);
    if (!TRANSB) { vb0 = *(const float4*)(gB); vb1 = *(const float4*)(gB + ldb); }
    else         { vb0 = *(const float4*)(gB); vb1 = *(const float4*)(gB + 4); }
    {
        uint32_t* ap = &As[0][arow * 12 + ahalf * 4];
        ap[0] = pk(va0.x, va0.y); ap[1] = pk(va0.z, va0.w);
        ap[2] = pk(va1.x, va1.y); ap[3] = pk(va1.z, va1.w);
        if (!TRANSB) {
            uint32_t* bh = &Bs[0][0];
            int w0 = (2 * kp) * 68 + nq * 2;
            bh[w0]      = pk(vb0.x, vb0.y);
            bh[w0 + 1]  = pk(vb0.z, vb0.w);
            bh[w0 + 68] = pk(vb1.x, vb1.y);
            bh[w0 + 69] = pk(vb1.z, vb1.w);
        } else {
            uint32_t* bp = &Bs[0][arow * 12 + ahalf * 4];
            bp[0] = pk(vb0.x, vb0.y); bp[1] = pk(vb0.z, vb0.w);
            bp[2] = pk(vb1.x, vb1.y); bp[3] = pk(vb1.z, vb1.w);
        }
    }
    if (nk > 1) {
        va0 = *(const float4*)(gA + 16);
        va1 = *(const float4*)(gA + 20);
        if (!TRANSB) { vb0 = *(const float4*)(gB + (size_t)16 * ldb); vb1 = *(const float4*)(gB + (size_t)17 * ldb); }
        else         { vb0 = *(const float4*)(gB + 16); vb1 = *(const float4*)(gB + 20); }
    }

    int s = 0;
    for (int i = 0; i < nk; i++) {
        __syncthreads();
        if (i + 1 < nk) {
            int d = s ^ 1;
            uint32_t* ap = &As[d][arow * 12 + ahalf * 4];
            ap[0] = pk(va0.x, va0.y); ap[1] = pk(va0.z, va0.w);
            ap[2] = pk(va1.x, va1.y); ap[3] = pk(va1.z, va1.w);
            if (!TRANSB) {
                uint32_t* bh = &Bs[d][0];
                int w0 = (2 * kp) * 68 + nq * 2;
                bh[w0]      = pk(vb0.x, vb0.y);
                bh[w0 + 1]  = pk(vb0.z, vb0.w);
                bh[w0 + 68] = pk(vb1.x, vb1.y);
                bh[w0 + 69] = pk(vb1.z, vb1.w);
            } else {
                uint32_t* bp = &Bs[d][arow * 12 + ahalf * 4];
                bp[0] = pk(vb0.x, vb0.y); bp[1] = pk(vb0.z, vb0.w);
                bp[2] = pk(vb1.x, vb1.y); bp[3] = pk(vb1.z, vb1.w);
            }
            if (i + 2 < nk) {
                int k0 = (i + 2) * 16;
                va0 = *(const float4*)(gA + k0);
                va1 = *(const float4*)(gA + k0 + 4);
                if (!TRANSB) {
                    vb0 = *(const float4*)(gB + (size_t)k0 * ldb);
                    vb1 = *(const float4*)(gB + (size_t)(k0 + 1) * ldb);
                } else {
                    vb0 = *(const float4*)(gB + k0);
                    vb1 = *(const float4*)(gB + k0 + 4);
                }
            }
        }
        uint32_t soff = (uint32_t)(s * 6144);
        uint32_t af[4][4];
        #pragma unroll
        for (int fm = 0; fm < 4; fm++) ldm_x4(af[fm], aBase[fm] + soff);
        uint32_t bfr[4][2];
        #pragma unroll
        for (int fp = 0; fp < 2; fp++) {
            uint32_t t4[4];
            if (!TRANSB) ldm_x4_t(t4, bBase[fp] + soff);
            else         ldm_x4(t4, bBase[fp] + soff);
            bfr[fp * 2][0] = t4[0]; bfr[fp * 2 + 1][0] = t4[1];
            bfr[fp * 2][1] = t4[2]; bfr[fp * 2 + 1][1] = t4[3];
        }
        #pragma unroll
        for (int fm = 0; fm < 4; fm++)
            #pragma unroll
            for (int fn = 0; fn < 4; fn++)
                mma_f16(acc[fm][fn], af[fm], bfr[fn]);
        s ^= 1;
    }

    #pragma unroll
    for (int fm = 0; fm < 4; fm++) {
        int row0 = m0 + mbase + fm * 16 + grp;
        #pragma unroll
        for (int fn = 0; fn < 4; fn++) {
            int col = n0 + nbase + fn * 8 + 2 * tig;
            float v0 = acc[fm][fn][0], v1 = acc[fm][fn][1];
            float v2 = acc[fm][fn][2], v3 = acc[fm][fn][3];
            if (FLAGS & F_BIAS) {
                float bb0 = bias[col], bb1 = bias[col + 1];
                v0 += bb0; v1 += bb1; v2 += bb0; v3 += bb1;
            }
            if (FLAGS & F_RELU) {
                v0 = fmaxf(v0, 0.f); v1 = fmaxf(v1, 0.f);
                v2 = fmaxf(v2, 0.f); v3 = fmaxf(v3, 0.f);
            }
            if (FLAGS & F_AUX) {
                const float* ar = aux + (size_t)row0 * auxld + col;
                const float* ar8 = aux + (size_t)(row0 + 8) * auxld + col;
                v0 += ar[0]; v1 += ar[1]; v2 += ar8[0]; v3 += ar8[1];
            }
            if (FLAGS & F_SIG) {
                const unsigned char* q0p = adjp + (size_t)row0 * ldc + col;
                const unsigned char* q8p = adjp + (size_t)(row0 + 8) * ldc + col;
                v0 = q0p[0] ? 1.f / (1.f + __expf(-v0 * 0.0625f)) : 0.f;
                v1 = q0p[1] ? 1.f / (1.f + __expf(-v1 * 0.0625f)) : 0.f;
                v2 = q8p[0] ? 1.f / (1.f + __expf(-v2 * 0.0625f)) : 0.f;
                v3 = q8p[1] ? 1.f / (1.f + __expf(-v3 * 0.0625f)) : 0.f;
                if (FLAGS & F_DIAG) {
                    if (row0 == col) v0 = 0.f;
                    if (row0 == col + 1) v1 = 0.f;
                    if (row0 + 8 == col) v2 = 0.f;
                    if (row0 + 8 == col + 1) v3 = 0.f;
                }
            }
            *(float2*)&C[(size_t)row0 * ldc + col] = make_float2(v0, v1);
            *(float2*)&C[(size_t)(row0 + 8) * ldc + col] = make_float2(v2, v3);
        }
    }
}

// ---------------------------------------------------------------------------
// GAT aggregation as pure fp16 GEMM: x = 0.5*elu(inv_row * (anum @ h)) + 0.5*aux
// A = fp16 numerators (global), double-buffered. CTA 128x64, warp 32x32.
// grid (1, NN/128, BB*HH).
// ---------------------------------------------------------------------------
__global__ __launch_bounds__(256)
void agg_fused(const __half* __restrict__ anum, const float2* __restrict__ stat,
               const float* __restrict__ hmat,
               const float* __restrict__ aux, float* __restrict__ xout, int NN)
{
    int z = blockIdx.z;
    int b = z >> 2, h = z & 3;
    const float* B = hmat + (size_t)b * NN * 256 + h * 64;
    float* C = xout + (size_t)b * NN * 256 + h * 64;
    const float* auxp = aux + (size_t)b * NN * 256 + h * 64;
    const float2* statz = stat + (size_t)z * NN;

    int m0 = blockIdx.y * 128;
    __shared__ uint32_t As[2][1536];
    __shared__ uint32_t Bs[2][576];
    int tid = threadIdx.x;

    int arow = tid >> 1, ahalf = tid & 1;
    const __half* gA = anum + ((size_t)z * NN + m0 + arow) * NN + ahalf * 8;

    int kp = tid >> 5, nq = tid & 31;
    const float* gB = B + (size_t)(2 * kp) * 256 + 2 * nq;

    int w = tid >> 5, l = tid & 31;
    int wm = w >> 1, wn = w & 1;
    int mrow = wm * 32, ncol = wn * 32;
    int grp = l >> 2, tig = l & 3;

    int lrowA = ((l >> 3) & 1) * 8 + (l & 7);
    int khalf = l >> 4;
    uint32_t aBase[2];
    #pragma unroll
    for (int fm = 0; fm < 2; fm++)
        aBase[fm] = cvs(&As[0][(mrow + fm * 16 + lrowA) * 12 + khalf * 4]);
    int krow = ((l >> 4) & 1) * 8 + (l & 7);
    int nblk = ((l >> 3) & 1) * 8;
    uint32_t bBase[2];
    #pragma unroll
    for (int fp = 0; fp < 2; fp++)
        bBase[fp] = cvs(&Bs[0][krow * 36 + ((ncol + fp * 16 + nblk) >> 1)]);

    float acc[2][4][4];
    #pragma unroll
    for (int i = 0; i < 2; i++)
        #pragma unroll
        for (int j = 0; j < 4; j++)
            #pragma unroll
            for (int q = 0; q < 4; q++) acc[i][j][q] = 0.f;

    int nk = NN >> 4;
    uint4 ra;
    float2 rb0, rb1;

    // stage 0
    ra  = *(const uint4*)(gA);
    rb0 = *(const float2*)(gB);
    rb1 = *(const float2*)(gB + 256);
    {
        uint32_t* ap = &As[0][arow * 12 + ahalf * 4];
        ap[0] = ra.x; ap[1] = ra.y; ap[2] = ra.z; ap[3] = ra.w;
        Bs[0][(2 * kp) * 36 + nq]     = pk(rb0.x, rb0.y);
        Bs[0][(2 * kp + 1) * 36 + nq] = pk(rb1.x, rb1.y);
    }
    if (nk > 1) {
        ra  = *(const uint4*)(gA + 16);
        rb0 = *(const float2*)(gB + 16 * 256);
        rb1 = *(const float2*)(gB + 17 * 256);
    }

    int s = 0;
    for (int i = 0; i < nk; i++) {
        __syncthreads();
        if (i + 1 < nk) {
            int d = s ^ 1;
            uint32_t* ap = &As[d][arow * 12 + ahalf * 4];
            ap[0] = ra.x; ap[1] = ra.y; ap[2] = ra.z; ap[3] = ra.w;
            Bs[d][(2 * kp) * 36 + nq]     = pk(rb0.x, rb0.y);
            Bs[d][(2 * kp + 1) * 36 + nq] = pk(rb1.x, rb1.y);
            if (i + 2 < nk) {
                int k0 = (i + 2) * 16;
                ra  = *(const uint4*)(gA + k0);
                rb0 = *(const float2*)(gB + (size_t)k0 * 256);
                rb1 = *(const float2*)(gB + (size_t)(k0 + 1) * 256);
            }
        }
        uint32_t sa = (uint32_t)(s * 6144);
        uint32_t sbo = (uint32_t)(s * 2304);
        uint32_t af[2][4];
        #pragma unroll
        for (int fm = 0; fm < 2; fm++) ldm_x4(af[fm], aBase[fm] + sa);
        uint32_t bfr[4][2];
        #pragma unroll
        for (int fp = 0; fp < 2; fp++) {
            uint32_t t4[4];
            ldm_x4_t(t4, bBase[fp] + sbo);
            bfr[fp * 2][0] = t4[0]; bfr[fp * 2 + 1][0] = t4[1];
            bfr[fp * 2][1] = t4[2]; bfr[fp * 2 + 1][1] = t4[3];
        }
        #pragma unroll
        for (int fm = 0; fm < 2; fm++)
            #pragma unroll
            for (int fn = 0; fn < 4; fn++)
                mma_f16(acc[fm][fn], af[fm], bfr[fn]);
        s ^= 1;
    }

    #pragma unroll
    for (int fm = 0; fm < 2; fm++) {
        int row = m0 + mrow + fm * 16 + grp;
        float inv0 = statz[row].y;
        float inv8 = statz[row + 8].y;
        #pragma unroll
        for (int fn = 0; fn < 4; fn++) {
            int col = ncol + fn * 8 + 2 * tig;
            float v0 = acc[fm][fn][0] * inv0, v1 = acc[fm][fn][1] * inv0;
            float v2 = acc[fm][fn][2] * inv8, v3 = acc[fm][fn][3] * inv8;
            v0 = (v0 > 0.f) ? v0 : expm1f(v0);
            v1 = (v1 > 0.f) ? v1 : expm1f(v1);
            v2 = (v2 > 0.f) ? v2 : expm1f(v2);
            v3 = (v3 > 0.f) ? v3 : expm1f(v3);
            float2 x0 = *(const float2*)&auxp[(size_t)row * 256 + col];
            float2 x1 = *(const float2*)&auxp[(size_t)(row + 8) * 256 + col];
            *(float2*)&C[(size_t)row * 256 + col] =
                make_float2(0.5f * v0 + 0.5f * x0.x, 0.5f * v1 + 0.5f * x0.y);
            *(float2*)&C[(size_t)(row + 8) * 256 + col] =
                make_float2(0.5f * v2 + 0.5f * x1.x, 0.5f * v3 + 0.5f * x1.y);
        }
    }
}

// ---------------------------------------------------------------------------
// Small kernels
// ---------------------------------------------------------------------------
// feat layer1: 4 rows per block, 4 cols per thread
__global__ void k_feat1(const float* __restrict__ x, const float* __restrict__ W1,
                        const float* __restrict__ b1, float* __restrict__ out)
{
    int tid = threadIdx.x;
    size_t row = (size_t)blockIdx.x * 4 + (tid >> 6);
    int c4 = (tid & 63) * 4;
    const float4 xr = *(const float4*)(x + row * 4);
    float4 v = *(const float4*)(b1 + c4);
    float4 w0 = *(const float4*)(W1 + c4);
    float4 w1 = *(const float4*)(W1 + 256 + c4);
    float4 w2 = *(const float4*)(W1 + 512 + c4);
    float4 w3 = *(const float4*)(W1 + 768 + c4);
    v.x += xr.x * w0.x + xr.y * w1.x + xr.z * w2.x + xr.w * w3.x;
    v.y += xr.x * w0.y + xr.y * w1.y + xr.z * w2.y + xr.w * w3.y;
    v.z += xr.x * w0.z + xr.y * w1.z + xr.z * w2.z + xr.w * w3.z;
    v.w += xr.x * w0.w + xr.y * w1.w + xr.z * w2.w + xr.w * w3.w;
    v.x = (v.x > 0.f) ? v.x : (__expf(v.x) - 1.f);
    v.y = (v.y > 0.f) ? v.y : (__expf(v.y) - 1.f);
    v.z = (v.z > 0.f) ? v.z : (__expf(v.z) - 1.f);
    v.w = (v.w > 0.f) ? v.w : (__expf(v.w) - 1.f);
    *(float4*)(out + row * 256 + c4) = v;
}

// LayerNorm: one warp per row, 8 rows per block
__global__ void k_ln(const float* __restrict__ in, float* __restrict__ out)
{
    int w = threadIdx.x >> 5, lane = threadIdx.x & 31;
    size_t row = (size_t)blockIdx.x * 8 + w;
    const float4* ip = (const float4*)(in + row * 256);
    float4 v0 = ip[lane], v1 = ip[lane + 32];
    float a = v0.x + v0.y + v0.z + v0.w + v1.x + v1.y + v1.z + v1.w;
    float b = v0.x*v0.x + v0.y*v0.y + v0.z*v0.z + v0.w*v0.w
            + v1.x*v1.x + v1.y*v1.y + v1.z*v1.z + v1.w*v1.w;
    #pragma unroll
    for (int o = 16; o; o >>= 1) {
        a += __shfl_xor_sync(0xffffffff, a, o);
        b += __shfl_xor_sync(0xffffffff, b, o);
    }
    float mean = a * (1.f / 256.f);
    float var = b * (1.f / 256.f) - mean * mean;
    float rstd = rsqrtf(var + 1e-5f);
    float4* op = (float4*)(out + row * 256);
    v0.x = (v0.x - mean) * rstd; v0.y = (v0.y - mean) * rstd;
    v0.z = (v0.z - mean) * rstd; v0.w = (v0.w - mean) * rstd;
    v1.x = (v1.x - mean) * rstd; v1.y = (v1.y - mean) * rstd;
    v1.z = (v1.z - mean) * rstd; v1.w = (v1.w - mean) * rstd;
    op[lane] = v0; op[lane + 32] = v1;
}

// tiny attention, single barrier
__global__ void k_attn(const float* __restrict__ q0, const float* __restrict__ kv,
                       float* __restrict__ o0)
{
    size_t t = blockIdx.x;
    int d = threadIdx.x;
    int w = d >> 5, lane = d & 31, h = d >> 6;
    __shared__ float red[8][8];
    const float* kvb = kv + t * 8 * 512;
    float qd = q0[t * 256 + d];
    float p[8];
    #pragma unroll
    for (int s = 0; s < 8; s++) p[s] = qd * kvb[s * 512 + d];
    #pragma unroll
    for (int s = 0; s < 8; s++) {
        float v = p[s];
        #pragma unroll
        for (int o = 16; o; o >>= 1) v += __shfl_xor_sync(0xffffffff, v, o);
        if (lane == 0) red[w][s] = v;
    }
    __syncthreads();
    float lg[8];
    float m = -1e30f;
    #pragma unroll
    for (int s = 0; s < 8; s++) {
        lg[s] = (red[2 * h][s] + red[2 * h + 1][s]) * 0.125f;
        m = fmaxf(m, lg[s]);
    }
    float sum = 0.f;
    #pragma unroll
    for (int s = 0; s < 8; s++) { lg[s] = __expf(lg[s] - m); sum += lg[s]; }
    float inv = 1.f / sum;
    float o = 0.f;
    #pragma unroll
    for (int s = 0; s < 8; s++) o += lg[s] * inv * kvb[s * 512 + 256 + d];
    o0[t * 256 + d] = o;
}

__global__ void k_feat0(const float* __restrict__ tr_emb, const float* __restrict__ x1,
                        const float* __restrict__ ffout, const float* __restrict__ det_emb,
                        float* __restrict__ feat0, float* __restrict__ x)
{
    size_t idx = (size_t)blockIdx.x * 256 + threadIdx.x;
    int d = idx & 255;
    size_t row = idx >> 8;
    int i = row & 1023;
    int b = row >> 10;
    float v;
    if (i < 512) {
        size_t t = (size_t)b * 512 + i;
        v = tr_emb[t * 2048 + d] + 0.9f * (x1[t * 256 + d] + ffout[t * 256 + d]);
    } else {
        size_t t = (size_t)b * 512 + (i - 512);
        v = det_emb[t * 256 + d];
    }
    feat0[idx] = v;
    x[idx] = v;
}

__global__ void k_posvm(const float* __restrict__ tracks, const float* __restrict__ dets,
                        const int* __restrict__ tmarks, const int* __restrict__ dmarks,
                        float* __restrict__ pos, unsigned char* __restrict__ vm)
{
    int idx = blockIdx.x * 256 + threadIdx.x;
    if (idx >= BB * NN1) return;
    int b = idx >> 10, i = idx & 1023;
    float x, y; unsigned char v;
    if (i < 512) {
        const float* p = tracks + ((size_t)(b * 512 + i)) * 8 * 4;
        x = p[0]; y = p[1];
        v = (i < tmarks[b]);
    } else {
        int n = i - 512;
        const float* p = dets + ((size_t)(b * 512 + n)) * 4;
        x = p[0]; y = p[1];
        v = (n < dmarks[b]);
    }
    pos[idx * 2] = x; pos[idx * 2 + 1] = y; vm[idx] = v;
}

__global__ void k_adj(const float* __restrict__ pos, const unsigned char* __restrict__ vm,
                      unsigned char* __restrict__ adj)
{
    int i = blockIdx.x, b = blockIdx.y;
    size_t base = (size_t)b * NN1;
    const float2* p2 = (const float2*)pos;
    float2 pi = p2[base + i];
    unsigned char vi = vm[base + i];
    int j0 = threadIdx.x * 4;
    uchar4 r;
    unsigned char* rp = &r.x;
    #pragma unroll
    for (int u = 0; u < 4; u++) {
        int j = j0 + u;
        float2 pj = p2[base + j];
        float dx = pi.x - pj.x, dy = pi.y - pj.y;
        rp[u] = (unsigned char)((dx * dx + dy * dy < 4.0f) && vi && vm[base + j]);
    }
    ((uchar4*)(adj + ((size_t)b * NN1 + i) * NN1))[threadIdx.x] = r;
}

__global__ void k_adjd(const float* __restrict__ pos, const unsigned char* __restrict__ vm,
                       unsigned char* __restrict__ adjd)
{
    int i = blockIdx.x, b = blockIdx.y;
    size_t base = (size_t)b * NN1 + 512;
    const float2* p2 = (const float2*)pos;
    float2 pi = p2[base + i];
    unsigned char vi = vm[base + i];
    int j0 = threadIdx.x * 4;
    uchar4 r;
    unsigned char* rp = &r.x;
    #pragma unroll
    for (int u = 0; u < 4; u++) {
        int j = j0 + u;
        float2 pj = p2[base + j];
        float dx = pi.x - pj.x, dy = pi.y - pj.y;
        rp[u] = (unsigned char)((dx * dx + dy * dy < 4.0f) && vi && vm[base + j]);
    }
    ((uchar4*)(adjd + ((size_t)b * NNd + i) * NNd))[threadIdx.x] = r;
}

__global__ void k_srcdst(const float* __restrict__ Hm, const float* __restrict__ a0,
                         float* __restrict__ src, float* __restrict__ dstT, int NN)
{
    size_t row = blockIdx.x;
    int d = threadIdx.x;
    float hv = Hm[row * 256 + d];
    float s = hv * a0[d];
    float t2 = hv * a0[256 + d];
    #pragma unroll
    for (int o = 16; o; o >>= 1) {
        s  += __shfl_xor_sync(0xffffffff, s, o);
        t2 += __shfl_xor_sync(0xffffffff, t2, o);
    }
    __shared__ float ps[8], pt[8];
    if ((d & 31) == 0) { ps[d >> 5] = s; pt[d >> 5] = t2; }
    __syncthreads();
    if (d < 4) {
        int b = (int)(row / NN);
        int i = (int)(row - (size_t)b * NN);
        src[row * 4 + d] = ps[2 * d] + ps[2 * d + 1];
        dstT[((size_t)b * 4 + d) * NN + i] = pt[2 * d] + pt[2 * d + 1];
    }
}

// row softmax stats + fp16 numerator write. grid (NN, BB), 128 thr.
__global__ void k_rowstat(const float* __restrict__ src, const float* __restrict__ dstT,
                          const unsigned char* __restrict__ adj, float2* __restrict__ stat,
                          __half* __restrict__ anum, int NN)
{
    int i = blockIdx.x, b = blockIdx.y;
    int h = threadIdx.x >> 5, lane = threadIdx.x & 31;
    int z = b * 4 + h;
    float s = src[((size_t)b * NN + i) * 4 + h];
    const uchar4* adjrow = (const uchar4*)(adj + ((size_t)b * NN + i) * NN);
    const float4* dsth = (const float4*)(dstT + ((size_t)z) * NN);
    __half* arow = anum + ((size_t)z * NN + i) * NN;
    int nq = NN >> 2;
    float mx = -1e30f;
    for (int jq = lane; jq < nq; jq += 32) {
        uchar4 a4 = adjrow[jq];
        float4 d4 = dsth[jq];
        float e0 = s + d4.x; e0 = e0 > 0.f ? e0 : 0.2f * e0; e0 = a4.x ? e0 : -1e9f;
        float e1 = s + d4.y; e1 = e1 > 0.f ? e1 : 0.2f * e1; e1 = a4.y ? e1 : -1e9f;
        float e2 = s + d4.z; e2 = e2 > 0.f ? e2 : 0.2f * e2; e2 = a4.z ? e2 : -1e9f;
        float e3 = s + d4.w; e3 = e3 > 0.f ? e3 : 0.2f * e3; e3 = a4.w ? e3 : -1e9f;
        mx = fmaxf(mx, fmaxf(fmaxf(e0, e1), fmaxf(e2, e3)));
    }
    #pragma unroll
    for (int o = 16; o; o >>= 1) mx = fmaxf(mx, __shfl_xor_sync(0xffffffff, mx, o));
    float sum = 0.f;
    for (int jq = lane; jq < nq; jq += 32) {
        uchar4 a4 = adjrow[jq];
        float4 d4 = dsth[jq];
        float e0 = s + d4.x; e0 = e0 > 0.f ? e0 : 0.2f * e0; e0 = a4.x ? e0 : -1e9f;
        float e1 = s + d4.y; e1 = e1 > 0.f ? e1 : 0.2f * e1; e1 = a4.y ? e1 : -1e9f;
        float e2 = s + d4.z; e2 = e2 > 0.f ? e2 : 0.2f * e2; e2 = a4.z ? e2 : -1e9f;
        float e3 = s + d4.w; e3 = e3 > 0.f ? e3 : 0.2f * e3; e3 = a4.w ? e3 : -1e9f;
        float n0 = __expf(e0 - mx), n1 = __expf(e1 - mx);
        float n2 = __expf(e2 - mx), n3 = __expf(e3 - mx);
        sum += n0 + n1 + n2 + n3;
        __half2 p01 = __floats2half2_rn(n0, n1);
        __half2 p23 = __floats2half2_rn(n2, n3);
        uint2 pkd;
        pkd.x = *reinterpret_cast<uint32_t*>(&p01);
        pkd.y = *reinterpret_cast<uint32_t*>(&p23);
        *(uint2*)(arow + jq * 4) = pkd;
    }
    #pragma unroll
    for (int o = 16; o; o >>= 1) sum += __shfl_xor_sync(0xffffffff, sum, o);
    if (lane == 0)
        stat[(size_t)z * NN + i] = make_float2(mx, 1.f / sum);
}

__global__ void k_asso(const float* __restrict__ scores, float* __restrict__ out)
{
    size_t idx = (size_t)blockIdx.x * 256 + threadIdx.x;
    int j = idx & 511;
    size_t r = idx >> 9;
    int m = r & 511;
    int b = (int)(r >> 9);
    out[idx] = scores[(((size_t)b * 1024 + m) * 1024) + 512 + j];
}

// ---------------------------------------------------------------------------
// Host side
// ---------------------------------------------------------------------------
static void run_big(const float* A, int lda, long long sA,
                    const float* B, int ldb, long long sB,
                    float* C, int ldc, long long sC,
                    int M, int N, int K, int batch,
                    const float* bias, const float* aux, int auxld,
                    const unsigned char* adjp, long long sAdj,
                    int flags, bool transb,
                    const float* B2 = nullptr, float* C2 = nullptr, int dual = 0)
{
    dim3 g(N / 128, M / 128, batch);
#define CALLBIG(T, F) tgemm_big<T, F><<<g, 256>>>(A, lda, sA, B, ldb, sB, \
        C, ldc, sC, K, bias, aux, auxld, adjp, sAdj, B2, C2, dual)
    if (!transb) {
        if (flags == 0)           CALLBIG(false, 0);
        else if (flags == F_BIAS) CALLBIG(false, F_BIAS);
        else if (flags == F_RELU) CALLBIG(false, F_RELU);
        else                      CALLBIG(false, F_AUX);
    } else {
        if (flags == F_SIG)       CALLBIG(true, F_SIG);
        else                      CALLBIG(true, F_SIG | F_DIAG);
    }
#undef CALLBIG
}

#define SYM(p, s) cudaGetSymbolAddress((void**)&p, s)

extern "C" void kernel_launch(void* const* d_in, const int* in_sizes, int n_in,
                              void* d_out, int out_size)
{
    (void)in_sizes; (void)n_in; (void)out_size;
    const float* tracks = (const float*)d_in[0];
    const float* dets   = (const float*)d_in[1];
    const int* tmarks   = (const int*)d_in[2];
    const int* dmarks   = (const int*)d_in[3];
    const float* W1     = (const float*)d_in[4];
    const float* b1     = (const float*)d_in[5];
    const float* W2     = (const float*)d_in[6];
    const float* b2     = (const float*)d_in[7];
    const float* Wqkv   = (const float*)d_in[8];
    const float* Wo     = (const float*)d_in[9];
    const float* ff1    = (const float*)d_in[10];
    const float* ff2    = (const float*)d_in[11];
    const float* gatW   = (const float*)d_in[12];
    const float* gata   = (const float*)d_in[13];
    const float* dgatW  = (const float*)d_in[14];
    const float* dgata  = (const float*)d_in[15];
    const float* clsWq  = (const float*)d_in[16];
    const float* clsWk  = (const float*)d_in[17];

    float* out = (float*)d_out;
    float* out_scores = out;
    float* out_det    = out + (size_t)BB * NN1 * NN1;
    float* out_asso   = out_det + (size_t)BB * NNd * NNd;

    float *h1, *emb, *ln, *kv, *q0, *o0, *x1,
          *ln2, *ffh, *ffout, *feat0, *x, *h, *src, *dstT, *pos, *xq, *xk;
    float2* stat;
    __half* anum;
    unsigned char *adj, *adjd, *vm;
    SYM(h1, g_h1);         SYM(emb, g_emb);       SYM(ln, g_ln);
    SYM(kv, g_kv);
    SYM(q0, g_q0);         SYM(o0, g_o0);
    SYM(x1, g_x1);         SYM(ln2, g_ln2);       SYM(ffh, g_ffh);
    SYM(ffout, g_ffout);   SYM(feat0, g_feat0);   SYM(x, g_x);
    SYM(h, g_h);           SYM(src, g_src);       SYM(dstT, g_dstT);
    SYM(stat, g_stat);     SYM(anum, g_anum);     SYM(adj, g_adj);
    SYM(adjd, g_adjd);     SYM(pos, g_pos);       SYM(vm, g_vm);
    SYM(xq, g_xq);         SYM(xk, g_xk);

    float* tr_emb = emb;
    float* det_emb = emb + (size_t)TM * DD;

    // ---- feature MLP (combined) ----
    k_feat1<<<TM / 4, 256>>>(tracks, W1, b1, h1);
    k_feat1<<<ND / 4, 256>>>(dets, W1, b1, h1 + (size_t)TM * DD);
    run_big(h1, 256, 0, W2, 256, 0, emb, 256, 0,
            TM + ND, 256, 256, 1, b2, nullptr, 0, nullptr, 0, F_BIAS, false);

    // ---- encoder (only r=0 outputs needed downstream) ----
    k_ln<<<TM / 8, 256>>>(tr_emb, ln);
    run_big(ln, 256, 0, Wqkv + 256, 768, 0, kv, 512, 0,
            TM, 512, 256, 1, nullptr, nullptr, 0, nullptr, 0, 0, false);
    run_big(ln, 2048, 0, Wqkv, 768, 0, q0, 256, 0,
            TT, 256, 256, 1, nullptr, nullptr, 0, nullptr, 0, 0, false);
    k_attn<<<TT, 256>>>(q0, kv, o0);
    run_big(o0, 256, 0, Wo, 256, 0, x1, 256, 0,
            TT, 256, 256, 1, nullptr, tr_emb, 2048, nullptr, 0, F_AUX, false);
    k_ln<<<TT / 8, 256>>>(x1, ln2);
    run_big(ln2, 256, 0, ff1, 1024, 0, ffh, 1024, 0,
            TT, 1024, 256, 1, nullptr, nullptr, 0, nullptr, 0, F_RELU, false);
    run_big(ffh, 1024, 0, ff2, 256, 0, ffout, 256, 0,
            TT, 256, 1024, 1, nullptr, nullptr, 0, nullptr, 0, 0, false);
    k_feat0<<<ROWS1, 256>>>(tr_emb, x1, ffout, det_emb, feat0, x);

    // ---- adjacency ----
    k_posvm<<<64, 256>>>(tracks, dets, tmarks, dmarks, pos, vm);
    k_adj<<<dim3(NN1, BB), 256>>>(pos, vm, adj);
    k_adjd<<<dim3(NNd, BB), 128>>>(pos, vm, adjd);

    // ---- main GAT x2 ----
    for (int l = 0; l < 2; l++) {
        run_big(x, 256, 0, gatW + (size_t)l * 65536, 256, 0, h, 256, 0,
                ROWS1, 256, 256, 1, nullptr, nullptr, 0, nullptr, 0, 0, false);
        k_srcdst<<<ROWS1, 256>>>(h, gata + (size_t)l * 512, src, dstT, NN1);
        k_rowstat<<<dim3(NN1, BB), 128>>>(src, dstT, adj, stat, anum, NN1);
        agg_fused<<<dim3(1, NN1 / 128, BB * HH), 256>>>(anum, stat, h, feat0, x, NN1);
    }

    // ---- main scores (dual xq/xk) ----
    run_big(x, 256, 0, clsWq, 256, 0, xq, 256, 0,
            ROWS1, 256, 256, 2, nullptr, nullptr, 0, nullptr, 0, 0, false,
            clsWk, xk, 1);
    run_big(xq, 256, (long long)NN1 * 256, xk, 256, (long long)NN1 * 256,
            out_scores, NN1, (long long)NN1 * NN1,
            NN1, NN1, 256, BB, nullptr, nullptr, 0,
            adj, (long long)NN1 * NN1, F_SIG, true);
    k_asso<<<(int)(((size_t)BB * 512 * 512) / 256), 256>>>(out_scores, out_asso);

    // ---- detection GAT x2 ----
    for (int l = 0; l < 2; l++) {
        const float* xin = (l == 0) ? det_emb : x;
        run_big(xin, 256, 0, dgatW + (size_t)l * 65536, 256, 0, h, 256, 0,
                ND, 256, 256, 1, nullptr, nullptr, 0, nullptr, 0, 0, false);
        k_srcdst<<<ND, 256>>>(h, dgata + (size_t)l * 512, src, dstT, NNd);
        k_rowstat<<<dim3(NNd, BB), 128>>>(src, dstT, adjd, stat, anum, NNd);
        agg_fused<<<dim3(1, NNd / 128, BB * HH), 256>>>(anum, stat, h, det_emb, x, NNd);
    }

    // ---- detection scores (dual xq/xk) ----
    run_big(x, 256, 0, clsWq + 65536, 256, 0, xq, 256, 0,
            ND, 256, 256, 2, nullptr, nullptr, 0, nullptr, 0, 0, false,
            clsWk + 65536, xk, 1);
    run_big(xq, 256, (long long)NNd * 256, xk, 256, (long long)NNd * 256,
            out_det, NNd, (long long)NNd * NNd,
            NNd, NNd, 256, BB, nullptr, nullptr, 0,
            adjd, (long long)NNd * NNd, F_SIG | F_DIAG, true);
}

// round 11
// speedup vs baseline: 4.2546x; 1.0971x over previous
#include <cuda_runtime.h>
#include <cuda_fp16.h>
#include <math.h>
#include <stdint.h>

// ---------------------------------------------------------------------------
// Problem dims
// ---------------------------------------------------------------------------
#define BB 16
#define MM 512
#define NNd 512
#define RR 8
#define DD 256
#define HH 4
#define NN1 1024
#define TM  (BB*MM*RR)    // 65536
#define TT  (BB*MM)       // 8192
#define ND  (BB*NNd)      // 8192
#define ROWS1 (BB*NN1)    // 16384

#define F_BIAS 1
#define F_RELU 2
#define F_AUX  4
#define F_SIG  8
#define F_DIAG 16
#define F_OUT16 32

// ---------------------------------------------------------------------------
// Scratch
// ---------------------------------------------------------------------------
__device__ __half g_h1[(TM+ND)*DD];
__device__ __half g_emb[(TM+ND)*DD];     // fp16: tr_emb | det_emb
__device__ __half g_lnb[TM*DD];
__device__ __half g_kv[TM*512];
__device__ __half g_q0[TT*DD];
__device__ __half g_o0[TT*DD];
__device__ float  g_x1[TT*DD];
__device__ __half g_ln2[TT*DD];
__device__ __half g_ffh[TT*1024];
__device__ float  g_ffout[TT*DD];
__device__ float  g_feat0[ROWS1*DD];
__device__ float  g_detf[ND*DD];
__device__ __half g_x[ROWS1*DD];
__device__ __half g_hh[ROWS1*DD];
__device__ float g_src[ROWS1*HH];
__device__ float g_dstT[BB*HH*NN1];
__device__ float2 g_stat[BB*HH*NN1];
__device__ __half g_anum[(size_t)BB*HH*NN1*NN1];
__device__ unsigned char g_adj[(size_t)BB*NN1*NN1];
__device__ unsigned char g_adjd[(size_t)BB*NNd*NNd];
__device__ float g_pos[BB*NN1*2];
__device__ unsigned char g_vm[BB*NN1];
__device__ __half g_xq[ROWS1*DD];
__device__ __half g_xk[ROWS1*DD];
// fp16 weights
__device__ __half g_w2h[256*256];
__device__ __half g_wqkvh[256*768];
__device__ __half g_woh[256*256];
__device__ __half g_ff1h[256*1024];
__device__ __half g_ff2h[1024*256];
__device__ __half g_gatWh[2*256*256];
__device__ __half g_dgatWh[2*256*256];
__device__ __half g_clsWqh[2*256*256];
__device__ __half g_clsWkh[2*256*256];

// ---------------------------------------------------------------------------
// helpers
// ---------------------------------------------------------------------------
__device__ __forceinline__ uint32_t pk(float lo, float hi) {
    __half2 v = __floats2half2_rn(lo, hi);
    return *reinterpret_cast<uint32_t*>(&v);
}
__device__ __forceinline__ void mma_f16(float* c, const uint32_t* a, const uint32_t* b) {
    asm volatile(
        "mma.sync.aligned.m16n8k16.row.col.f32.f16.f16.f32 "
        "{%0,%1,%2,%3}, {%4,%5,%6,%7}, {%8,%9}, {%0,%1,%2,%3};\n"
        : "+f"(c[0]), "+f"(c[1]), "+f"(c[2]), "+f"(c[3])
        : "r"(a[0]), "r"(a[1]), "r"(a[2]), "r"(a[3]), "r"(b[0]), "r"(b[1]));
}
__device__ __forceinline__ void ldm_x4(uint32_t* r, uint32_t addr) {
    asm volatile("ldmatrix.sync.aligned.m8n8.x4.shared.b16 {%0,%1,%2,%3}, [%4];"
        : "=r"(r[0]), "=r"(r[1]), "=r"(r[2]), "=r"(r[3]) : "r"(addr));
}
__device__ __forceinline__ void ldm_x4_t(uint32_t* r, uint32_t addr) {
    asm volatile("ldmatrix.sync.aligned.m8n8.x4.trans.shared.b16 {%0,%1,%2,%3}, [%4];"
        : "=r"(r[0]), "=r"(r[1]), "=r"(r[2]), "=r"(r[3]) : "r"(addr));
}
__device__ __forceinline__ uint32_t cvs(const void* p) {
    return (uint32_t)__cvta_generic_to_shared(p);
}

// fp32 -> fp16 conversion (weights), 4 per thread
__global__ void k_f2h(const float* __restrict__ in, __half* __restrict__ out, int n)
{
    int i = (blockIdx.x * 256 + threadIdx.x) * 4;
    if (i >= n) return;
    float4 v = *(const float4*)(in + i);
    uint2 p;
    p.x = pk(v.x, v.y);
    p.y = pk(v.z, v.w);
    *(uint2*)(out + i) = p;
}

// ---------------------------------------------------------------------------
// BIG GEMM (fp16 in / fp16-or-fp32 out): CTA 128x128, BK=16, 256 thr,
// warp 64x32, double-buffered, ldmatrix. A,B fp16 global.
// ---------------------------------------------------------------------------
template<bool TRANSB, int FLAGS>
__global__ __launch_bounds__(256, 2)
void tgemm_big(const __half* __restrict__ A, int lda, long long sA,
               const __half* __restrict__ B, int ldb, long long sB,
               void* __restrict__ Cv, int ldc, long long sC,
               int K,
               const float* __restrict__ bias,
               const __half* __restrict__ aux, int auxld,
               const unsigned char* __restrict__ adjp, long long sAdj,
               const __half* __restrict__ B2, void* __restrict__ C2v, int dual)
{
    int bz = blockIdx.z;
    if (dual && bz) { B = B2; Cv = C2v; bz = 0; }
    A += (long long)bz * sA;
    B += (long long)bz * sB;
    size_t coff = (size_t)((long long)bz * sC);
    if (FLAGS & F_SIG) adjp += (long long)bz * sAdj;

    int m0 = blockIdx.y * 128, n0 = blockIdx.x * 128;

    __shared__ uint32_t As[2][1536];
    __shared__ uint32_t Bs[2][1536];

    int tid = threadIdx.x;
    int arow = tid >> 1, ahalf = tid & 1;
    const __half* gA = A + (size_t)(m0 + arow) * lda + ahalf * 8;

    const __half* gB;
    int kp = tid >> 5, nq = tid & 31;
    if (!TRANSB) gB = B + (size_t)(2 * kp) * ldb + n0 + nq * 4;
    else         gB = B + (size_t)(n0 + arow) * ldb + ahalf * 8;

    int w = tid >> 5, l = tid & 31;
    int mbase = (w >> 2) * 64, nbase = (w & 3) * 32;
    int grp = l >> 2, tig = l & 3;

    int lrowA = ((l >> 3) & 1) * 8 + (l & 7);
    int khalf = l >> 4;
    uint32_t aBase[4];
    #pragma unroll
    for (int fm = 0; fm < 4; fm++)
        aBase[fm] = cvs(&As[0][(mbase + fm * 16 + lrowA) * 12 + khalf * 4]);
    uint32_t bBase[2];
    if (!TRANSB) {
        int krow = ((l >> 4) & 1) * 8 + (l & 7);
        int nblk = ((l >> 3) & 1) * 8;
        #pragma unroll
        for (int fp = 0; fp < 2; fp++)
            bBase[fp] = cvs(&Bs[0][krow * 68 + ((nbase + fp * 16 + nblk) >> 1)]);
    } else {
        #pragma unroll
        for (int fp = 0; fp < 2; fp++)
            bBase[fp] = cvs(&Bs[0][(nbase + fp * 16 + lrowA) * 12 + khalf * 4]);
    }

    float acc[4][4][4];
    #pragma unroll
    for (int i = 0; i < 4; i++)
        #pragma unroll
        for (int j = 0; j < 4; j++)
            #pragma unroll
            for (int q = 0; q < 4; q++) acc[i][j][q] = 0.f;

    int nk = K >> 4;
    uint4 ra;
    uint2 rb0, rb1;
    uint4 rbt;

    // stage 0
    ra = *(const uint4*)(gA);
    if (!TRANSB) { rb0 = *(const uint2*)(gB); rb1 = *(const uint2*)(gB + ldb); }
    else         { rbt = *(const uint4*)(gB); }
    {
        uint32_t* ap = &As[0][arow * 12 + ahalf * 4];
        ap[0] = ra.x; ap[1] = ra.y; ap[2] = ra.z; ap[3] = ra.w;
        if (!TRANSB) {
            int w0 = (2 * kp) * 68 + nq * 2;
            Bs[0][w0] = rb0.x; Bs[0][w0 + 1] = rb0.y;
            Bs[0][w0 + 68] = rb1.x; Bs[0][w0 + 69] = rb1.y;
        } else {
            uint32_t* bp = &Bs[0][arow * 12 + ahalf * 4];
            bp[0] = rbt.x; bp[1] = rbt.y; bp[2] = rbt.z; bp[3] = rbt.w;
        }
    }
    if (nk > 1) {
        ra = *(const uint4*)(gA + 16);
        if (!TRANSB) { rb0 = *(const uint2*)(gB + (size_t)16 * ldb); rb1 = *(const uint2*)(gB + (size_t)17 * ldb); }
        else         { rbt = *(const uint4*)(gB + 16); }
    }

    int s = 0;
    for (int i = 0; i < nk; i++) {
        __syncthreads();
        if (i + 1 < nk) {
            int d = s ^ 1;
            uint32_t* ap = &As[d][arow * 12 + ahalf * 4];
            ap[0] = ra.x; ap[1] = ra.y; ap[2] = ra.z; ap[3] = ra.w;
            if (!TRANSB) {
                int w0 = (2 * kp) * 68 + nq * 2;
                Bs[d][w0] = rb0.x; Bs[d][w0 + 1] = rb0.y;
                Bs[d][w0 + 68] = rb1.x; Bs[d][w0 + 69] = rb1.y;
            } else {
                uint32_t* bp = &Bs[d][arow * 12 + ahalf * 4];
                bp[0] = rbt.x; bp[1] = rbt.y; bp[2] = rbt.z; bp[3] = rbt.w;
            }
            if (i + 2 < nk) {
                int k0 = (i + 2) * 16;
                ra = *(const uint4*)(gA + k0);
                if (!TRANSB) {
                    rb0 = *(const uint2*)(gB + (size_t)k0 * ldb);
                    rb1 = *(const uint2*)(gB + (size_t)(k0 + 1) * ldb);
                } else {
                    rbt = *(const uint4*)(gB + k0);
                }
            }
        }
        uint32_t soff = (uint32_t)(s * 6144);
        uint32_t af[4][4];
        #pragma unroll
        for (int fm = 0; fm < 4; fm++) ldm_x4(af[fm], aBase[fm] + soff);
        uint32_t bfr[4][2];
        #pragma unroll
        for (int fp = 0; fp < 2; fp++) {
            uint32_t t4[4];
            if (!TRANSB) ldm_x4_t(t4, bBase[fp] + soff);
            else         ldm_x4(t4, bBase[fp] + soff);
            bfr[fp * 2][0] = t4[0]; bfr[fp * 2 + 1][0] = t4[1];
            bfr[fp * 2][1] = t4[2]; bfr[fp * 2 + 1][1] = t4[3];
        }
        #pragma unroll
        for (int fm = 0; fm < 4; fm++)
            #pragma unroll
            for (int fn = 0; fn < 4; fn++)
                mma_f16(acc[fm][fn], af[fm], bfr[fn]);
        s ^= 1;
    }

    // epilogue
    #pragma unroll
    for (int fm = 0; fm < 4; fm++) {
        int row0 = m0 + mbase + fm * 16 + grp;
        #pragma unroll
        for (int fn = 0; fn < 4; fn++) {
            int col = n0 + nbase + fn * 8 + 2 * tig;
            float v0 = acc[fm][fn][0], v1 = acc[fm][fn][1];
            float v2 = acc[fm][fn][2], v3 = acc[fm][fn][3];
            if (FLAGS & F_BIAS) {
                float bb0 = bias[col], bb1 = bias[col + 1];
                v0 += bb0; v1 += bb1; v2 += bb0; v3 += bb1;
            }
            if (FLAGS & F_RELU) {
                v0 = fmaxf(v0, 0.f); v1 = fmaxf(v1, 0.f);
                v2 = fmaxf(v2, 0.f); v3 = fmaxf(v3, 0.f);
            }
            if (FLAGS & F_AUX) {
                float2 a0 = __half22float2(*(const __half2*)(aux + (size_t)row0 * auxld + col));
                float2 a8 = __half22float2(*(const __half2*)(aux + (size_t)(row0 + 8) * auxld + col));
                v0 += a0.x; v1 += a0.y; v2 += a8.x; v3 += a8.y;
            }
            if (FLAGS & F_SIG) {
                const unsigned char* q0p = adjp + (size_t)row0 * ldc + col;
                const unsigned char* q8p = adjp + (size_t)(row0 + 8) * ldc + col;
                v0 = q0p[0] ? 1.f / (1.f + __expf(-v0 * 0.0625f)) : 0.f;
                v1 = q0p[1] ? 1.f / (1.f + __expf(-v1 * 0.0625f)) : 0.f;
                v2 = q8p[0] ? 1.f / (1.f + __expf(-v2 * 0.0625f)) : 0.f;
                v3 = q8p[1] ? 1.f / (1.f + __expf(-v3 * 0.0625f)) : 0.f;
                if (FLAGS & F_DIAG) {
                    if (row0 == col) v0 = 0.f;
                    if (row0 == col + 1) v1 = 0.f;
                    if (row0 + 8 == col) v2 = 0.f;
                    if (row0 + 8 == col + 1) v3 = 0.f;
                }
            }
            if (FLAGS & F_OUT16) {
                __half* Ch = (__half*)Cv + coff;
                *(uint32_t*)&Ch[(size_t)row0 * ldc + col] = pk(v0, v1);
                *(uint32_t*)&Ch[(size_t)(row0 + 8) * ldc + col] = pk(v2, v3);
            } else {
                float* C = (float*)Cv + coff;
                *(float2*)&C[(size_t)row0 * ldc + col] = make_float2(v0, v1);
                *(float2*)&C[(size_t)(row0 + 8) * ldc + col] = make_float2(v2, v3);
            }
        }
    }
}

// ---------------------------------------------------------------------------
// GAT aggregation: x(fp16) = 0.5*elu(inv*(anum @ h)) + 0.5*aux(fp32).
// anum fp16, h fp16 -> direct-copy staging. CTA 128x64, warp 32x32.
// ---------------------------------------------------------------------------
__global__ __launch_bounds__(256)
void agg_fused(const __half* __restrict__ anum, const float2* __restrict__ stat,
               const __half* __restrict__ hmat,
               const float* __restrict__ aux, __half* __restrict__ xout, int NN)
{
    int z = blockIdx.z;
    int b = z >> 2, h = z & 3;
    const __half* B = hmat + (size_t)b * NN * 256 + h * 64;
    __half* C = xout + (size_t)b * NN * 256 + h * 64;
    const float* auxp = aux + (size_t)b * NN * 256 + h * 64;
    const float2* statz = stat + (size_t)z * NN;

    int m0 = blockIdx.y * 128;
    __shared__ uint32_t As[2][1536];
    __shared__ uint32_t Bs[2][576];
    int tid = threadIdx.x;

    int arow = tid >> 1, ahalf = tid & 1;
    const __half* gA = anum + ((size_t)z * NN + m0 + arow) * NN + ahalf * 8;

    int kp = tid >> 5, nq = tid & 31;
    const __half* gB = B + (size_t)(2 * kp) * 256 + 2 * nq;

    int w = tid >> 5, l = tid & 31;
    int wm = w >> 1, wn = w & 1;
    int mrow = wm * 32, ncol = wn * 32;
    int grp = l >> 2, tig = l & 3;

    int lrowA = ((l >> 3) & 1) * 8 + (l & 7);
    int khalf = l >> 4;
    uint32_t aBase[2];
    #pragma unroll
    for (int fm = 0; fm < 2; fm++)
        aBase[fm] = cvs(&As[0][(mrow + fm * 16 + lrowA) * 12 + khalf * 4]);
    int krow = ((l >> 4) & 1) * 8 + (l & 7);
    int nblk = ((l >> 3) & 1) * 8;
    uint32_t bBase[2];
    #pragma unroll
    for (int fp = 0; fp < 2; fp++)
        bBase[fp] = cvs(&Bs[0][krow * 36 + ((ncol + fp * 16 + nblk) >> 1)]);

    float acc[2][4][4];
    #pragma unroll
    for (int i = 0; i < 2; i++)
        #pragma unroll
        for (int j = 0; j < 4; j++)
            #pragma unroll
            for (int q = 0; q < 4; q++) acc[i][j][q] = 0.f;

    int nk = NN >> 4;
    uint4 ra;
    uint32_t rb0, rb1;

    ra  = *(const uint4*)(gA);
    rb0 = *(const uint32_t*)(gB);
    rb1 = *(const uint32_t*)(gB + 256);
    {
        uint32_t* ap = &As[0][arow * 12 + ahalf * 4];
        ap[0] = ra.x; ap[1] = ra.y; ap[2] = ra.z; ap[3] = ra.w;
        Bs[0][(2 * kp) * 36 + nq]     = rb0;
        Bs[0][(2 * kp + 1) * 36 + nq] = rb1;
    }
    if (nk > 1) {
        ra  = *(const uint4*)(gA + 16);
        rb0 = *(const uint32_t*)(gB + 16 * 256);
        rb1 = *(const uint32_t*)(gB + 17 * 256);
    }

    int s = 0;
    for (int i = 0; i < nk; i++) {
        __syncthreads();
        if (i + 1 < nk) {
            int d = s ^ 1;
            uint32_t* ap = &As[d][arow * 12 + ahalf * 4];
            ap[0] = ra.x; ap[1] = ra.y; ap[2] = ra.z; ap[3] = ra.w;
            Bs[d][(2 * kp) * 36 + nq]     = rb0;
            Bs[d][(2 * kp + 1) * 36 + nq] = rb1;
            if (i + 2 < nk) {
                int k0 = (i + 2) * 16;
                ra  = *(const uint4*)(gA + k0);
                rb0 = *(const uint32_t*)(gB + (size_t)k0 * 256);
                rb1 = *(const uint32_t*)(gB + (size_t)(k0 + 1) * 256);
            }
        }
        uint32_t sa = (uint32_t)(s * 6144);
        uint32_t sbo = (uint32_t)(s * 2304);
        uint32_t af[2][4];
        #pragma unroll
        for (int fm = 0; fm < 2; fm++) ldm_x4(af[fm], aBase[fm] + sa);
        uint32_t bfr[4][2];
        #pragma unroll
        for (int fp = 0; fp < 2; fp++) {
            uint32_t t4[4];
            ldm_x4_t(t4, bBase[fp] + sbo);
            bfr[fp * 2][0] = t4[0]; bfr[fp * 2 + 1][0] = t4[1];
            bfr[fp * 2][1] = t4[2]; bfr[fp * 2 + 1][1] = t4[3];
        }
        #pragma unroll
        for (int fm = 0; fm < 2; fm++)
            #pragma unroll
            for (int fn = 0; fn < 4; fn++)
                mma_f16(acc[fm][fn], af[fm], bfr[fn]);
        s ^= 1;
    }

    #pragma unroll
    for (int fm = 0; fm < 2; fm++) {
        int row = m0 + mrow + fm * 16 + grp;
        float inv0 = statz[row].y;
        float inv8 = statz[row + 8].y;
        #pragma unroll
        for (int fn = 0; fn < 4; fn++) {
            int col = ncol + fn * 8 + 2 * tig;
            float v0 = acc[fm][fn][0] * inv0, v1 = acc[fm][fn][1] * inv0;
            float v2 = acc[fm][fn][2] * inv8, v3 = acc[fm][fn][3] * inv8;
            v0 = (v0 > 0.f) ? v0 : expm1f(v0);
            v1 = (v1 > 0.f) ? v1 : expm1f(v1);
            v2 = (v2 > 0.f) ? v2 : expm1f(v2);
            v3 = (v3 > 0.f) ? v3 : expm1f(v3);
            float2 x0 = *(const float2*)&auxp[(size_t)row * 256 + col];
            float2 x1 = *(const float2*)&auxp[(size_t)(row + 8) * 256 + col];
            *(uint32_t*)&C[(size_t)row * 256 + col] =
                pk(0.5f * v0 + 0.5f * x0.x, 0.5f * v1 + 0.5f * x0.y);
            *(uint32_t*)&C[(size_t)(row + 8) * 256 + col] =
                pk(0.5f * v2 + 0.5f * x1.x, 0.5f * v3 + 0.5f * x1.y);
        }
    }
}

// ---------------------------------------------------------------------------
// Small kernels
// ---------------------------------------------------------------------------
__global__ void k_feat1(const float* __restrict__ x, const float* __restrict__ W1,
                        const float* __restrict__ b1, __half* __restrict__ out)
{
    int tid = threadIdx.x;
    size_t row = (size_t)blockIdx.x * 4 + (tid >> 6);
    int c4 = (tid & 63) * 4;
    const float4 xr = *(const float4*)(x + row * 4);
    float4 v = *(const float4*)(b1 + c4);
    float4 w0 = *(const float4*)(W1 + c4);
    float4 w1 = *(const float4*)(W1 + 256 + c4);
    float4 w2 = *(const float4*)(W1 + 512 + c4);
    float4 w3 = *(const float4*)(W1 + 768 + c4);
    v.x += xr.x * w0.x + xr.y * w1.x + xr.z * w2.x + xr.w * w3.x;
    v.y += xr.x * w0.y + xr.y * w1.y + xr.z * w2.y + xr.w * w3.y;
    v.z += xr.x * w0.z + xr.y * w1.z + xr.z * w2.z + xr.w * w3.z;
    v.w += xr.x * w0.w + xr.y * w1.w + xr.z * w2.w + xr.w * w3.w;
    v.x = (v.x > 0.f) ? v.x : (__expf(v.x) - 1.f);
    v.y = (v.y > 0.f) ? v.y : (__expf(v.y) - 1.f);
    v.z = (v.z > 0.f) ? v.z : (__expf(v.z) - 1.f);
    v.w = (v.w > 0.f) ? v.w : (__expf(v.w) - 1.f);
    uint2 p;
    p.x = pk(v.x, v.y);
    p.y = pk(v.z, v.w);
    *(uint2*)(out + row * 256 + c4) = p;
}

// LayerNorm fp16 -> fp16: one warp per row, 8 rows per block
__global__ void k_ln_h(const __half* __restrict__ in, __half* __restrict__ out)
{
    int w = threadIdx.x >> 5, lane = threadIdx.x & 31;
    size_t row = (size_t)blockIdx.x * 8 + w;
    const uint4* ip = (const uint4*)(in + row * 256);
    uint4 u = ip[lane];
    float2 f0 = __half22float2(*(__half2*)&u.x);
    float2 f1 = __half22float2(*(__half2*)&u.y);
    float2 f2 = __half22float2(*(__half2*)&u.z);
    float2 f3 = __half22float2(*(__half2*)&u.w);
    float a = f0.x + f0.y + f1.x + f1.y + f2.x + f2.y + f3.x + f3.y;
    float b = f0.x*f0.x + f0.y*f0.y + f1.x*f1.x + f1.y*f1.y
            + f2.x*f2.x + f2.y*f2.y + f3.x*f3.x + f3.y*f3.y;
    #pragma unroll
    for (int o = 16; o; o >>= 1) {
        a += __shfl_xor_sync(0xffffffff, a, o);
        b += __shfl_xor_sync(0xffffffff, b, o);
    }
    float mean = a * (1.f / 256.f);
    float var = b * (1.f / 256.f) - mean * mean;
    float rstd = rsqrtf(var + 1e-5f);
    uint4 r;
    r.x = pk((f0.x - mean) * rstd, (f0.y - mean) * rstd);
    r.y = pk((f1.x - mean) * rstd, (f1.y - mean) * rstd);
    r.z = pk((f2.x - mean) * rstd, (f2.y - mean) * rstd);
    r.w = pk((f3.x - mean) * rstd, (f3.y - mean) * rstd);
    ((uint4*)(out + row * 256))[lane] = r;
}

// LayerNorm fp32 -> fp16
__global__ void k_ln_f(const float* __restrict__ in, __half* __restrict__ out)
{
    int w = threadIdx.x >> 5, lane = threadIdx.x & 31;
    size_t row = (size_t)blockIdx.x * 8 + w;
    const float4* ip = (const float4*)(in + row * 256);
    float4 v0 = ip[lane], v1 = ip[lane + 32];
    float a = v0.x + v0.y + v0.z + v0.w + v1.x + v1.y + v1.z + v1.w;
    float b = v0.x*v0.x + v0.y*v0.y + v0.z*v0.z + v0.w*v0.w
            + v1.x*v1.x + v1.y*v1.y + v1.z*v1.z + v1.w*v1.w;
    #pragma unroll
    for (int o = 16; o; o >>= 1) {
        a += __shfl_xor_sync(0xffffffff, a, o);
        b += __shfl_xor_sync(0xffffffff, b, o);
    }
    float mean = a * (1.f / 256.f);
    float var = b * (1.f / 256.f) - mean * mean;
    float rstd = rsqrtf(var + 1e-5f);
    uint2 p0, p1;
    p0.x = pk((v0.x - mean) * rstd, (v0.y - mean) * rstd);
    p0.y = pk((v0.z - mean) * rstd, (v0.w - mean) * rstd);
    p1.x = pk((v1.x - mean) * rstd, (v1.y - mean) * rstd);
    p1.y = pk((v1.z - mean) * rstd, (v1.w - mean) * rstd);
    *(uint2*)(out + row * 256 + lane * 4) = p0;
    *(uint2*)(out + row * 256 + 128 + lane * 4) = p1;
}

// tiny attention (fp16 in/out), single barrier
__global__ void k_attn(const __half* __restrict__ q0, const __half* __restrict__ kv,
                       __half* __restrict__ o0)
{
    size_t t = blockIdx.x;
    int d = threadIdx.x;
    int w = d >> 5, lane = d & 31, h = d >> 6;
    __shared__ float red[8][8];
    const __half* kvb = kv + t * 8 * 512;
    float qd = __half2float(q0[t * 256 + d]);
    #pragma unroll
    for (int s = 0; s < 8; s++) {
        float v = qd * __half2float(kvb[s * 512 + d]);
        #pragma unroll
        for (int o = 16; o; o >>= 1) v += __shfl_xor_sync(0xffffffff, v, o);
        if (lane == 0) red[w][s] = v;
    }
    __syncthreads();
    float lg[8];
    float m = -1e30f;
    #pragma unroll
    for (int s = 0; s < 8; s++) {
        lg[s] = (red[2 * h][s] + red[2 * h + 1][s]) * 0.125f;
        m = fmaxf(m, lg[s]);
    }
    float sum = 0.f;
    #pragma unroll
    for (int s = 0; s < 8; s++) { lg[s] = __expf(lg[s] - m); sum += lg[s]; }
    float inv = 1.f / sum;
    float o = 0.f;
    #pragma unroll
    for (int s = 0; s < 8; s++) o += lg[s] * inv * __half2float(kvb[s * 512 + 256 + d]);
    o0[t * 256 + d] = __float2half(o);
}

// feat0 (fp32) + x (fp16) + det fp32 copy
__global__ void k_feat0(const __half* __restrict__ tr_emb, const float* __restrict__ x1,
                        const float* __restrict__ ffout, const __half* __restrict__ det_emb,
                        float* __restrict__ feat0, __half* __restrict__ x,
                        float* __restrict__ detf)
{
    size_t idx = (size_t)blockIdx.x * 256 + threadIdx.x;
    int d = idx & 255;
    size_t row = idx >> 8;
    int i = row & 1023;
    int b = row >> 10;
    float v;
    if (i < 512) {
        size_t t = (size_t)b * 512 + i;
        v = __half2float(tr_emb[t * 2048 + d]) + 0.9f * (x1[t * 256 + d] + ffout[t * 256 + d]);
    } else {
        size_t t = (size_t)b * 512 + (i - 512);
        v = __half2float(det_emb[t * 256 + d]);
        detf[t * 256 + d] = v;
    }
    feat0[idx] = v;
    x[idx] = __float2half(v);
}

__global__ void k_posvm(const float* __restrict__ tracks, const float* __restrict__ dets,
                        const int* __restrict__ tmarks, const int* __restrict__ dmarks,
                        float* __restrict__ pos, unsigned char* __restrict__ vm)
{
    int idx = blockIdx.x * 256 + threadIdx.x;
    if (idx >= BB * NN1) return;
    int b = idx >> 10, i = idx & 1023;
    float x, y; unsigned char v;
    if (i < 512) {
        const float* p = tracks + ((size_t)(b * 512 + i)) * 8 * 4;
        x = p[0]; y = p[1];
        v = (i < tmarks[b]);
    } else {
        int n = i - 512;
        const float* p = dets + ((size_t)(b * 512 + n)) * 4;
        x = p[0]; y = p[1];
        v = (n < dmarks[b]);
    }
    pos[idx * 2] = x; pos[idx * 2 + 1] = y; vm[idx] = v;
}

__global__ void k_adj(const float* __restrict__ pos, const unsigned char* __restrict__ vm,
                      unsigned char* __restrict__ adj)
{
    int i = blockIdx.x, b = blockIdx.y;
    size_t base = (size_t)b * NN1;
    const float2* p2 = (const float2*)pos;
    float2 pi = p2[base + i];
    unsigned char vi = vm[base + i];
    int j0 = threadIdx.x * 4;
    uchar4 r;
    unsigned char* rp = &r.x;
    #pragma unroll
    for (int u = 0; u < 4; u++) {
        int j = j0 + u;
        float2 pj = p2[base + j];
        float dx = pi.x - pj.x, dy = pi.y - pj.y;
        rp[u] = (unsigned char)((dx * dx + dy * dy < 4.0f) && vi && vm[base + j]);
    }
    ((uchar4*)(adj + ((size_t)b * NN1 + i) * NN1))[threadIdx.x] = r;
}

__global__ void k_adjd(const float* __restrict__ pos, const unsigned char* __restrict__ vm,
                       unsigned char* __restrict__ adjd)
{
    int i = blockIdx.x, b = blockIdx.y;
    size_t base = (size_t)b * NN1 + 512;
    const float2* p2 = (const float2*)pos;
    float2 pi = p2[base + i];
    unsigned char vi = vm[base + i];
    int j0 = threadIdx.x * 4;
    uchar4 r;
    unsigned char* rp = &r.x;
    #pragma unroll
    for (int u = 0; u < 4; u++) {
        int j = j0 + u;
        float2 pj = p2[base + j];
        float dx = pi.x - pj.x, dy = pi.y - pj.y;
        rp[u] = (unsigned char)((dx * dx + dy * dy < 4.0f) && vi && vm[base + j]);
    }
    ((uchar4*)(adjd + ((size_t)b * NNd + i) * NNd))[threadIdx.x] = r;
}

__global__ void k_srcdst(const __half* __restrict__ Hm, const float* __restrict__ a0,
                         float* __restrict__ src, float* __restrict__ dstT, int NN)
{
    size_t row = blockIdx.x;
    int d = threadIdx.x;
    float hv = __half2float(Hm[row * 256 + d]);
    float s = hv * a0[d];
    float t2 = hv * a0[256 + d];
    #pragma unroll
    for (int o = 16; o; o >>= 1) {
        s  += __shfl_xor_sync(0xffffffff, s, o);
        t2 += __shfl_xor_sync(0xffffffff, t2, o);
    }
    __shared__ float ps[8], pt[8];
    if ((d & 31) == 0) { ps[d >> 5] = s; pt[d >> 5] = t2; }
    __syncthreads();
    if (d < 4) {
        int b = (int)(row / NN);
        int i = (int)(row - (size_t)b * NN);
        src[row * 4 + d] = ps[2 * d] + ps[2 * d + 1];
        dstT[((size_t)b * 4 + d) * NN + i] = pt[2 * d] + pt[2 * d + 1];
    }
}

__global__ void k_rowstat(const float* __restrict__ src, const float* __restrict__ dstT,
                          const unsigned char* __restrict__ adj, float2* __restrict__ stat,
                          __half* __restrict__ anum, int NN)
{
    int i = blockIdx.x, b = blockIdx.y;
    int h = threadIdx.x >> 5, lane = threadIdx.x & 31;
    int z = b * 4 + h;
    float s = src[((size_t)b * NN + i) * 4 + h];
    const uchar4* adjrow = (const uchar4*)(adj + ((size_t)b * NN + i) * NN);
    const float4* dsth = (const float4*)(dstT + ((size_t)z) * NN);
    __half* arow = anum + ((size_t)z * NN + i) * NN;
    int nq = NN >> 2;
    float mx = -1e30f;
    for (int jq = lane; jq < nq; jq += 32) {
        uchar4 a4 = adjrow[jq];
        float4 d4 = dsth[jq];
        float e0 = s + d4.x; e0 = e0 > 0.f ? e0 : 0.2f * e0; e0 = a4.x ? e0 : -1e9f;
        float e1 = s + d4.y; e1 = e1 > 0.f ? e1 : 0.2f * e1; e1 = a4.y ? e1 : -1e9f;
        float e2 = s + d4.z; e2 = e2 > 0.f ? e2 : 0.2f * e2; e2 = a4.z ? e2 : -1e9f;
        float e3 = s + d4.w; e3 = e3 > 0.f ? e3 : 0.2f * e3; e3 = a4.w ? e3 : -1e9f;
        mx = fmaxf(mx, fmaxf(fmaxf(e0, e1), fmaxf(e2, e3)));
    }
    #pragma unroll
    for (int o = 16; o; o >>= 1) mx = fmaxf(mx, __shfl_xor_sync(0xffffffff, mx, o));
    float sum = 0.f;
    for (int jq = lane; jq < nq; jq += 32) {
        uchar4 a4 = adjrow[jq];
        float4 d4 = dsth[jq];
        float e0 = s + d4.x; e0 = e0 > 0.f ? e0 : 0.2f * e0; e0 = a4.x ? e0 : -1e9f;
        float e1 = s + d4.y; e1 = e1 > 0.f ? e1 : 0.2f * e1; e1 = a4.y ? e1 : -1e9f;
        float e2 = s + d4.z; e2 = e2 > 0.f ? e2 : 0.2f * e2; e2 = a4.z ? e2 : -1e9f;
        float e3 = s + d4.w; e3 = e3 > 0.f ? e3 : 0.2f * e3; e3 = a4.w ? e3 : -1e9f;
        float n0 = __expf(e0 - mx), n1 = __expf(e1 - mx);
        float n2 = __expf(e2 - mx), n3 = __expf(e3 - mx);
        sum += n0 + n1 + n2 + n3;
        uint2 pkd;
        pkd.x = pk(n0, n1);
        pkd.y = pk(n2, n3);
        *(uint2*)(arow + jq * 4) = pkd;
    }
    #pragma unroll
    for (int o = 16; o; o >>= 1) sum += __shfl_xor_sync(0xffffffff, sum, o);
    if (lane == 0)
        stat[(size_t)z * NN + i] = make_float2(mx, 1.f / sum);
}

__global__ void k_asso(const float* __restrict__ scores, float* __restrict__ out)
{
    size_t idx = (size_t)blockIdx.x * 256 + threadIdx.x;
    int j = idx & 511;
    size_t r = idx >> 9;
    int m = r & 511;
    int b = (int)(r >> 9);
    out[idx] = scores[(((size_t)b * 1024 + m) * 1024) + 512 + j];
}

// ---------------------------------------------------------------------------
// Host side
// ---------------------------------------------------------------------------
static void run_big(const __half* A, int lda, long long sA,
                    const __half* B, int ldb, long long sB,
                    void* C, int ldc, long long sC,
                    int M, int N, int K, int batch,
                    const float* bias, const __half* aux, int auxld,
                    const unsigned char* adjp, long long sAdj,
                    int flags, bool transb,
                    const __half* B2 = nullptr, void* C2 = nullptr, int dual = 0)
{
    dim3 g(N / 128, M / 128, batch);
#define CALLBIG(T, F) tgemm_big<T, F><<<g, 256>>>(A, lda, sA, B, ldb, sB, \
        C, ldc, sC, K, bias, aux, auxld, adjp, sAdj, B2, C2, dual)
    if (!transb) {
        if (flags == (F_BIAS | F_OUT16))      CALLBIG(false, F_BIAS | F_OUT16);
        else if (flags == F_OUT16)            CALLBIG(false, F_OUT16);
        else if (flags == F_AUX)              CALLBIG(false, F_AUX);
        else if (flags == (F_RELU | F_OUT16)) CALLBIG(false, F_RELU | F_OUT16);
        else                                  CALLBIG(false, 0);
    } else {
        if (flags == F_SIG)                   CALLBIG(true, F_SIG);
        else                                  CALLBIG(true, F_SIG | F_DIAG);
    }
#undef CALLBIG
}

#define SYM(p, s) cudaGetSymbolAddress((void**)&p, s)

extern "C" void kernel_launch(void* const* d_in, const int* in_sizes, int n_in,
                              void* d_out, int out_size)
{
    (void)in_sizes; (void)n_in; (void)out_size;
    const float* tracks = (const float*)d_in[0];
    const float* dets   = (const float*)d_in[1];
    const int* tmarks   = (const int*)d_in[2];
    const int* dmarks   = (const int*)d_in[3];
    const float* W1     = (const float*)d_in[4];
    const float* b1     = (const float*)d_in[5];
    const float* W2     = (const float*)d_in[6];
    const float* b2     = (const float*)d_in[7];
    const float* Wqkv   = (const float*)d_in[8];
    const float* Wo     = (const float*)d_in[9];
    const float* ff1    = (const float*)d_in[10];
    const float* ff2    = (const float*)d_in[11];
    const float* gatW   = (const float*)d_in[12];
    const float* gata   = (const float*)d_in[13];
    const float* dgatW  = (const float*)d_in[14];
    const float* dgata  = (const float*)d_in[15];
    const float* clsWq  = (const float*)d_in[16];
    const float* clsWk  = (const float*)d_in[17];

    float* out = (float*)d_out;
    float* out_scores = out;
    float* out_det    = out + (size_t)BB * NN1 * NN1;
    float* out_asso   = out_det + (size_t)BB * NNd * NNd;

    __half *h1, *emb, *lnb, *kv, *q0, *o0, *ln2, *ffh, *x, *hh, *xq, *xk, *anum;
    __half *w2h, *wqkvh, *woh, *ff1h, *ff2h, *gatWh, *dgatWh, *clsWqh, *clsWkh;
    float *x1, *ffout, *feat0, *detf, *src, *dstT, *pos;
    float2* stat;
    unsigned char *adj, *adjd, *vm;
    SYM(h1, g_h1);         SYM(emb, g_emb);       SYM(lnb, g_lnb);
    SYM(kv, g_kv);         SYM(q0, g_q0);         SYM(o0, g_o0);
    SYM(x1, g_x1);         SYM(ln2, g_ln2);       SYM(ffh, g_ffh);
    SYM(ffout, g_ffout);   SYM(feat0, g_feat0);   SYM(detf, g_detf);
    SYM(x, g_x);           SYM(hh, g_hh);         SYM(src, g_src);
    SYM(dstT, g_dstT);     SYM(stat, g_stat);     SYM(anum, g_anum);
    SYM(adj, g_adj);       SYM(adjd, g_adjd);     SYM(pos, g_pos);
    SYM(vm, g_vm);         SYM(xq, g_xq);         SYM(xk, g_xk);
    SYM(w2h, g_w2h);       SYM(wqkvh, g_wqkvh);   SYM(woh, g_woh);
    SYM(ff1h, g_ff1h);     SYM(ff2h, g_ff2h);     SYM(gatWh, g_gatWh);
    SYM(dgatWh, g_dgatWh); SYM(clsWqh, g_clsWqh); SYM(clsWkh, g_clsWkh);

    __half* tr_emb = emb;
    __half* det_emb = emb + (size_t)TM * DD;

    // ---- weight fp32 -> fp16 ----
    k_f2h<<<64, 256>>>(W2, w2h, 65536);
    k_f2h<<<192, 256>>>(Wqkv, wqkvh, 196608);
    k_f2h<<<64, 256>>>(Wo, woh, 65536);
    k_f2h<<<256, 256>>>(ff1, ff1h, 262144);
    k_f2h<<<256, 256>>>(ff2, ff2h, 262144);
    k_f2h<<<128, 256>>>(gatW, gatWh, 131072);
    k_f2h<<<128, 256>>>(dgatW, dgatWh, 131072);
    k_f2h<<<128, 256>>>(clsWq, clsWqh, 131072);
    k_f2h<<<128, 256>>>(clsWk, clsWkh, 131072);

    // ---- feature MLP (combined) ----
    k_feat1<<<TM / 4, 256>>>(tracks, W1, b1, h1);
    k_feat1<<<ND / 4, 256>>>(dets, W1, b1, h1 + (size_t)TM * DD);
    run_big(h1, 256, 0, w2h, 256, 0, emb, 256, 0,
            TM + ND, 256, 256, 1, b2, nullptr, 0, nullptr, 0, F_BIAS | F_OUT16, false);

    // ---- encoder (only r=0 outputs needed downstream) ----
    k_ln_h<<<TM / 8, 256>>>(tr_emb, lnb);
    run_big(lnb, 256, 0, wqkvh + 256, 768, 0, kv, 512, 0,
            TM, 512, 256, 1, nullptr, nullptr, 0, nullptr, 0, F_OUT16, false);
    run_big(lnb, 2048, 0, wqkvh, 768, 0, q0, 256, 0,
            TT, 256, 256, 1, nullptr, nullptr, 0, nullptr, 0, F_OUT16, false);
    k_attn<<<TT, 256>>>(q0, kv, o0);
    run_big(o0, 256, 0, woh, 256, 0, x1, 256, 0,
            TT, 256, 256, 1, nullptr, tr_emb, 2048, nullptr, 0, F_AUX, false);
    k_ln_f<<<TT / 8, 256>>>(x1, ln2);
    run_big(ln2, 256, 0, ff1h, 1024, 0, ffh, 1024, 0,
            TT, 1024, 256, 1, nullptr, nullptr, 0, nullptr, 0, F_RELU | F_OUT16, false);
    run_big(ffh, 1024, 0, ff2h, 256, 0, ffout, 256, 0,
            TT, 256, 1024, 1, nullptr, nullptr, 0, nullptr, 0, 0, false);
    k_feat0<<<ROWS1, 256>>>(tr_emb, x1, ffout, det_emb, feat0, x, detf);

    // ---- adjacency ----
    k_posvm<<<64, 256>>>(tracks, dets, tmarks, dmarks, pos, vm);
    k_adj<<<dim3(NN1, BB), 256>>>(pos, vm, adj);
    k_adjd<<<dim3(NNd, BB), 128>>>(pos, vm, adjd);

    // ---- main GAT x2 ----
    for (int l = 0; l < 2; l++) {
        run_big(x, 256, 0, gatWh + (size_t)l * 65536, 256, 0, hh, 256, 0,
                ROWS1, 256, 256, 1, nullptr, nullptr, 0, nullptr, 0, F_OUT16, false);
        k_srcdst<<<ROWS1, 256>>>(hh, gata + (size_t)l * 512, src, dstT, NN1);
        k_rowstat<<<dim3(NN1, BB), 128>>>(src, dstT, adj, stat, anum, NN1);
        agg_fused<<<dim3(1, NN1 / 128, BB * HH), 256>>>(anum, stat, hh, feat0, x, NN1);
    }

    // ---- main scores (dual xq/xk fp16) ----
    run_big(x, 256, 0, clsWqh, 256, 0, xq, 256, 0,
            ROWS1, 256, 256, 2, nullptr, nullptr, 0, nullptr, 0, F_OUT16, false,
            clsWkh, xk, 1);
    run_big(xq, 256, (long long)NN1 * 256, xk, 256, (long long)NN1 * 256,
            out_scores, NN1, (long long)NN1 * NN1,
            NN1, NN1, 256, BB, nullptr, nullptr, 0,
            adj, (long long)NN1 * NN1, F_SIG, true);
    k_asso<<<(int)(((size_t)BB * 512 * 512) / 256), 256>>>(out_scores, out_asso);

    // ---- detection GAT x2 ----
    for (int l = 0; l < 2; l++) {
        const __half* xin = (l == 0) ? det_emb : x;
        run_big(xin, 256, 0, dgatWh + (size_t)l * 65536, 256, 0, hh, 256, 0,
                ND, 256, 256, 1, nullptr, nullptr, 0, nullptr, 0, F_OUT16, false);
        k_srcdst<<<ND, 256>>>(hh, dgata + (size_t)l * 512, src, dstT, NNd);
        k_rowstat<<<dim3(NNd, BB), 128>>>(src, dstT, adjd, stat, anum, NNd);
        agg_fused<<<dim3(1, NNd / 128, BB * HH), 256>>>(anum, stat, hh, detf, x, NNd);
    }

    // ---- detection scores (dual xq/xk) ----
    run_big(x, 256, 0, clsWqh + 65536, 256, 0, xq, 256, 0,
            ND, 256, 256, 2, nullptr, nullptr, 0, nullptr, 0, F_OUT16, false,
            clsWkh + 65536, xk, 1);
    run_big(xq, 256, (long long)NNd * 256, xk, 256, (long long)NNd * 256,
            out_det, NNd, (long long)NNd * NNd,
            NNd, NNd, 256, BB, nullptr, nullptr, 0,
            adjd, (long long)NNd * NNd, F_SIG | F_DIAG, true);
}

// round 12
// speedup vs baseline: 4.7903x; 1.1259x over previous
#include <cuda_runtime.h>
#include <cuda_fp16.h>
#include <math.h>
#include <stdint.h>

// ---------------------------------------------------------------------------
// Problem dims
// ---------------------------------------------------------------------------
#define BB 16
#define MM 512
#define NNd 512
#define RR 8
#define DD 256
#define HH 4
#define NN1 1024
#define TM  (BB*MM*RR)    // 65536
#define TT  (BB*MM)       // 8192
#define ND  (BB*NNd)      // 8192
#define ROWS1 (BB*NN1)    // 16384

#define F_BIAS 1
#define F_RELU 2
#define F_AUX  4
#define F_SIG  8
#define F_DIAG 16
#define F_OUT16 32

// ---------------------------------------------------------------------------
// Scratch
// ---------------------------------------------------------------------------
__device__ __half g_h1[(TM+ND)*DD];
__device__ __half g_emb[(TM+ND)*DD];
__device__ __half g_lnb[TM*DD];
__device__ __half g_kv[TM*512];
__device__ __half g_q0[TT*DD];
__device__ __half g_o0[TT*DD];
__device__ float  g_x1[TT*DD];
__device__ __half g_ln2[TT*DD];
__device__ __half g_ffh[TT*1024];
__device__ float  g_ffout[TT*DD];
__device__ float  g_feat0[ROWS1*DD];
__device__ float  g_detf[ND*DD];
__device__ __half g_x[ROWS1*DD];
__device__ __half g_hh[ROWS1*DD];
__device__ float g_src[ROWS1*HH];
__device__ float g_dstT[BB*HH*NN1];
__device__ float2 g_stat[BB*HH*NN1];
__device__ __half g_anum[(size_t)BB*HH*NN1*NN1];
__device__ unsigned char g_adj[(size_t)BB*NN1*NN1];
__device__ unsigned char g_adjd[(size_t)BB*NNd*NNd];
__device__ float g_pos[BB*NN1*2];
__device__ unsigned char g_vm[BB*NN1];
__device__ __half g_xq[ROWS1*DD];
__device__ __half g_xk[ROWS1*DD];
// fp16 weights
__device__ __half g_w2h[256*256];
__device__ __half g_wqkvh[256*768];
__device__ __half g_woh[256*256];
__device__ __half g_ff1h[256*1024];
__device__ __half g_ff2h[1024*256];
__device__ __half g_gatWh[2*256*256];
__device__ __half g_dgatWh[2*256*256];
__device__ __half g_clsWqh[2*256*256];
__device__ __half g_clsWkh[2*256*256];

// ---------------------------------------------------------------------------
// helpers
// ---------------------------------------------------------------------------
__device__ __forceinline__ uint32_t pk(float lo, float hi) {
    __half2 v = __floats2half2_rn(lo, hi);
    return *reinterpret_cast<uint32_t*>(&v);
}
__device__ __forceinline__ void mma_f16(float* c, const uint32_t* a, const uint32_t* b) {
    asm volatile(
        "mma.sync.aligned.m16n8k16.row.col.f32.f16.f16.f32 "
        "{%0,%1,%2,%3}, {%4,%5,%6,%7}, {%8,%9}, {%0,%1,%2,%3};\n"
        : "+f"(c[0]), "+f"(c[1]), "+f"(c[2]), "+f"(c[3])
        : "r"(a[0]), "r"(a[1]), "r"(a[2]), "r"(a[3]), "r"(b[0]), "r"(b[1]));
}
__device__ __forceinline__ void ldm_x4(uint32_t* r, uint32_t addr) {
    asm volatile("ldmatrix.sync.aligned.m8n8.x4.shared.b16 {%0,%1,%2,%3}, [%4];"
        : "=r"(r[0]), "=r"(r[1]), "=r"(r[2]), "=r"(r[3]) : "r"(addr));
}
__device__ __forceinline__ void ldm_x4_t(uint32_t* r, uint32_t addr) {
    asm volatile("ldmatrix.sync.aligned.m8n8.x4.trans.shared.b16 {%0,%1,%2,%3}, [%4];"
        : "=r"(r[0]), "=r"(r[1]), "=r"(r[2]), "=r"(r[3]) : "r"(addr));
}
__device__ __forceinline__ uint32_t cvs(const void* p) {
    return (uint32_t)__cvta_generic_to_shared(p);
}
__device__ __forceinline__ void cp16(uint32_t dst, const void* src) {
    asm volatile("cp.async.cg.shared.global [%0], [%1], 16;" :: "r"(dst), "l"(src));
}
__device__ __forceinline__ void cp8(uint32_t dst, const void* src) {
    asm volatile("cp.async.ca.shared.global [%0], [%1], 8;" :: "r"(dst), "l"(src));
}
__device__ __forceinline__ void cp4(uint32_t dst, const void* src) {
    asm volatile("cp.async.ca.shared.global [%0], [%1], 4;" :: "r"(dst), "l"(src));
}
#define CP_COMMIT() asm volatile("cp.async.commit_group;")
#define CP_WAIT1()  asm volatile("cp.async.wait_group 1;")
#define CP_WAIT0()  asm volatile("cp.async.wait_group 0;")

// combined weight fp32->fp16
struct WPack {
    const float* s[9];
    __half* d[9];
    int n[9];
};
__global__ void k_f2h_all(WPack p)
{
    int g = blockIdx.y;
    int i = (blockIdx.x * 256 + threadIdx.x) * 4;
    if (i >= p.n[g]) return;
    float4 v = *(const float4*)(p.s[g] + i);
    uint2 o;
    o.x = pk(v.x, v.y);
    o.y = pk(v.z, v.w);
    *(uint2*)(p.d[g] + i) = o;
}

// ---------------------------------------------------------------------------
// BIG GEMM (fp16, cp.async 3-stage): CTA 128x128, BK=16, 256 thr, warp 64x32.
// ---------------------------------------------------------------------------
template<bool TRANSB, int FLAGS>
__global__ __launch_bounds__(256, 2)
void tgemm_big(const __half* __restrict__ A, int lda, long long sA,
               const __half* __restrict__ B, int ldb, long long sB,
               void* __restrict__ Cv, int ldc, long long sC,
               int K,
               const float* __restrict__ bias,
               const __half* __restrict__ aux, int auxld,
               const unsigned char* __restrict__ adjp, long long sAdj,
               const __half* __restrict__ B2, void* __restrict__ C2v, int dual)
{
    int bz = blockIdx.z;
    if (dual && bz) { B = B2; Cv = C2v; bz = 0; }
    A += (long long)bz * sA;
    B += (long long)bz * sB;
    size_t coff = (size_t)((long long)bz * sC);
    if (FLAGS & F_SIG) adjp += (long long)bz * sAdj;

    int m0 = blockIdx.y * 128, n0 = blockIdx.x * 128;

    __shared__ uint32_t As[3][1536];
    __shared__ uint32_t Bs[3][1536];

    int tid = threadIdx.x;
    int arow = tid >> 1, ahalf = tid & 1;
    const __half* gA = A + (size_t)(m0 + arow) * lda + ahalf * 8;

    const __half* gB;
    int kp = tid >> 5, nq = tid & 31;
    if (!TRANSB) gB = B + (size_t)(2 * kp) * ldb + n0 + nq * 4;
    else         gB = B + (size_t)(n0 + arow) * ldb + ahalf * 8;

    uint32_t aD = cvs(&As[0][arow * 12 + ahalf * 4]);
    uint32_t bD1, bD2;
    if (!TRANSB) {
        int w0 = (2 * kp) * 68 + nq * 2;
        bD1 = cvs(&Bs[0][w0]);
        bD2 = cvs(&Bs[0][w0 + 68]);
    } else {
        bD1 = cvs(&Bs[0][arow * 12 + ahalf * 4]);
        bD2 = 0;
    }

    int w = tid >> 5, l = tid & 31;
    int mbase = (w >> 2) * 64, nbase = (w & 3) * 32;
    int grp = l >> 2, tig = l & 3;

    int lrowA = ((l >> 3) & 1) * 8 + (l & 7);
    int khalf = l >> 4;
    uint32_t aBase[4];
    #pragma unroll
    for (int fm = 0; fm < 4; fm++)
        aBase[fm] = cvs(&As[0][(mbase + fm * 16 + lrowA) * 12 + khalf * 4]);
    uint32_t bBase[2];
    if (!TRANSB) {
        int krow = ((l >> 4) & 1) * 8 + (l & 7);
        int nblk = ((l >> 3) & 1) * 8;
        #pragma unroll
        for (int fp = 0; fp < 2; fp++)
            bBase[fp] = cvs(&Bs[0][krow * 68 + ((nbase + fp * 16 + nblk) >> 1)]);
    } else {
        #pragma unroll
        for (int fp = 0; fp < 2; fp++)
            bBase[fp] = cvs(&Bs[0][(nbase + fp * 16 + lrowA) * 12 + khalf * 4]);
    }

    float acc[4][4][4];
    #pragma unroll
    for (int i = 0; i < 4; i++)
        #pragma unroll
        for (int j = 0; j < 4; j++)
            #pragma unroll
            for (int q = 0; q < 4; q++) acc[i][j][q] = 0.f;

    int nk = K >> 4;

    // prologue: issue stages 0 and 1
    {
        cp16(aD, gA);
        if (!TRANSB) {
            cp8(bD1, gB);
            cp8(bD2, gB + ldb);
        } else {
            cp16(bD1, gB);
        }
        CP_COMMIT();
        if (nk > 1) {
            cp16(aD + 6144, gA + 16);
            if (!TRANSB) {
                cp8(bD1 + 6144, gB + (size_t)16 * ldb);
                cp8(bD2 + 6144, gB + (size_t)17 * ldb);
            } else {
                cp16(bD1 + 6144, gB + 16);
            }
            CP_COMMIT();
        }
    }

    int s = 0;
    for (int i = 0; i < nk; i++) {
        if (i + 1 < nk) CP_WAIT1(); else CP_WAIT0();
        __syncthreads();
        uint32_t soff = (uint32_t)(s * 6144);
        uint32_t af[4][4];
        #pragma unroll
        for (int fm = 0; fm < 4; fm++) ldm_x4(af[fm], aBase[fm] + soff);
        uint32_t bfr[4][2];
        #pragma unroll
        for (int fp = 0; fp < 2; fp++) {
            uint32_t t4[4];
            if (!TRANSB) ldm_x4_t(t4, bBase[fp] + soff);
            else         ldm_x4(t4, bBase[fp] + soff);
            bfr[fp * 2][0] = t4[0]; bfr[fp * 2 + 1][0] = t4[1];
            bfr[fp * 2][1] = t4[2]; bfr[fp * 2 + 1][1] = t4[3];
        }
        #pragma unroll
        for (int fm = 0; fm < 4; fm++)
            #pragma unroll
            for (int fn = 0; fn < 4; fn++)
                mma_f16(acc[fm][fn], af[fm], bfr[fn]);
        if (i + 2 < nk) {
            int st = s >= 1 ? s - 1 : s + 2;   // (s+2)%3
            uint32_t toff = (uint32_t)(st * 6144);
            int k0 = (i + 2) * 16;
            cp16(aD + toff, gA + k0);
            if (!TRANSB) {
                cp8(bD1 + toff, gB + (size_t)k0 * ldb);
                cp8(bD2 + toff, gB + (size_t)(k0 + 1) * ldb);
            } else {
                cp16(bD1 + toff, gB + k0);
            }
            CP_COMMIT();
        }
        s = (s + 1) == 3 ? 0 : s + 1;
    }

    // epilogue
    #pragma unroll
    for (int fm = 0; fm < 4; fm++) {
        int row0 = m0 + mbase + fm * 16 + grp;
        #pragma unroll
        for (int fn = 0; fn < 4; fn++) {
            int col = n0 + nbase + fn * 8 + 2 * tig;
            float v0 = acc[fm][fn][0], v1 = acc[fm][fn][1];
            float v2 = acc[fm][fn][2], v3 = acc[fm][fn][3];
            if (FLAGS & F_BIAS) {
                float bb0 = bias[col], bb1 = bias[col + 1];
                v0 += bb0; v1 += bb1; v2 += bb0; v3 += bb1;
            }
            if (FLAGS & F_RELU) {
                v0 = fmaxf(v0, 0.f); v1 = fmaxf(v1, 0.f);
                v2 = fmaxf(v2, 0.f); v3 = fmaxf(v3, 0.f);
            }
            if (FLAGS & F_AUX) {
                float2 a0 = __half22float2(*(const __half2*)(aux + (size_t)row0 * auxld + col));
                float2 a8 = __half22float2(*(const __half2*)(aux + (size_t)(row0 + 8) * auxld + col));
                v0 += a0.x; v1 += a0.y; v2 += a8.x; v3 += a8.y;
            }
            if (FLAGS & F_SIG) {
                const unsigned char* q0p = adjp + (size_t)row0 * ldc + col;
                const unsigned char* q8p = adjp + (size_t)(row0 + 8) * ldc + col;
                v0 = q0p[0] ? 1.f / (1.f + __expf(-v0 * 0.0625f)) : 0.f;
                v1 = q0p[1] ? 1.f / (1.f + __expf(-v1 * 0.0625f)) : 0.f;
                v2 = q8p[0] ? 1.f / (1.f + __expf(-v2 * 0.0625f)) : 0.f;
                v3 = q8p[1] ? 1.f / (1.f + __expf(-v3 * 0.0625f)) : 0.f;
                if (FLAGS & F_DIAG) {
                    if (row0 == col) v0 = 0.f;
                    if (row0 == col + 1) v1 = 0.f;
                    if (row0 + 8 == col) v2 = 0.f;
                    if (row0 + 8 == col + 1) v3 = 0.f;
                }
            }
            if (FLAGS & F_OUT16) {
                __half* Ch = (__half*)Cv + coff;
                *(uint32_t*)&Ch[(size_t)row0 * ldc + col] = pk(v0, v1);
                *(uint32_t*)&Ch[(size_t)(row0 + 8) * ldc + col] = pk(v2, v3);
            } else {
                float* C = (float*)Cv + coff;
                *(float2*)&C[(size_t)row0 * ldc + col] = make_float2(v0, v1);
                *(float2*)&C[(size_t)(row0 + 8) * ldc + col] = make_float2(v2, v3);
            }
        }
    }
}

// ---------------------------------------------------------------------------
// GAT aggregation (fp16 GEMM, cp.async 3-stage): CTA 128x64, warp 32x32.
// ---------------------------------------------------------------------------
__global__ __launch_bounds__(256)
void agg_fused(const __half* __restrict__ anum, const float2* __restrict__ stat,
               const __half* __restrict__ hmat,
               const float* __restrict__ aux, __half* __restrict__ xout, int NN)
{
    int z = blockIdx.z;
    int b = z >> 2, h = z & 3;
    const __half* B = hmat + (size_t)b * NN * 256 + h * 64;
    __half* C = xout + (size_t)b * NN * 256 + h * 64;
    const float* auxp = aux + (size_t)b * NN * 256 + h * 64;
    const float2* statz = stat + (size_t)z * NN;

    int m0 = blockIdx.y * 128;
    __shared__ uint32_t As[3][1536];
    __shared__ uint32_t Bs[3][576];
    int tid = threadIdx.x;

    int arow = tid >> 1, ahalf = tid & 1;
    const __half* gA = anum + ((size_t)z * NN + m0 + arow) * NN + ahalf * 8;

    int kp = tid >> 5, nq = tid & 31;
    const __half* gB = B + (size_t)(2 * kp) * 256 + 2 * nq;

    uint32_t aD = cvs(&As[0][arow * 12 + ahalf * 4]);
    uint32_t bD1 = cvs(&Bs[0][(2 * kp) * 36 + nq]);
    uint32_t bD2 = cvs(&Bs[0][(2 * kp + 1) * 36 + nq]);

    int w = tid >> 5, l = tid & 31;
    int wm = w >> 1, wn = w & 1;
    int mrow = wm * 32, ncol = wn * 32;
    int grp = l >> 2, tig = l & 3;

    int lrowA = ((l >> 3) & 1) * 8 + (l & 7);
    int khalf = l >> 4;
    uint32_t aBase[2];
    #pragma unroll
    for (int fm = 0; fm < 2; fm++)
        aBase[fm] = cvs(&As[0][(mrow + fm * 16 + lrowA) * 12 + khalf * 4]);
    int krow = ((l >> 4) & 1) * 8 + (l & 7);
    int nblk = ((l >> 3) & 1) * 8;
    uint32_t bBase[2];
    #pragma unroll
    for (int fp = 0; fp < 2; fp++)
        bBase[fp] = cvs(&Bs[0][krow * 36 + ((ncol + fp * 16 + nblk) >> 1)]);

    float acc[2][4][4];
    #pragma unroll
    for (int i = 0; i < 2; i++)
        #pragma unroll
        for (int j = 0; j < 4; j++)
            #pragma unroll
            for (int q = 0; q < 4; q++) acc[i][j][q] = 0.f;

    int nk = NN >> 4;

    // prologue
    {
        cp16(aD, gA);
        cp4(bD1, gB);
        cp4(bD2, gB + 256);
        CP_COMMIT();
        if (nk > 1) {
            cp16(aD + 6144, gA + 16);
            cp4(bD1 + 2304, gB + 16 * 256);
            cp4(bD2 + 2304, gB + 17 * 256);
            CP_COMMIT();
        }
    }

    int s = 0;
    for (int i = 0; i < nk; i++) {
        if (i + 1 < nk) CP_WAIT1(); else CP_WAIT0();
        __syncthreads();
        uint32_t sa = (uint32_t)(s * 6144);
        uint32_t sbo = (uint32_t)(s * 2304);
        uint32_t af[2][4];
        #pragma unroll
        for (int fm = 0; fm < 2; fm++) ldm_x4(af[fm], aBase[fm] + sa);
        uint32_t bfr[4][2];
        #pragma unroll
        for (int fp = 0; fp < 2; fp++) {
            uint32_t t4[4];
            ldm_x4_t(t4, bBase[fp] + sbo);
            bfr[fp * 2][0] = t4[0]; bfr[fp * 2 + 1][0] = t4[1];
            bfr[fp * 2][1] = t4[2]; bfr[fp * 2 + 1][1] = t4[3];
        }
        #pragma unroll
        for (int fm = 0; fm < 2; fm++)
            #pragma unroll
            for (int fn = 0; fn < 4; fn++)
                mma_f16(acc[fm][fn], af[fm], bfr[fn]);
        if (i + 2 < nk) {
            int st = s >= 1 ? s - 1 : s + 2;
            int k0 = (i + 2) * 16;
            cp16(aD + st * 6144, gA + k0);
            cp4(bD1 + st * 2304, gB + (size_t)k0 * 256);
            cp4(bD2 + st * 2304, gB + (size_t)(k0 + 1) * 256);
            CP_COMMIT();
        }
        s = (s + 1) == 3 ? 0 : s + 1;
    }

    #pragma unroll
    for (int fm = 0; fm < 2; fm++) {
        int row = m0 + mrow + fm * 16 + grp;
        float inv0 = statz[row].y;
        float inv8 = statz[row + 8].y;
        #pragma unroll
        for (int fn = 0; fn < 4; fn++) {
            int col = ncol + fn * 8 + 2 * tig;
            float v0 = acc[fm][fn][0] * inv0, v1 = acc[fm][fn][1] * inv0;
            float v2 = acc[fm][fn][2] * inv8, v3 = acc[fm][fn][3] * inv8;
            v0 = (v0 > 0.f) ? v0 : expm1f(v0);
            v1 = (v1 > 0.f) ? v1 : expm1f(v1);
            v2 = (v2 > 0.f) ? v2 : expm1f(v2);
            v3 = (v3 > 0.f) ? v3 : expm1f(v3);
            float2 x0 = *(const float2*)&auxp[(size_t)row * 256 + col];
            float2 x1 = *(const float2*)&auxp[(size_t)(row + 8) * 256 + col];
            *(uint32_t*)&C[(size_t)row * 256 + col] =
                pk(0.5f * v0 + 0.5f * x0.x, 0.5f * v1 + 0.5f * x0.y);
            *(uint32_t*)&C[(size_t)(row + 8) * 256 + col] =
                pk(0.5f * v2 + 0.5f * x1.x, 0.5f * v3 + 0.5f * x1.y);
        }
    }
}

// ---------------------------------------------------------------------------
// Small kernels
// ---------------------------------------------------------------------------
__global__ void k_feat1(const float* __restrict__ x, const float* __restrict__ W1,
                        const float* __restrict__ b1, __half* __restrict__ out)
{
    int tid = threadIdx.x;
    size_t row = (size_t)blockIdx.x * 4 + (tid >> 6);
    int c4 = (tid & 63) * 4;
    const float4 xr = *(const float4*)(x + row * 4);
    float4 v = *(const float4*)(b1 + c4);
    float4 w0 = *(const float4*)(W1 + c4);
    float4 w1 = *(const float4*)(W1 + 256 + c4);
    float4 w2 = *(const float4*)(W1 + 512 + c4);
    float4 w3 = *(const float4*)(W1 + 768 + c4);
    v.x += xr.x * w0.x + xr.y * w1.x + xr.z * w2.x + xr.w * w3.x;
    v.y += xr.x * w0.y + xr.y * w1.y + xr.z * w2.y + xr.w * w3.y;
    v.z += xr.x * w0.z + xr.y * w1.z + xr.z * w2.z + xr.w * w3.z;
    v.w += xr.x * w0.w + xr.y * w1.w + xr.z * w2.w + xr.w * w3.w;
    v.x = (v.x > 0.f) ? v.x : (__expf(v.x) - 1.f);
    v.y = (v.y > 0.f) ? v.y : (__expf(v.y) - 1.f);
    v.z = (v.z > 0.f) ? v.z : (__expf(v.z) - 1.f);
    v.w = (v.w > 0.f) ? v.w : (__expf(v.w) - 1.f);
    uint2 p;
    p.x = pk(v.x, v.y);
    p.y = pk(v.z, v.w);
    *(uint2*)(out + row * 256 + c4) = p;
}

__global__ void k_ln_h(const __half* __restrict__ in, __half* __restrict__ out)
{
    int w = threadIdx.x >> 5, lane = threadIdx.x & 31;
    size_t row = (size_t)blockIdx.x * 8 + w;
    const uint4* ip = (const uint4*)(in + row * 256);
    uint4 u = ip[lane];
    float2 f0 = __half22float2(*(__half2*)&u.x);
    float2 f1 = __half22float2(*(__half2*)&u.y);
    float2 f2 = __half22float2(*(__half2*)&u.z);
    float2 f3 = __half22float2(*(__half2*)&u.w);
    float a = f0.x + f0.y + f1.x + f1.y + f2.x + f2.y + f3.x + f3.y;
    float b = f0.x*f0.x + f0.y*f0.y + f1.x*f1.x + f1.y*f1.y
            + f2.x*f2.x + f2.y*f2.y + f3.x*f3.x + f3.y*f3.y;
    #pragma unroll
    for (int o = 16; o; o >>= 1) {
        a += __shfl_xor_sync(0xffffffff, a, o);
        b += __shfl_xor_sync(0xffffffff, b, o);
    }
    float mean = a * (1.f / 256.f);
    float var = b * (1.f / 256.f) - mean * mean;
    float rstd = rsqrtf(var + 1e-5f);
    uint4 r;
    r.x = pk((f0.x - mean) * rstd, (f0.y - mean) * rstd);
    r.y = pk((f1.x - mean) * rstd, (f1.y - mean) * rstd);
    r.z = pk((f2.x - mean) * rstd, (f2.y - mean) * rstd);
    r.w = pk((f3.x - mean) * rstd, (f3.y - mean) * rstd);
    ((uint4*)(out + row * 256))[lane] = r;
}

__global__ void k_ln_f(const float* __restrict__ in, __half* __restrict__ out)
{
    int w = threadIdx.x >> 5, lane = threadIdx.x & 31;
    size_t row = (size_t)blockIdx.x * 8 + w;
    const float4* ip = (const float4*)(in + row * 256);
    float4 v0 = ip[lane], v1 = ip[lane + 32];
    float a = v0.x + v0.y + v0.z + v0.w + v1.x + v1.y + v1.z + v1.w;
    float b = v0.x*v0.x + v0.y*v0.y + v0.z*v0.z + v0.w*v0.w
            + v1.x*v1.x + v1.y*v1.y + v1.z*v1.z + v1.w*v1.w;
    #pragma unroll
    for (int o = 16; o; o >>= 1) {
        a += __shfl_xor_sync(0xffffffff, a, o);
        b += __shfl_xor_sync(0xffffffff, b, o);
    }
    float mean = a * (1.f / 256.f);
    float var = b * (1.f / 256.f) - mean * mean;
    float rstd = rsqrtf(var + 1e-5f);
    uint2 p0, p1;
    p0.x = pk((v0.x - mean) * rstd, (v0.y - mean) * rstd);
    p0.y = pk((v0.z - mean) * rstd, (v0.w - mean) * rstd);
    p1.x = pk((v1.x - mean) * rstd, (v1.y - mean) * rstd);
    p1.y = pk((v1.z - mean) * rstd, (v1.w - mean) * rstd);
    *(uint2*)(out + row * 256 + lane * 4) = p0;
    *(uint2*)(out + row * 256 + 128 + lane * 4) = p1;
}

__global__ void k_attn(const __half* __restrict__ q0, const __half* __restrict__ kv,
                       __half* __restrict__ o0)
{
    size_t t = blockIdx.x;
    int d = threadIdx.x;
    int w = d >> 5, lane = d & 31, h = d >> 6;
    __shared__ float red[8][8];
    const __half* kvb = kv + t * 8 * 512;
    float qd = __half2float(q0[t * 256 + d]);
    #pragma unroll
    for (int s = 0; s < 8; s++) {
        float v = qd * __half2float(kvb[s * 512 + d]);
        #pragma unroll
        for (int o = 16; o; o >>= 1) v += __shfl_xor_sync(0xffffffff, v, o);
        if (lane == 0) red[w][s] = v;
    }
    __syncthreads();
    float lg[8];
    float m = -1e30f;
    #pragma unroll
    for (int s = 0; s < 8; s++) {
        lg[s] = (red[2 * h][s] + red[2 * h + 1][s]) * 0.125f;
        m = fmaxf(m, lg[s]);
    }
    float sum = 0.f;
    #pragma unroll
    for (int s = 0; s < 8; s++) { lg[s] = __expf(lg[s] - m); sum += lg[s]; }
    float inv = 1.f / sum;
    float o = 0.f;
    #pragma unroll
    for (int s = 0; s < 8; s++) o += lg[s] * inv * __half2float(kvb[s * 512 + 256 + d]);
    o0[t * 256 + d] = __float2half(o);
}

__global__ void k_feat0(const __half* __restrict__ tr_emb, const float* __restrict__ x1,
                        const float* __restrict__ ffout, const __half* __restrict__ det_emb,
                        float* __restrict__ feat0, __half* __restrict__ x,
                        float* __restrict__ detf)
{
    size_t idx = (size_t)blockIdx.x * 256 + threadIdx.x;
    int d = idx & 255;
    size_t row = idx >> 8;
    int i = row & 1023;
    int b = row >> 10;
    float v;
    if (i < 512) {
        size_t t = (size_t)b * 512 + i;
        v = __half2float(tr_emb[t * 2048 + d]) + 0.9f * (x1[t * 256 + d] + ffout[t * 256 + d]);
    } else {
        size_t t = (size_t)b * 512 + (i - 512);
        v = __half2float(det_emb[t * 256 + d]);
        detf[t * 256 + d] = v;
    }
    feat0[idx] = v;
    x[idx] = __float2half(v);
}

__global__ void k_posvm(const float* __restrict__ tracks, const float* __restrict__ dets,
                        const int* __restrict__ tmarks, const int* __restrict__ dmarks,
                        float* __restrict__ pos, unsigned char* __restrict__ vm)
{
    int idx = blockIdx.x * 256 + threadIdx.x;
    if (idx >= BB * NN1) return;
    int b = idx >> 10, i = idx & 1023;
    float x, y; unsigned char v;
    if (i < 512) {
        const float* p = tracks + ((size_t)(b * 512 + i)) * 8 * 4;
        x = p[0]; y = p[1];
        v = (i < tmarks[b]);
    } else {
        int n = i - 512;
        const float* p = dets + ((size_t)(b * 512 + n)) * 4;
        x = p[0]; y = p[1];
        v = (n < dmarks[b]);
    }
    pos[idx * 2] = x; pos[idx * 2 + 1] = y; vm[idx] = v;
}

__global__ void k_adj(const float* __restrict__ pos, const unsigned char* __restrict__ vm,
                      unsigned char* __restrict__ adj)
{
    int i = blockIdx.x, b = blockIdx.y;
    size_t base = (size_t)b * NN1;
    const float2* p2 = (const float2*)pos;
    float2 pi = p2[base + i];
    unsigned char vi = vm[base + i];
    int j0 = threadIdx.x * 4;
    uchar4 r;
    unsigned char* rp = &r.x;
    #pragma unroll
    for (int u = 0; u < 4; u++) {
        int j = j0 + u;
        float2 pj = p2[base + j];
        float dx = pi.x - pj.x, dy = pi.y - pj.y;
        rp[u] = (unsigned char)((dx * dx + dy * dy < 4.0f) && vi && vm[base + j]);
    }
    ((uchar4*)(adj + ((size_t)b * NN1 + i) * NN1))[threadIdx.x] = r;
}

__global__ void k_adjd(const float* __restrict__ pos, const unsigned char* __restrict__ vm,
                       unsigned char* __restrict__ adjd)
{
    int i = blockIdx.x, b = blockIdx.y;
    size_t base = (size_t)b * NN1 + 512;
    const float2* p2 = (const float2*)pos;
    float2 pi = p2[base + i];
    unsigned char vi = vm[base + i];
    int j0 = threadIdx.x * 4;
    uchar4 r;
    unsigned char* rp = &r.x;
    #pragma unroll
    for (int u = 0; u < 4; u++) {
        int j = j0 + u;
        float2 pj = p2[base + j];
        float dx = pi.x - pj.x, dy = pi.y - pj.y;
        rp[u] = (unsigned char)((dx * dx + dy * dy < 4.0f) && vi && vm[base + j]);
    }
    ((uchar4*)(adjd + ((size_t)b * NNd + i) * NNd))[threadIdx.x] = r;
}

__global__ void k_srcdst(const __half* __restrict__ Hm, const float* __restrict__ a0,
                         float* __restrict__ src, float* __restrict__ dstT, int NN)
{
    size_t row = blockIdx.x;
    int d = threadIdx.x;
    float hv = __half2float(Hm[row * 256 + d]);
    float s = hv * a0[d];
    float t2 = hv * a0[256 + d];
    #pragma unroll
    for (int o = 16; o; o >>= 1) {
        s  += __shfl_xor_sync(0xffffffff, s, o);
        t2 += __shfl_xor_sync(0xffffffff, t2, o);
    }
    __shared__ float ps[8], pt[8];
    if ((d & 31) == 0) { ps[d >> 5] = s; pt[d >> 5] = t2; }
    __syncthreads();
    if (d < 4) {
        int b = (int)(row / NN);
        int i = (int)(row - (size_t)b * NN);
        src[row * 4 + d] = ps[2 * d] + ps[2 * d + 1];
        dstT[((size_t)b * 4 + d) * NN + i] = pt[2 * d] + pt[2 * d + 1];
    }
}

__global__ void k_rowstat(const float* __restrict__ src, const float* __restrict__ dstT,
                          const unsigned char* __restrict__ adj, float2* __restrict__ stat,
                          __half* __restrict__ anum, int NN)
{
    int i = blockIdx.x, b = blockIdx.y;
    int h = threadIdx.x >> 5, lane = threadIdx.x & 31;
    int z = b * 4 + h;
    float s = src[((size_t)b * NN + i) * 4 + h];
    const uchar4* adjrow = (const uchar4*)(adj + ((size_t)b * NN + i) * NN);
    const float4* dsth = (const float4*)(dstT + ((size_t)z) * NN);
    __half* arow = anum + ((size_t)z * NN + i) * NN;
    int nq = NN >> 2;
    float mx = -1e30f;
    for (int jq = lane; jq < nq; jq += 32) {
        uchar4 a4 = adjrow[jq];
        float4 d4 = dsth[jq];
        float e0 = s + d4.x; e0 = e0 > 0.f ? e0 : 0.2f * e0; e0 = a4.x ? e0 : -1e9f;
        float e1 = s + d4.y; e1 = e1 > 0.f ? e1 : 0.2f * e1; e1 = a4.y ? e1 : -1e9f;
        float e2 = s + d4.z; e2 = e2 > 0.f ? e2 : 0.2f * e2; e2 = a4.z ? e2 : -1e9f;
        float e3 = s + d4.w; e3 = e3 > 0.f ? e3 : 0.2f * e3; e3 = a4.w ? e3 : -1e9f;
        mx = fmaxf(mx, fmaxf(fmaxf(e0, e1), fmaxf(e2, e3)));
    }
    #pragma unroll
    for (int o = 16; o; o >>= 1) mx = fmaxf(mx, __shfl_xor_sync(0xffffffff, mx, o));
    float sum = 0.f;
    for (int jq = lane; jq < nq; jq += 32) {
        uchar4 a4 = adjrow[jq];
        float4 d4 = dsth[jq];
        float e0 = s + d4.x; e0 = e0 > 0.f ? e0 : 0.2f * e0; e0 = a4.x ? e0 : -1e9f;
        float e1 = s + d4.y; e1 = e1 > 0.f ? e1 : 0.2f * e1; e1 = a4.y ? e1 : -1e9f;
        float e2 = s + d4.z; e2 = e2 > 0.f ? e2 : 0.2f * e2; e2 = a4.z ? e2 : -1e9f;
        float e3 = s + d4.w; e3 = e3 > 0.f ? e3 : 0.2f * e3; e3 = a4.w ? e3 : -1e9f;
        float n0 = __expf(e0 - mx), n1 = __expf(e1 - mx);
        float n2 = __expf(e2 - mx), n3 = __expf(e3 - mx);
        sum += n0 + n1 + n2 + n3;
        uint2 pkd;
        pkd.x = pk(n0, n1);
        pkd.y = pk(n2, n3);
        *(uint2*)(arow + jq * 4) = pkd;
    }
    #pragma unroll
    for (int o = 16; o; o >>= 1) sum += __shfl_xor_sync(0xffffffff, sum, o);
    if (lane == 0)
        stat[(size_t)z * NN + i] = make_float2(mx, 1.f / sum);
}

__global__ void k_asso(const float* __restrict__ scores, float* __restrict__ out)
{
    size_t idx = (size_t)blockIdx.x * 256 + threadIdx.x;
    int j = idx & 511;
    size_t r = idx >> 9;
    int m = r & 511;
    int b = (int)(r >> 9);
    out[idx] = scores[(((size_t)b * 1024 + m) * 1024) + 512 + j];
}

// ---------------------------------------------------------------------------
// Host side
// ---------------------------------------------------------------------------
static void run_big(const __half* A, int lda, long long sA,
                    const __half* B, int ldb, long long sB,
                    void* C, int ldc, long long sC,
                    int M, int N, int K, int batch,
                    const float* bias, const __half* aux, int auxld,
                    const unsigned char* adjp, long long sAdj,
                    int flags, bool transb,
                    const __half* B2 = nullptr, void* C2 = nullptr, int dual = 0)
{
    dim3 g(N / 128, M / 128, batch);
#define CALLBIG(T, F) tgemm_big<T, F><<<g, 256>>>(A, lda, sA, B, ldb, sB, \
        C, ldc, sC, K, bias, aux, auxld, adjp, sAdj, B2, C2, dual)
    if (!transb) {
        if (flags == (F_BIAS | F_OUT16))      CALLBIG(false, F_BIAS | F_OUT16);
        else if (flags == F_OUT16)            CALLBIG(false, F_OUT16);
        else if (flags == F_AUX)              CALLBIG(false, F_AUX);
        else if (flags == (F_RELU | F_OUT16)) CALLBIG(false, F_RELU | F_OUT16);
        else                                  CALLBIG(false, 0);
    } else {
        if (flags == F_SIG)                   CALLBIG(true, F_SIG);
        else                                  CALLBIG(true, F_SIG | F_DIAG);
    }
#undef CALLBIG
}

#define SYM(p, s) cudaGetSymbolAddress((void**)&p, s)

extern "C" void kernel_launch(void* const* d_in, const int* in_sizes, int n_in,
                              void* d_out, int out_size)
{
    (void)in_sizes; (void)n_in; (void)out_size;
    const float* tracks = (const float*)d_in[0];
    const float* dets   = (const float*)d_in[1];
    const int* tmarks   = (const int*)d_in[2];
    const int* dmarks   = (const int*)d_in[3];
    const float* W1     = (const float*)d_in[4];
    const float* b1     = (const float*)d_in[5];
    const float* W2     = (const float*)d_in[6];
    const float* b2     = (const float*)d_in[7];
    const float* Wqkv   = (const float*)d_in[8];
    const float* Wo     = (const float*)d_in[9];
    const float* ff1    = (const float*)d_in[10];
    const float* ff2    = (const float*)d_in[11];
    const float* gatW   = (const float*)d_in[12];
    const float* gata   = (const float*)d_in[13];
    const float* dgatW  = (const float*)d_in[14];
    const float* dgata  = (const float*)d_in[15];
    const float* clsWq  = (const float*)d_in[16];
    const float* clsWk  = (const float*)d_in[17];

    float* out = (float*)d_out;
    float* out_scores = out;
    float* out_det    = out + (size_t)BB * NN1 * NN1;
    float* out_asso   = out_det + (size_t)BB * NNd * NNd;

    __half *h1, *emb, *lnb, *kv, *q0, *o0, *ln2, *ffh, *x, *hh, *xq, *xk, *anum;
    __half *w2h, *wqkvh, *woh, *ff1h, *ff2h, *gatWh, *dgatWh, *clsWqh, *clsWkh;
    float *x1, *ffout, *feat0, *detf, *src, *dstT, *pos;
    float2* stat;
    unsigned char *adj, *adjd, *vm;
    SYM(h1, g_h1);         SYM(emb, g_emb);       SYM(lnb, g_lnb);
    SYM(kv, g_kv);         SYM(q0, g_q0);         SYM(o0, g_o0);
    SYM(x1, g_x1);         SYM(ln2, g_ln2);       SYM(ffh, g_ffh);
    SYM(ffout, g_ffout);   SYM(feat0, g_feat0);   SYM(detf, g_detf);
    SYM(x, g_x);           SYM(hh, g_hh);         SYM(src, g_src);
    SYM(dstT, g_dstT);     SYM(stat, g_stat);     SYM(anum, g_anum);
    SYM(adj, g_adj);       SYM(adjd, g_adjd);     SYM(pos, g_pos);
    SYM(vm, g_vm);         SYM(xq, g_xq);         SYM(xk, g_xk);
    SYM(w2h, g_w2h);       SYM(wqkvh, g_wqkvh);   SYM(woh, g_woh);
    SYM(ff1h, g_ff1h);     SYM(ff2h, g_ff2h);     SYM(gatWh, g_gatWh);
    SYM(dgatWh, g_dgatWh); SYM(clsWqh, g_clsWqh); SYM(clsWkh, g_clsWkh);

    __half* tr_emb = emb;
    __half* det_emb = emb + (size_t)TM * DD;

    // ---- weight fp32 -> fp16, one launch ----
    {
        WPack p;
        p.s[0] = W2;    p.d[0] = w2h;    p.n[0] = 65536;
        p.s[1] = Wqkv;  p.d[1] = wqkvh;  p.n[1] = 196608;
        p.s[2] = Wo;    p.d[2] = woh;    p.n[2] = 65536;
        p.s[3] = ff1;   p.d[3] = ff1h;   p.n[3] = 262144;
        p.s[4] = ff2;   p.d[4] = ff2h;   p.n[4] = 262144;
        p.s[5] = gatW;  p.d[5] = gatWh;  p.n[5] = 131072;
        p.s[6] = dgatW; p.d[6] = dgatWh; p.n[6] = 131072;
        p.s[7] = clsWq; p.d[7] = clsWqh; p.n[7] = 131072;
        p.s[8] = clsWk; p.d[8] = clsWkh; p.n[8] = 131072;
        k_f2h_all<<<dim3(256, 9), 256>>>(p);
    }

    // ---- feature MLP (combined) ----
    k_feat1<<<TM / 4, 256>>>(tracks, W1, b1, h1);
    k_feat1<<<ND / 4, 256>>>(dets, W1, b1, h1 + (size_t)TM * DD);
    run_big(h1, 256, 0, w2h, 256, 0, emb, 256, 0,
            TM + ND, 256, 256, 1, b2, nullptr, 0, nullptr, 0, F_BIAS | F_OUT16, false);

    // ---- encoder (only r=0 outputs needed downstream) ----
    k_ln_h<<<TM / 8, 256>>>(tr_emb, lnb);
    run_big(lnb, 256, 0, wqkvh + 256, 768, 0, kv, 512, 0,
            TM, 512, 256, 1, nullptr, nullptr, 0, nullptr, 0, F_OUT16, false);
    run_big(lnb, 2048, 0, wqkvh, 768, 0, q0, 256, 0,
            TT, 256, 256, 1, nullptr, nullptr, 0, nullptr, 0, F_OUT16, false);
    k_attn<<<TT, 256>>>(q0, kv, o0);
    run_big(o0, 256, 0, woh, 256, 0, x1, 256, 0,
            TT, 256, 256, 1, nullptr, tr_emb, 2048, nullptr, 0, F_AUX, false);
    k_ln_f<<<TT / 8, 256>>>(x1, ln2);
    run_big(ln2, 256, 0, ff1h, 1024, 0, ffh, 1024, 0,
            TT, 1024, 256, 1, nullptr, nullptr, 0, nullptr, 0, F_RELU | F_OUT16, false);
    run_big(ffh, 1024, 0, ff2h, 256, 0, ffout, 256, 0,
            TT, 256, 1024, 1, nullptr, nullptr, 0, nullptr, 0, 0, false);
    k_feat0<<<ROWS1, 256>>>(tr_emb, x1, ffout, det_emb, feat0, x, detf);

    // ---- adjacency ----
    k_posvm<<<64, 256>>>(tracks, dets, tmarks, dmarks, pos, vm);
    k_adj<<<dim3(NN1, BB), 256>>>(pos, vm, adj);
    k_adjd<<<dim3(NNd, BB), 128>>>(pos, vm, adjd);

    // ---- main GAT x2 ----
    for (int l = 0; l < 2; l++) {
        run_big(x, 256, 0, gatWh + (size_t)l * 65536, 256, 0, hh, 256, 0,
                ROWS1, 256, 256, 1, nullptr, nullptr, 0, nullptr, 0, F_OUT16, false);
        k_srcdst<<<ROWS1, 256>>>(hh, gata + (size_t)l * 512, src, dstT, NN1);
        k_rowstat<<<dim3(NN1, BB), 128>>>(src, dstT, adj, stat, anum, NN1);
        agg_fused<<<dim3(1, NN1 / 128, BB * HH), 256>>>(anum, stat, hh, feat0, x, NN1);
    }

    // ---- main scores (dual xq/xk) ----
    run_big(x, 256, 0, clsWqh, 256, 0, xq, 256, 0,
            ROWS1, 256, 256, 2, nullptr, nullptr, 0, nullptr, 0, F_OUT16, false,
            clsWkh, xk, 1);
    run_big(xq, 256, (long long)NN1 * 256, xk, 256, (long long)NN1 * 256,
            out_scores, NN1, (long long)NN1 * NN1,
            NN1, NN1, 256, BB, nullptr, nullptr, 0,
            adj, (long long)NN1 * NN1, F_SIG, true);
    k_asso<<<(int)(((size_t)BB * 512 * 512) / 256), 256>>>(out_scores, out_asso);

    // ---- detection GAT x2 ----
    for (int l = 0; l < 2; l++) {
        const __half* xin = (l == 0) ? det_emb : x;
        run_big(xin, 256, 0, dgatWh + (size_t)l * 65536, 256, 0, hh, 256, 0,
                ND, 256, 256, 1, nullptr, nullptr, 0, nullptr, 0, F_OUT16, false);
        k_srcdst<<<ND, 256>>>(hh, dgata + (size_t)l * 512, src, dstT, NNd);
        k_rowstat<<<dim3(NNd, BB), 128>>>(src, dstT, adjd, stat, anum, NNd);
        agg_fused<<<dim3(1, NNd / 128, BB * HH), 256>>>(anum, stat, hh, detf, x, NNd);
    }

    // ---- detection scores (dual xq/xk) ----
    run_big(x, 256, 0, clsWqh + 65536, 256, 0, xq, 256, 0,
            ND, 256, 256, 2, nullptr, nullptr, 0, nullptr, 0, F_OUT16, false,
            clsWkh + 65536, xk, 1);
    run_big(xq, 256, (long long)NNd * 256, xk, 256, (long long)NNd * 256,
            out_det, NNd, (long long)NNd * NNd,
            NNd, NNd, 256, BB, nullptr, nullptr, 0,
            adjd, (long long)NNd * NNd, F_SIG | F_DIAG, true);
}